// round 6
// baseline (speedup 1.0000x reference)
#include <cuda_runtime.h>
#include <cuda_bf16.h>
#include <math.h>
#include <stdint.h>

#define BB 4
#define SS 2048
#define DMODEL 1024
#define NH 16
#define DKV 64
#define INNER 1024
#define BS_TOT (BB * SS)
#define NREL 4095

// ---------------- scratch (device globals: allocation-free) ----------------
__device__ __align__(256) float g_biasTab[NH * NREL];
__device__ __align__(256) __nv_bfloat16 g_Hh[BS_TOT * DMODEL];
__device__ __align__(256) __nv_bfloat16 g_Hl[BS_TOT * DMODEL];
__device__ __align__(256) __nv_bfloat16 g_Qh[BS_TOT * INNER];
__device__ __align__(256) __nv_bfloat16 g_Ql[BS_TOT * INNER];
__device__ __align__(256) __nv_bfloat16 g_Kh[BS_TOT * INNER];
__device__ __align__(256) __nv_bfloat16 g_Kl[BS_TOT * INNER];
__device__ __align__(256) __nv_bfloat16 g_Vh[BS_TOT * INNER];
__device__ __align__(256) __nv_bfloat16 g_Vl[BS_TOT * INNER];
__device__ __align__(256) __nv_bfloat16 g_Ch[BS_TOT * INNER];
__device__ __align__(256) __nv_bfloat16 g_Cl[BS_TOT * INNER];
__device__ __align__(256) __nv_bfloat16 g_WqTh[INNER * DMODEL];
__device__ __align__(256) __nv_bfloat16 g_WqTl[INNER * DMODEL];
__device__ __align__(256) __nv_bfloat16 g_WkTh[INNER * DMODEL];
__device__ __align__(256) __nv_bfloat16 g_WkTl[INNER * DMODEL];
__device__ __align__(256) __nv_bfloat16 g_WvTh[INNER * DMODEL];
__device__ __align__(256) __nv_bfloat16 g_WvTl[INNER * DMODEL];
__device__ __align__(256) __nv_bfloat16 g_WoTh[DMODEL * INNER];
__device__ __align__(256) __nv_bfloat16 g_WoTl[DMODEL * INNER];

// ---------------------------- PTX helpers ----------------------------------
__device__ __forceinline__ uint32_t smem_u32(const void* p) {
    uint32_t a;
    asm("{ .reg .u64 t; cvta.to.shared.u64 t, %1; cvt.u32.u64 %0, t; }"
        : "=r"(a) : "l"(p));
    return a;
}
__device__ __forceinline__ void cp16(uint32_t dst, const void* src) {
    asm volatile("cp.async.cg.shared.global [%0], [%1], 16;"
                 :: "r"(dst), "l"(src) : "memory");
}
__device__ __forceinline__ void cp_commit() {
    asm volatile("cp.async.commit_group;" ::: "memory");
}
__device__ __forceinline__ void cp_wait0() {
    asm volatile("cp.async.wait_group 0;" ::: "memory");
}
__device__ __forceinline__ void cp_wait1() {
    asm volatile("cp.async.wait_group 1;" ::: "memory");
}
__device__ __forceinline__ void ldmx4(uint32_t* r, uint32_t addr) {
    asm volatile("ldmatrix.sync.aligned.m8n8.x4.shared.b16 {%0,%1,%2,%3}, [%4];"
                 : "=r"(r[0]), "=r"(r[1]), "=r"(r[2]), "=r"(r[3]) : "r"(addr));
}
__device__ __forceinline__ void ldmx4t(uint32_t* r, uint32_t addr) {
    asm volatile("ldmatrix.sync.aligned.m8n8.x4.trans.shared.b16 {%0,%1,%2,%3}, [%4];"
                 : "=r"(r[0]), "=r"(r[1]), "=r"(r[2]), "=r"(r[3]) : "r"(addr));
}
__device__ __forceinline__ void mma16816(float* c, const uint32_t* a,
                                         uint32_t b0, uint32_t b1) {
    asm volatile("mma.sync.aligned.m16n8k16.row.col.f32.bf16.bf16.f32 "
                 "{%0,%1,%2,%3}, {%4,%5,%6,%7}, {%8,%9}, {%0,%1,%2,%3};"
                 : "+f"(c[0]), "+f"(c[1]), "+f"(c[2]), "+f"(c[3])
                 : "r"(a[0]), "r"(a[1]), "r"(a[2]), "r"(a[3]), "r"(b0), "r"(b1));
}
__device__ __forceinline__ uint32_t pack_bf2(float x, float y) {
    __nv_bfloat162 p;
    p.x = __float2bfloat16(x);
    p.y = __float2bfloat16(y);
    return *(uint32_t*)&p;
}
__device__ __forceinline__ void store_split2(__nv_bfloat16* Ch, __nv_bfloat16* Cl,
                                             size_t off, float x, float y) {
    __nv_bfloat16 hx = __float2bfloat16(x), hy = __float2bfloat16(y);
    __nv_bfloat16 lx = __float2bfloat16(x - __bfloat162float(hx));
    __nv_bfloat16 ly = __float2bfloat16(y - __bfloat162float(hy));
    __nv_bfloat162 ph; ph.x = hx; ph.y = hy;
    __nv_bfloat162 pl; pl.x = lx; pl.y = ly;
    *(__nv_bfloat162*)(Ch + off) = ph;
    *(__nv_bfloat162*)(Cl + off) = pl;
}

// ---------------------------------------------------------------------------
// Relative-position bias table
// ---------------------------------------------------------------------------
__global__ void bias_table_kernel(const float* __restrict__ rel_emb,
                                  float* __restrict__ biasTab) {
    int h = blockIdx.x;
    for (int idx = threadIdx.x; idx < NREL; idx += blockDim.x) {
        int rel = idx - (SS - 1);
        int n = -rel;
        int ret = 0;
        if (n < 0) { ret = 16; n = -n; }
        int bucket;
        if (n < 8) {
            bucket = ret + n;
        } else {
            float v = logf((float)n / 8.0f) / logf(16.0f) * 8.0f;
            int vi = 8 + (int)v;
            if (vi > 15) vi = 15;
            bucket = ret + vi;
        }
        biasTab[h * NREL + idx] = rel_emb[bucket * NH + h];
    }
}

// ---------------------------------------------------------------------------
// fp32 -> bf16 hi/lo split (row-major)
// ---------------------------------------------------------------------------
__global__ __launch_bounds__(256) void split_plain(const float* __restrict__ X,
                                                   __nv_bfloat16* __restrict__ Xh,
                                                   __nv_bfloat16* __restrict__ Xl,
                                                   int n4) {
    int i = blockIdx.x * 256 + threadIdx.x;
    if (i >= n4) return;
    float4 v = ((const float4*)X)[i];
    __nv_bfloat16 h0 = __float2bfloat16(v.x), h1 = __float2bfloat16(v.y);
    __nv_bfloat16 h2 = __float2bfloat16(v.z), h3 = __float2bfloat16(v.w);
    __nv_bfloat16 l0 = __float2bfloat16(v.x - __bfloat162float(h0));
    __nv_bfloat16 l1 = __float2bfloat16(v.y - __bfloat162float(h1));
    __nv_bfloat16 l2 = __float2bfloat16(v.z - __bfloat162float(h2));
    __nv_bfloat16 l3 = __float2bfloat16(v.w - __bfloat162float(h3));
    __nv_bfloat162 ph0; ph0.x = h0; ph0.y = h1;
    __nv_bfloat162 ph1; ph1.x = h2; ph1.y = h3;
    __nv_bfloat162 pl0; pl0.x = l0; pl0.y = l1;
    __nv_bfloat162 pl1; pl1.x = l2; pl1.y = l3;
    ((__nv_bfloat162*)Xh)[2 * i]     = ph0;
    ((__nv_bfloat162*)Xh)[2 * i + 1] = ph1;
    ((__nv_bfloat162*)Xl)[2 * i]     = pl0;
    ((__nv_bfloat162*)Xl)[2 * i + 1] = pl1;
}

// ---------------------------------------------------------------------------
// Weight transpose + split: W[R,C] fp32 -> Th/Tl[C,R] bf16 (K-major)
// ---------------------------------------------------------------------------
__global__ __launch_bounds__(256) void split_transpose(const float* __restrict__ W,
                                                       __nv_bfloat16* __restrict__ Th,
                                                       __nv_bfloat16* __restrict__ Tl,
                                                       int R, int C) {
    __shared__ float t[32][33];
    int bx = blockIdx.x * 32, by = blockIdx.y * 32;
    int tx = threadIdx.x, ty = threadIdx.y;
#pragma unroll
    for (int i = 0; i < 32; i += 8)
        t[ty + i][tx] = W[(size_t)(by + ty + i) * C + bx + tx];
    __syncthreads();
#pragma unroll
    for (int i = 0; i < 32; i += 8) {
        float v = t[tx][ty + i];
        __nv_bfloat16 h = __float2bfloat16(v);
        __nv_bfloat16 l = __float2bfloat16(v - __bfloat162float(h));
        size_t o = (size_t)(bx + ty + i) * R + by + tx;
        Th[o] = h;
        Tl[o] = l;
    }
}

// ---------------------------------------------------------------------------
// Split-bf16 mma.sync GEMM: C[M,N] = A[M,K] @ BT[N,K]^T
// 128x128 CTA tile, 128 threads = 4 warps (2x2), warp tile 64x64.
// BK=32, 2-stage cp.async pipeline. B-fragments cached across M loop.
// ---------------------------------------------------------------------------
#define LDS 40
#define STG_A_L 10240
#define STG_B_H 20480
#define STG_B_L 30720
#define STG_SZ  40960

__global__ __launch_bounds__(128)
void mma_gemm(const __nv_bfloat16* __restrict__ Ah, const __nv_bfloat16* __restrict__ Al,
              const __nv_bfloat16* __restrict__ Bh, const __nv_bfloat16* __restrict__ Bl,
              float* __restrict__ Cf,
              __nv_bfloat16* __restrict__ Ch, __nv_bfloat16* __restrict__ Cl,
              int M, int N, int K, int split_out) {
    extern __shared__ __align__(128) char smem[];
    const int tid = threadIdx.x, lane = tid & 31, wid = tid >> 5;
    const int wm = wid >> 1, wn = wid & 1;
    const int rowA0 = blockIdx.y * 128, rowB0 = blockIdx.x * 128;
    const uint32_t sb = smem_u32(smem);
    const int nk = K >> 5;

    float acc[32][4];
#pragma unroll
    for (int i = 0; i < 32; i++)
#pragma unroll
        for (int j = 0; j < 4; j++) acc[i][j] = 0.0f;

    auto load_stage = [&](int stage, int kc) {
        const uint32_t d0 = sb + (uint32_t)stage * STG_SZ;
        const int k0 = kc * 32;
#pragma unroll
        for (int i = 0; i < 16; i++) {
            int id = tid + i * 128;
            int arr = id >> 9;
            int rem = id & 511;
            int row = rem >> 2;
            int ch  = (rem & 3) << 4;
            uint32_t dst = d0 + arr * 10240 + row * 80 + ch;
            const __nv_bfloat16* src = (arr == 0) ? Ah : (arr == 1) ? Al
                                    : (arr == 2) ? Bh : Bl;
            int grow = ((arr < 2) ? rowA0 : rowB0) + row;
            cp16(dst, (const char*)src + ((size_t)grow * K + k0) * 2 + ch);
        }
        cp_commit();
    };

    load_stage(0, 0);

    const int rA = lane & 15;
    const int cA8 = (lane >> 4) << 3;

    for (int kc = 0; kc < nk; kc++) {
        const int s = kc & 1;
        if (kc + 1 < nk) { load_stage(s ^ 1, kc + 1); cp_wait1(); }
        else             { cp_wait0(); }
        __syncthreads();

        const uint32_t base = sb + (uint32_t)s * STG_SZ;
#pragma unroll
        for (int ks = 0; ks < 32; ks += 16) {
            uint32_t b_h[4][4], b_l[4][4];
#pragma unroll
            for (int nt = 0; nt < 4; nt++) {
                uint32_t boff = ((64 * wn + nt * 16 + rA) * LDS + ks + cA8) * 2;
                ldmx4(b_h[nt], base + STG_B_H + boff);
                ldmx4(b_l[nt], base + STG_B_L + boff);
            }
#pragma unroll
            for (int im = 0; im < 4; im++) {
                uint32_t a_h[4], a_l[4];
                uint32_t aoff = ((64 * wm + im * 16 + rA) * LDS + ks + cA8) * 2;
                ldmx4(a_h, base + aoff);
                ldmx4(a_l, base + STG_A_L + aoff);
#pragma unroll
                for (int nt = 0; nt < 4; nt++)
#pragma unroll
                    for (int s2 = 0; s2 < 2; s2++) {
                        float* a = acc[im * 8 + nt * 2 + s2];
                        mma16816(a, a_h, b_h[nt][s2], b_h[nt][s2 + 2]);
                        mma16816(a, a_h, b_l[nt][s2], b_l[nt][s2 + 2]);
                        mma16816(a, a_l, b_h[nt][s2], b_h[nt][s2 + 2]);
                    }
            }
        }
        __syncthreads();
    }

    const int er = lane >> 2, ec = (lane & 3) << 1;
#pragma unroll
    for (int im = 0; im < 4; im++) {
        int r0 = rowA0 + 64 * wm + im * 16 + er;
#pragma unroll
        for (int jn = 0; jn < 8; jn++) {
            int c = rowB0 + 64 * wn + jn * 8 + ec;
            float* a = acc[im * 8 + jn];
            if (split_out) {
                store_split2(Ch, Cl, (size_t)r0 * N + c, a[0], a[1]);
                store_split2(Ch, Cl, (size_t)(r0 + 8) * N + c, a[2], a[3]);
            } else {
                *(float2*)(Cf + (size_t)r0 * N + c) = make_float2(a[0], a[1]);
                *(float2*)(Cf + (size_t)(r0 + 8) * N + c) = make_float2(a[2], a[3]);
            }
        }
    }
}

// ---------------------------------------------------------------------------
// Register-resident FA2 flash attention (split-bf16 mma, T5 bias).
// Grid (S/128, B*H), 128 threads = 4 warps; warp tile: 32 q-rows x 64 keys.
// S/P live in registers; P packed acc->A-fragment per k16-tile on the fly.
// ---------------------------------------------------------------------------
#define LKV 72
#define AQH 0
#define AQL 18432
#define AKH 36864
#define AKL 46080
#define AVH 55296
#define AVL 64512
#define ABIAS 73728
#define ATTN_SMEM 74624
#define NKT (SS / 64)

__global__ __launch_bounds__(128)
void attn_fa2(const __nv_bfloat16* __restrict__ Qh, const __nv_bfloat16* __restrict__ Ql,
              const __nv_bfloat16* __restrict__ Kh, const __nv_bfloat16* __restrict__ Kl,
              const __nv_bfloat16* __restrict__ Vh, const __nv_bfloat16* __restrict__ Vl,
              const float* __restrict__ biasTab,
              __nv_bfloat16* __restrict__ Ch, __nv_bfloat16* __restrict__ Cl) {
    extern __shared__ __align__(128) char sm[];
    const int tid = threadIdx.x, lane = tid & 31, wid = tid >> 5;
    const int qt = blockIdx.x, bhi = blockIdx.y;
    const int b = bhi >> 4, h = bhi & 15;
    const int q0 = qt * 128;
    const size_t base = (size_t)b * SS * INNER + (size_t)h * DKV;
    const float* bt = biasTab + h * NREL + (SS - 1) - q0 - 127;   // index by k0+i
    const uint32_t sb = smem_u32(sm);
    float* bias_s = (float*)(sm + ABIAS);

    const int rA = lane & 15, cA8 = (lane >> 4) << 3;
    const int er = lane >> 2, qr = (lane & 3) << 1;

    auto loadK = [&](int kt) {
        const int k0 = kt * 64;
#pragma unroll
        for (int i = 0; i < 8; i++) {
            int id = tid + i * 128;
            int arr = id >> 9, rem = id & 511;
            int row = rem >> 3, ch = (rem & 7) << 4;
            const __nv_bfloat16* src = arr ? Kl : Kh;
            cp16(sb + AKH + arr * 9216 + row * 144 + ch,
                 (const char*)src + (base + (size_t)(k0 + row) * INNER) * 2 + ch);
        }
    };
    auto loadV = [&](int kt) {
        const int k0 = kt * 64;
#pragma unroll
        for (int i = 0; i < 8; i++) {
            int id = tid + i * 128;
            int arr = id >> 9, rem = id & 511;
            int row = rem >> 3, ch = (rem & 7) << 4;
            const __nv_bfloat16* src = arr ? Vl : Vh;
            cp16(sb + AVH + arr * 9216 + row * 144 + ch,
                 (const char*)src + (base + (size_t)(k0 + row) * INNER) * 2 + ch);
        }
    };

    // Q tile (hi+lo): 128 rows x 64 cols
#pragma unroll
    for (int i = 0; i < 16; i++) {
        int id = tid + i * 128;
        int arr = id >> 10, rem = id & 1023;
        int row = rem >> 3, ch = (rem & 7) << 4;
        const __nv_bfloat16* src = arr ? Ql : Qh;
        cp16(sb + (arr ? AQL : AQH) + row * 144 + ch,
             (const char*)src + (base + (size_t)(q0 + row) * INNER) * 2 + ch);
    }
    loadK(0);
    loadV(0);
    bias_s[tid] = bt[tid];
    if (tid < 63) bias_s[tid + 128] = bt[tid + 128];
    cp_commit();

    float mr[2][2], lr[2][2];
#pragma unroll
    for (int im = 0; im < 2; im++) {
        mr[im][0] = -1e30f; mr[im][1] = -1e30f;
        lr[im][0] = 0.0f;   lr[im][1] = 0.0f;
    }
    float oac[2][8][4];
#pragma unroll
    for (int im = 0; im < 2; im++)
#pragma unroll
        for (int jn = 0; jn < 8; jn++)
#pragma unroll
            for (int j = 0; j < 4; j++) oac[im][jn][j] = 0.0f;

    for (int kt = 0; kt < NKT; kt++) {
        cp_wait0();
        __syncthreads();

        // ---- S = Q K^T (m32 x n64 per warp, in registers) ----
        float sac[2][8][4];
#pragma unroll
        for (int im = 0; im < 2; im++)
#pragma unroll
            for (int jn = 0; jn < 8; jn++)
#pragma unroll
                for (int j = 0; j < 4; j++) sac[im][jn][j] = 0.0f;
#pragma unroll
        for (int ks = 0; ks < 64; ks += 16) {
            uint32_t khf[4][4], klf[4][4];
#pragma unroll
            for (int kb = 0; kb < 4; kb++) {
                uint32_t boff = ((16 * kb + rA) * LKV + ks + cA8) * 2;
                ldmx4(khf[kb], sb + AKH + boff);
                ldmx4(klf[kb], sb + AKL + boff);
            }
#pragma unroll
            for (int im = 0; im < 2; im++) {
                uint32_t qfh[4], qfl[4];
                uint32_t aoff = ((wid * 32 + im * 16 + rA) * LKV + ks + cA8) * 2;
                ldmx4(qfh, sb + AQH + aoff);
                ldmx4(qfl, sb + AQL + aoff);
#pragma unroll
                for (int jn = 0; jn < 8; jn++) {
                    int kb = jn >> 1, sub = jn & 1;
                    mma16816(sac[im][jn], qfh, khf[kb][sub], khf[kb][sub + 2]);
                    mma16816(sac[im][jn], qfh, klf[kb][sub], klf[kb][sub + 2]);
                    mma16816(sac[im][jn], qfl, khf[kb][sub], khf[kb][sub + 2]);
                }
            }
        }
        __syncthreads();                 // all warps done reading K
        if (kt + 1 < NKT) loadK(kt + 1); // overlap next-K with softmax+PV
        cp_commit();

        // ---- softmax in registers (exp values stay in sac as fp32) ----
#pragma unroll
        for (int im = 0; im < 2; im++) {
            const int rm0 = wid * 32 + im * 16 + er, rm1 = rm0 + 8;
            float vx0 = -1e30f, vx1 = -1e30f;
#pragma unroll
            for (int jn = 0; jn < 8; jn++) {
                int c = jn * 8 + qr;
                float* s4 = sac[im][jn];
                s4[0] += bias_s[c - rm0 + 127];
                s4[1] += bias_s[c + 1 - rm0 + 127];
                s4[2] += bias_s[c - rm1 + 127];
                s4[3] += bias_s[c + 1 - rm1 + 127];
                vx0 = fmaxf(vx0, fmaxf(s4[0], s4[1]));
                vx1 = fmaxf(vx1, fmaxf(s4[2], s4[3]));
            }
#pragma unroll
            for (int off = 1; off < 4; off <<= 1) {
                vx0 = fmaxf(vx0, __shfl_xor_sync(0xffffffffu, vx0, off));
                vx1 = fmaxf(vx1, __shfl_xor_sync(0xffffffffu, vx1, off));
            }
            float mn0 = fmaxf(mr[im][0], vx0), mn1 = fmaxf(mr[im][1], vx1);
            float al0 = __expf(mr[im][0] - mn0), al1 = __expf(mr[im][1] - mn1);
            float sum0 = 0.0f, sum1 = 0.0f;
#pragma unroll
            for (int jn = 0; jn < 8; jn++) {
                float* s4 = sac[im][jn];
                s4[0] = __expf(s4[0] - mn0);
                s4[1] = __expf(s4[1] - mn0);
                s4[2] = __expf(s4[2] - mn1);
                s4[3] = __expf(s4[3] - mn1);
                sum0 += s4[0] + s4[1];
                sum1 += s4[2] + s4[3];
            }
#pragma unroll
            for (int off = 1; off < 4; off <<= 1) {
                sum0 += __shfl_xor_sync(0xffffffffu, sum0, off);
                sum1 += __shfl_xor_sync(0xffffffffu, sum1, off);
            }
            lr[im][0] = lr[im][0] * al0 + sum0; mr[im][0] = mn0;
            lr[im][1] = lr[im][1] * al1 + sum1; mr[im][1] = mn1;
#pragma unroll
            for (int jn = 0; jn < 8; jn++) {
                float* o4 = oac[im][jn];
                o4[0] *= al0; o4[1] *= al0; o4[2] *= al1; o4[3] *= al1;
            }
        }

        // ---- O += P V, packing P fragments per k16-tile on the fly ----
#pragma unroll
        for (int t = 0; t < 4; t++) {
            uint32_t pfh[2][4], pfl[2][4];
#pragma unroll
            for (int im = 0; im < 2; im++)
#pragma unroll
                for (int half = 0; half < 2; half++) {
                    float* s4 = sac[im][2 * t + half];
                    uint32_t h01 = pack_bf2(s4[0], s4[1]);
                    uint32_t h23 = pack_bf2(s4[2], s4[3]);
                    __nv_bfloat162 bh01 = *(__nv_bfloat162*)&h01;
                    __nv_bfloat162 bh23 = *(__nv_bfloat162*)&h23;
                    pfh[im][half * 2 + 0] = h01;
                    pfh[im][half * 2 + 1] = h23;
                    pfl[im][half * 2 + 0] = pack_bf2(s4[0] - __bfloat162float(bh01.x),
                                                    s4[1] - __bfloat162float(bh01.y));
                    pfl[im][half * 2 + 1] = pack_bf2(s4[2] - __bfloat162float(bh23.x),
                                                    s4[3] - __bfloat162float(bh23.y));
                }
            uint32_t vhf[4][4], vlf[4][4];
#pragma unroll
            for (int db = 0; db < 4; db++) {
                uint32_t voff = ((16 * t + rA) * LKV + 16 * db + cA8) * 2;
                ldmx4t(vhf[db], sb + AVH + voff);
                ldmx4t(vlf[db], sb + AVL + voff);
            }
#pragma unroll
            for (int im = 0; im < 2; im++)
#pragma unroll
                for (int db = 0; db < 4; db++) {
                    mma16816(oac[im][2 * db],     pfh[im], vhf[db][0], vhf[db][1]);
                    mma16816(oac[im][2 * db + 1], pfh[im], vhf[db][2], vhf[db][3]);
                    mma16816(oac[im][2 * db],     pfh[im], vlf[db][0], vlf[db][1]);
                    mma16816(oac[im][2 * db + 1], pfh[im], vlf[db][2], vlf[db][3]);
                    mma16816(oac[im][2 * db],     pfl[im], vhf[db][0], vhf[db][1]);
                    mma16816(oac[im][2 * db + 1], pfl[im], vhf[db][2], vhf[db][3]);
                }
        }
        __syncthreads();                 // all warps done reading V + bias
        if (kt + 1 < NKT) {
            loadV(kt + 1);
            bias_s[tid] = bt[(kt + 1) * 64 + tid];
            if (tid < 63) bias_s[tid + 128] = bt[(kt + 1) * 64 + tid + 128];
        }
        cp_commit();
    }

    // ---- epilogue: normalize + split-bf16 store ----
#pragma unroll
    for (int im = 0; im < 2; im++) {
        const int r = q0 + wid * 32 + im * 16 + er;
        float inv0 = 1.0f / lr[im][0], inv1 = 1.0f / lr[im][1];
#pragma unroll
        for (int jn = 0; jn < 8; jn++) {
            int c = jn * 8 + qr;
            float* o4 = oac[im][jn];
            store_split2(Ch, Cl, base + (size_t)r * INNER + c,
                         o4[0] * inv0, o4[1] * inv0);
            store_split2(Ch, Cl, base + (size_t)(r + 8) * INNER + c,
                         o4[2] * inv1, o4[3] * inv1);
        }
    }
}

// ---------------------------------------------------------------------------
extern "C" void kernel_launch(void* const* d_in, const int* in_sizes, int n_in,
                              void* d_out, int out_size) {
    const float* hidden = (const float*)d_in[0];
    const float* Wq     = (const float*)d_in[1];
    const float* Wk     = (const float*)d_in[2];
    const float* Wv     = (const float*)d_in[3];
    const float* Wo     = (const float*)d_in[4];
    const float* rel    = (const float*)d_in[5];
    float* out = (float*)d_out;

    float* pB;
    __nv_bfloat16 *pHh, *pHl, *pQh, *pQl, *pKh, *pKl, *pVh, *pVl, *pCh, *pCl;
    __nv_bfloat16 *pWqTh, *pWqTl, *pWkTh, *pWkTl, *pWvTh, *pWvTl, *pWoTh, *pWoTl;
    cudaGetSymbolAddress((void**)&pB, g_biasTab);
    cudaGetSymbolAddress((void**)&pHh, g_Hh);
    cudaGetSymbolAddress((void**)&pHl, g_Hl);
    cudaGetSymbolAddress((void**)&pQh, g_Qh);
    cudaGetSymbolAddress((void**)&pQl, g_Ql);
    cudaGetSymbolAddress((void**)&pKh, g_Kh);
    cudaGetSymbolAddress((void**)&pKl, g_Kl);
    cudaGetSymbolAddress((void**)&pVh, g_Vh);
    cudaGetSymbolAddress((void**)&pVl, g_Vl);
    cudaGetSymbolAddress((void**)&pCh, g_Ch);
    cudaGetSymbolAddress((void**)&pCl, g_Cl);
    cudaGetSymbolAddress((void**)&pWqTh, g_WqTh);
    cudaGetSymbolAddress((void**)&pWqTl, g_WqTl);
    cudaGetSymbolAddress((void**)&pWkTh, g_WkTh);
    cudaGetSymbolAddress((void**)&pWkTl, g_WkTl);
    cudaGetSymbolAddress((void**)&pWvTh, g_WvTh);
    cudaGetSymbolAddress((void**)&pWvTl, g_WvTl);
    cudaGetSymbolAddress((void**)&pWoTh, g_WoTh);
    cudaGetSymbolAddress((void**)&pWoTl, g_WoTl);

    cudaFuncSetAttribute(mma_gemm,
                         cudaFuncAttributeMaxDynamicSharedMemorySize, 2 * STG_SZ);
    cudaFuncSetAttribute(attn_fa2,
                         cudaFuncAttributeMaxDynamicSharedMemorySize, ATTN_SMEM);

    bias_table_kernel<<<NH, 256>>>(rel, pB);

    int n4h = BS_TOT * DMODEL / 4;
    split_plain<<<n4h / 256, 256>>>(hidden, pHh, pHl, n4h);
    dim3 tgrid(DMODEL / 32, DMODEL / 32), tblk(32, 8);
    split_transpose<<<tgrid, tblk>>>(Wq, pWqTh, pWqTl, DMODEL, INNER);
    split_transpose<<<tgrid, tblk>>>(Wk, pWkTh, pWkTl, DMODEL, INNER);
    split_transpose<<<tgrid, tblk>>>(Wv, pWvTh, pWvTl, DMODEL, INNER);
    split_transpose<<<tgrid, tblk>>>(Wo, pWoTh, pWoTl, INNER, DMODEL);

    dim3 gproj(INNER / 128, BS_TOT / 128);
    mma_gemm<<<gproj, 128, 2 * STG_SZ>>>(pHh, pHl, pWqTh, pWqTl,
                                         nullptr, pQh, pQl, BS_TOT, INNER, DMODEL, 1);
    mma_gemm<<<gproj, 128, 2 * STG_SZ>>>(pHh, pHl, pWkTh, pWkTl,
                                         nullptr, pKh, pKl, BS_TOT, INNER, DMODEL, 1);
    mma_gemm<<<gproj, 128, 2 * STG_SZ>>>(pHh, pHl, pWvTh, pWvTl,
                                         nullptr, pVh, pVl, BS_TOT, INNER, DMODEL, 1);

    attn_fa2<<<dim3(SS / 128, BB * NH), 128, ATTN_SMEM>>>(
        pQh, pQl, pKh, pKl, pVh, pVl, pB, pCh, pCl);

    mma_gemm<<<dim3(DMODEL / 128, BS_TOT / 128), 128, 2 * STG_SZ>>>(
        pCh, pCl, pWoTh, pWoTl, out, nullptr, nullptr, BS_TOT, DMODEL, INNER, 0);
}

// round 7
// speedup vs baseline: 1.0404x; 1.0404x over previous
#include <cuda_runtime.h>
#include <cuda_bf16.h>
#include <math.h>
#include <stdint.h>

#define BB 4
#define SS 2048
#define DMODEL 1024
#define NH 16
#define DKV 64
#define INNER 1024
#define QSTR 3072              // fused QKV row stride
#define BS_TOT (BB * SS)
#define NREL 4095

// ---------------- scratch (device globals: allocation-free) ----------------
__device__ __align__(256) float g_biasTab[NH * NREL];
__device__ __align__(256) __nv_bfloat16 g_Hh[BS_TOT * DMODEL];
__device__ __align__(256) __nv_bfloat16 g_Hl[BS_TOT * DMODEL];
__device__ __align__(256) __nv_bfloat16 g_QKVh[BS_TOT * QSTR];
__device__ __align__(256) __nv_bfloat16 g_QKVl[BS_TOT * QSTR];
__device__ __align__(256) __nv_bfloat16 g_Ch[BS_TOT * INNER];
__device__ __align__(256) __nv_bfloat16 g_Cl[BS_TOT * INNER];
__device__ __align__(256) __nv_bfloat16 g_WTh[QSTR * DMODEL];   // [Wq;Wk;Wv]^T
__device__ __align__(256) __nv_bfloat16 g_WTl[QSTR * DMODEL];
__device__ __align__(256) __nv_bfloat16 g_WoTh[DMODEL * INNER];
__device__ __align__(256) __nv_bfloat16 g_WoTl[DMODEL * INNER];

// ---------------------------- PTX helpers ----------------------------------
__device__ __forceinline__ uint32_t smem_u32(const void* p) {
    uint32_t a;
    asm("{ .reg .u64 t; cvta.to.shared.u64 t, %1; cvt.u32.u64 %0, t; }"
        : "=r"(a) : "l"(p));
    return a;
}
__device__ __forceinline__ void cp16(uint32_t dst, const void* src) {
    asm volatile("cp.async.cg.shared.global [%0], [%1], 16;"
                 :: "r"(dst), "l"(src) : "memory");
}
__device__ __forceinline__ void cp_commit() {
    asm volatile("cp.async.commit_group;" ::: "memory");
}
__device__ __forceinline__ void cp_wait0() {
    asm volatile("cp.async.wait_group 0;" ::: "memory");
}
__device__ __forceinline__ void cp_wait1() {
    asm volatile("cp.async.wait_group 1;" ::: "memory");
}
__device__ __forceinline__ void ldmx4(uint32_t* r, uint32_t addr) {
    asm volatile("ldmatrix.sync.aligned.m8n8.x4.shared.b16 {%0,%1,%2,%3}, [%4];"
                 : "=r"(r[0]), "=r"(r[1]), "=r"(r[2]), "=r"(r[3]) : "r"(addr));
}
__device__ __forceinline__ void ldmx4t(uint32_t* r, uint32_t addr) {
    asm volatile("ldmatrix.sync.aligned.m8n8.x4.trans.shared.b16 {%0,%1,%2,%3}, [%4];"
                 : "=r"(r[0]), "=r"(r[1]), "=r"(r[2]), "=r"(r[3]) : "r"(addr));
}
__device__ __forceinline__ void mma16816(float* c, const uint32_t* a,
                                         uint32_t b0, uint32_t b1) {
    asm volatile("mma.sync.aligned.m16n8k16.row.col.f32.bf16.bf16.f32 "
                 "{%0,%1,%2,%3}, {%4,%5,%6,%7}, {%8,%9}, {%0,%1,%2,%3};"
                 : "+f"(c[0]), "+f"(c[1]), "+f"(c[2]), "+f"(c[3])
                 : "r"(a[0]), "r"(a[1]), "r"(a[2]), "r"(a[3]), "r"(b0), "r"(b1));
}
__device__ __forceinline__ uint32_t pack_bf2(float x, float y) {
    __nv_bfloat162 p;
    p.x = __float2bfloat16(x);
    p.y = __float2bfloat16(y);
    return *(uint32_t*)&p;
}
__device__ __forceinline__ void store_split2(__nv_bfloat16* Ch, __nv_bfloat16* Cl,
                                             size_t off, float x, float y) {
    __nv_bfloat16 hx = __float2bfloat16(x), hy = __float2bfloat16(y);
    __nv_bfloat16 lx = __float2bfloat16(x - __bfloat162float(hx));
    __nv_bfloat16 ly = __float2bfloat16(y - __bfloat162float(hy));
    __nv_bfloat162 ph; ph.x = hx; ph.y = hy;
    __nv_bfloat162 pl; pl.x = lx; pl.y = ly;
    *(__nv_bfloat162*)(Ch + off) = ph;
    *(__nv_bfloat162*)(Cl + off) = pl;
}

// ---------------------------------------------------------------------------
// Relative-position bias table
// ---------------------------------------------------------------------------
__global__ void bias_table_kernel(const float* __restrict__ rel_emb,
                                  float* __restrict__ biasTab) {
    int h = blockIdx.x;
    for (int idx = threadIdx.x; idx < NREL; idx += blockDim.x) {
        int rel = idx - (SS - 1);
        int n = -rel;
        int ret = 0;
        if (n < 0) { ret = 16; n = -n; }
        int bucket;
        if (n < 8) {
            bucket = ret + n;
        } else {
            float v = logf((float)n / 8.0f) / logf(16.0f) * 8.0f;
            int vi = 8 + (int)v;
            if (vi > 15) vi = 15;
            bucket = ret + vi;
        }
        biasTab[h * NREL + idx] = rel_emb[bucket * NH + h];
    }
}

// ---------------------------------------------------------------------------
// fp32 -> bf16 hi/lo split (row-major)
// ---------------------------------------------------------------------------
__global__ __launch_bounds__(256) void split_plain(const float* __restrict__ X,
                                                   __nv_bfloat16* __restrict__ Xh,
                                                   __nv_bfloat16* __restrict__ Xl,
                                                   int n4) {
    int i = blockIdx.x * 256 + threadIdx.x;
    if (i >= n4) return;
    float4 v = ((const float4*)X)[i];
    __nv_bfloat16 h0 = __float2bfloat16(v.x), h1 = __float2bfloat16(v.y);
    __nv_bfloat16 h2 = __float2bfloat16(v.z), h3 = __float2bfloat16(v.w);
    __nv_bfloat16 l0 = __float2bfloat16(v.x - __bfloat162float(h0));
    __nv_bfloat16 l1 = __float2bfloat16(v.y - __bfloat162float(h1));
    __nv_bfloat16 l2 = __float2bfloat16(v.z - __bfloat162float(h2));
    __nv_bfloat16 l3 = __float2bfloat16(v.w - __bfloat162float(h3));
    __nv_bfloat162 ph0; ph0.x = h0; ph0.y = h1;
    __nv_bfloat162 ph1; ph1.x = h2; ph1.y = h3;
    __nv_bfloat162 pl0; pl0.x = l0; pl0.y = l1;
    __nv_bfloat162 pl1; pl1.x = l2; pl1.y = l3;
    ((__nv_bfloat162*)Xh)[2 * i]     = ph0;
    ((__nv_bfloat162*)Xh)[2 * i + 1] = ph1;
    ((__nv_bfloat162*)Xl)[2 * i]     = pl0;
    ((__nv_bfloat162*)Xl)[2 * i + 1] = pl1;
}

// ---------------------------------------------------------------------------
// Weight transpose + split. 1024x1024 each.
// split_transpose3: Wq/Wk/Wv -> concatenated [3072,1024] K-major (z selects).
// ---------------------------------------------------------------------------
__device__ __forceinline__ void transp_tile(const float* __restrict__ W,
                                            __nv_bfloat16* __restrict__ Th,
                                            __nv_bfloat16* __restrict__ Tl) {
    __shared__ float t[32][33];
    int bx = blockIdx.x * 32, by = blockIdx.y * 32;
    int tx = threadIdx.x, ty = threadIdx.y;
#pragma unroll
    for (int i = 0; i < 32; i += 8)
        t[ty + i][tx] = W[(size_t)(by + ty + i) * DMODEL + bx + tx];
    __syncthreads();
#pragma unroll
    for (int i = 0; i < 32; i += 8) {
        float v = t[tx][ty + i];
        __nv_bfloat16 h = __float2bfloat16(v);
        __nv_bfloat16 l = __float2bfloat16(v - __bfloat162float(h));
        size_t o = (size_t)(bx + ty + i) * DMODEL + by + tx;
        Th[o] = h;
        Tl[o] = l;
    }
}
__global__ __launch_bounds__(256)
void split_transpose3(const float* __restrict__ Wq, const float* __restrict__ Wk,
                      const float* __restrict__ Wv,
                      __nv_bfloat16* __restrict__ Th, __nv_bfloat16* __restrict__ Tl) {
    const float* W = (blockIdx.z == 0) ? Wq : (blockIdx.z == 1) ? Wk : Wv;
    size_t off = (size_t)blockIdx.z * DMODEL * DMODEL;
    transp_tile(W, Th + off, Tl + off);
}
__global__ __launch_bounds__(256)
void split_transpose1(const float* __restrict__ W,
                      __nv_bfloat16* __restrict__ Th, __nv_bfloat16* __restrict__ Tl) {
    transp_tile(W, Th, Tl);
}

// ---------------------------------------------------------------------------
// Split-bf16 mma.sync GEMM: C[M,N] = A[M,K] @ BT[N,K]^T
// 128x128 tile, BK=32, 256 threads (8 warps, 2x4), 2-stage cp.async pipeline.
// ---------------------------------------------------------------------------
#define LDS 40
#define STG_A_L 10240
#define STG_B_H 20480
#define STG_B_L 30720
#define STG_SZ  40960

__global__ __launch_bounds__(256)
void mma_gemm(const __nv_bfloat16* __restrict__ Ah, const __nv_bfloat16* __restrict__ Al,
              const __nv_bfloat16* __restrict__ Bh, const __nv_bfloat16* __restrict__ Bl,
              float* __restrict__ Cf,
              __nv_bfloat16* __restrict__ Ch, __nv_bfloat16* __restrict__ Cl,
              int M, int N, int K, int split_out) {
    extern __shared__ __align__(128) char smem[];
    const int tid = threadIdx.x, lane = tid & 31, wid = tid >> 5;
    const int wm = wid >> 2, wn = wid & 3;
    const int rowA0 = blockIdx.y * 128, rowB0 = blockIdx.x * 128;
    const uint32_t sb = smem_u32(smem);
    const int nk = K >> 5;

    float acc[16][4];
#pragma unroll
    for (int i = 0; i < 16; i++)
#pragma unroll
        for (int j = 0; j < 4; j++) acc[i][j] = 0.0f;

    auto load_stage = [&](int stage, int kc) {
        const uint32_t d0 = sb + (uint32_t)stage * STG_SZ;
        const int k0 = kc * 32;
#pragma unroll
        for (int i = 0; i < 8; i++) {
            int id = tid + i * 256;
            int arr = id >> 9;
            int rem = id & 511;
            int row = rem >> 2;
            int ch  = (rem & 3) << 4;
            uint32_t dst = d0 + arr * 10240 + row * 80 + ch;
            const __nv_bfloat16* src = (arr == 0) ? Ah : (arr == 1) ? Al
                                    : (arr == 2) ? Bh : Bl;
            int grow = ((arr < 2) ? rowA0 : rowB0) + row;
            cp16(dst, (const char*)src + ((size_t)grow * K + k0) * 2 + ch);
        }
        cp_commit();
    };

    load_stage(0, 0);

    const int rA = lane & 15;
    const int cA8 = (lane >> 4) << 3;

    for (int kc = 0; kc < nk; kc++) {
        const int s = kc & 1;
        if (kc + 1 < nk) { load_stage(s ^ 1, kc + 1); cp_wait1(); }
        else             { cp_wait0(); }
        __syncthreads();

        const uint32_t base = sb + (uint32_t)s * STG_SZ;
#pragma unroll
        for (int ks = 0; ks < 32; ks += 16) {
            uint32_t a_h[4][4], b_h[2][4], b_l[2][4];
#pragma unroll
            for (int im = 0; im < 4; im++)
                ldmx4(a_h[im], base + ((64 * wm + im * 16 + rA) * LDS + ks + cA8) * 2);
#pragma unroll
            for (int jb = 0; jb < 2; jb++) {
                uint32_t boff = ((32 * wn + jb * 16 + rA) * LDS + ks + cA8) * 2;
                ldmx4(b_h[jb], base + STG_B_H + boff);
                ldmx4(b_l[jb], base + STG_B_L + boff);
            }
#pragma unroll
            for (int im = 0; im < 4; im++)
#pragma unroll
                for (int jn = 0; jn < 4; jn++) {
                    int jb = jn >> 1, sub = jn & 1;
                    mma16816(acc[im * 4 + jn], a_h[im], b_h[jb][sub], b_h[jb][sub + 2]);
                    mma16816(acc[im * 4 + jn], a_h[im], b_l[jb][sub], b_l[jb][sub + 2]);
                }
#pragma unroll
            for (int im = 0; im < 4; im++) {
                uint32_t a_l[4];
                ldmx4(a_l, base + STG_A_L + ((64 * wm + im * 16 + rA) * LDS + ks + cA8) * 2);
#pragma unroll
                for (int jn = 0; jn < 4; jn++) {
                    int jb = jn >> 1, sub = jn & 1;
                    mma16816(acc[im * 4 + jn], a_l, b_h[jb][sub], b_h[jb][sub + 2]);
                }
            }
        }
        __syncthreads();
    }

    const int er = lane >> 2, ec = (lane & 3) << 1;
#pragma unroll
    for (int im = 0; im < 4; im++) {
        int r0 = rowA0 + 64 * wm + im * 16 + er;
#pragma unroll
        for (int jn = 0; jn < 4; jn++) {
            int c = rowB0 + 32 * wn + jn * 8 + ec;
            float* a = acc[im * 4 + jn];
            if (split_out) {
                store_split2(Ch, Cl, (size_t)r0 * N + c, a[0], a[1]);
                store_split2(Ch, Cl, (size_t)(r0 + 8) * N + c, a[2], a[3]);
            } else {
                *(float2*)(Cf + (size_t)r0 * N + c) = make_float2(a[0], a[1]);
                *(float2*)(Cf + (size_t)(r0 + 8) * N + c) = make_float2(a[2], a[3]);
            }
        }
    }
}

// ---------------------------------------------------------------------------
// Register-resident FA2 flash attention (split-bf16 mma, T5 bias).
// Grid (S/128, B*H), 256 threads = 8 warps; each warp: 16 q-rows x 64 keys.
// Q/K/V read from fused [8192,3072] arrays (offsets 0/1024/2048).
// ---------------------------------------------------------------------------
#define LKV 72
#define AQH 0
#define AQL 18432
#define AKH 36864
#define AKL 46080
#define AVH 55296
#define AVL 64512
#define ABIAS 73728
#define ATTN_SMEM 74624
#define NKT (SS / 64)

__global__ __launch_bounds__(256, 2)
void attn_fa2(const __nv_bfloat16* __restrict__ Xh, const __nv_bfloat16* __restrict__ Xl,
              const float* __restrict__ biasTab,
              __nv_bfloat16* __restrict__ Ch, __nv_bfloat16* __restrict__ Cl) {
    extern __shared__ __align__(128) char sm[];
    const int tid = threadIdx.x, lane = tid & 31, wid = tid >> 5;
    const int qt = blockIdx.x, bhi = blockIdx.y;
    const int b = bhi >> 4, h = bhi & 15;
    const int q0 = qt * 128;
    const size_t ibase = (size_t)b * SS * QSTR + (size_t)h * DKV;
    const size_t obase = (size_t)b * SS * INNER + (size_t)h * DKV;
    const float* bt = biasTab + h * NREL + (SS - 1) - q0 - 127;   // index by k0+i
    const uint32_t sb = smem_u32(sm);
    float* bias_s = (float*)(sm + ABIAS);

    const int rA = lane & 15, cA8 = (lane >> 4) << 3;
    const int er = lane >> 2, qr = (lane & 3) << 1;
    const int r0 = wid * 16 + er, r1 = r0 + 8;

    auto loadK = [&](int kt) {
        const int k0 = kt * 64;
#pragma unroll
        for (int i = 0; i < 4; i++) {
            int id = tid + i * 256;
            int arr = id >> 9, rem = id & 511;
            int row = rem >> 3, ch = (rem & 7) << 4;
            const __nv_bfloat16* src = arr ? Xl : Xh;
            cp16(sb + AKH + arr * 9216 + row * 144 + ch,
                 (const char*)src + (ibase + 1024 + (size_t)(k0 + row) * QSTR) * 2 + ch);
        }
    };
    auto loadV = [&](int kt) {
        const int k0 = kt * 64;
#pragma unroll
        for (int i = 0; i < 4; i++) {
            int id = tid + i * 256;
            int arr = id >> 9, rem = id & 511;
            int row = rem >> 3, ch = (rem & 7) << 4;
            const __nv_bfloat16* src = arr ? Xl : Xh;
            cp16(sb + AVH + arr * 9216 + row * 144 + ch,
                 (const char*)src + (ibase + 2048 + (size_t)(k0 + row) * QSTR) * 2 + ch);
        }
    };

    // Q tile (hi+lo): 128 rows x 64 cols
#pragma unroll
    for (int i = 0; i < 8; i++) {
        int id = tid + i * 256;
        int arr = id >> 10, rem = id & 1023;
        int row = rem >> 3, ch = (rem & 7) << 4;
        const __nv_bfloat16* src = arr ? Xl : Xh;
        cp16(sb + (arr ? AQL : AQH) + row * 144 + ch,
             (const char*)src + (ibase + (size_t)(q0 + row) * QSTR) * 2 + ch);
    }
    loadK(0);
    loadV(0);
    if (tid < 191) bias_s[tid] = bt[tid];     // k0 = 0
    cp_commit();

    float m0 = -1e30f, m1 = -1e30f, l0 = 0.0f, l1 = 0.0f;
    float oac[8][4];
#pragma unroll
    for (int i = 0; i < 8; i++)
#pragma unroll
        for (int j = 0; j < 4; j++) oac[i][j] = 0.0f;

    for (int kt = 0; kt < NKT; kt++) {
        cp_wait0();
        __syncthreads();

        // ---- S = Q K^T (m16 x n64 per warp, in registers) ----
        float sac[8][4];
#pragma unroll
        for (int i = 0; i < 8; i++)
#pragma unroll
            for (int j = 0; j < 4; j++) sac[i][j] = 0.0f;
#pragma unroll
        for (int ks = 0; ks < 64; ks += 16) {
            uint32_t qfh[4], qfl[4], khf[4][4], klf[4][4];
            uint32_t aoff = ((wid * 16 + rA) * LKV + ks + cA8) * 2;
            ldmx4(qfh, sb + AQH + aoff);
            ldmx4(qfl, sb + AQL + aoff);
#pragma unroll
            for (int kb = 0; kb < 4; kb++) {
                uint32_t boff = ((16 * kb + rA) * LKV + ks + cA8) * 2;
                ldmx4(khf[kb], sb + AKH + boff);
                ldmx4(klf[kb], sb + AKL + boff);
            }
#pragma unroll
            for (int jn = 0; jn < 8; jn++) {
                int kb = jn >> 1, sub = jn & 1;
                mma16816(sac[jn], qfh, khf[kb][sub], khf[kb][sub + 2]);
                mma16816(sac[jn], qfh, klf[kb][sub], klf[kb][sub + 2]);
                mma16816(sac[jn], qfl, khf[kb][sub], khf[kb][sub + 2]);
            }
        }
        __syncthreads();                 // all warps done reading K
        if (kt + 1 < NKT) loadK(kt + 1); // overlap next-K with softmax+PV
        cp_commit();

        // ---- softmax in registers ----
        float vx0 = -1e30f, vx1 = -1e30f;
#pragma unroll
        for (int jn = 0; jn < 8; jn++) {
            int c = jn * 8 + qr;
            sac[jn][0] += bias_s[c - r0 + 127];
            sac[jn][1] += bias_s[c + 1 - r0 + 127];
            sac[jn][2] += bias_s[c - r1 + 127];
            sac[jn][3] += bias_s[c + 1 - r1 + 127];
            vx0 = fmaxf(vx0, fmaxf(sac[jn][0], sac[jn][1]));
            vx1 = fmaxf(vx1, fmaxf(sac[jn][2], sac[jn][3]));
        }
#pragma unroll
        for (int off = 1; off < 4; off <<= 1) {
            vx0 = fmaxf(vx0, __shfl_xor_sync(0xffffffffu, vx0, off));
            vx1 = fmaxf(vx1, __shfl_xor_sync(0xffffffffu, vx1, off));
        }
        float mn0 = fmaxf(m0, vx0), mn1 = fmaxf(m1, vx1);
        float al0 = __expf(m0 - mn0), al1 = __expf(m1 - mn1);
        float sum0 = 0.0f, sum1 = 0.0f;
        uint32_t pfh[4][4], pfl[4][4];
#pragma unroll
        for (int t = 0; t < 4; t++) {
#pragma unroll
            for (int half = 0; half < 2; half++) {
                int j = 2 * t + half;
                float e0 = __expf(sac[j][0] - mn0);
                float e1 = __expf(sac[j][1] - mn0);
                float e2 = __expf(sac[j][2] - mn1);
                float e3 = __expf(sac[j][3] - mn1);
                sum0 += e0 + e1;
                sum1 += e2 + e3;
                uint32_t h01 = pack_bf2(e0, e1);
                uint32_t h23 = pack_bf2(e2, e3);
                __nv_bfloat162 bh01 = *(__nv_bfloat162*)&h01;
                __nv_bfloat162 bh23 = *(__nv_bfloat162*)&h23;
                uint32_t lo01 = pack_bf2(e0 - __bfloat162float(bh01.x),
                                         e1 - __bfloat162float(bh01.y));
                uint32_t lo23 = pack_bf2(e2 - __bfloat162float(bh23.x),
                                         e3 - __bfloat162float(bh23.y));
                pfh[t][half * 2 + 0] = h01;
                pfh[t][half * 2 + 1] = h23;
                pfl[t][half * 2 + 0] = lo01;
                pfl[t][half * 2 + 1] = lo23;
            }
        }
#pragma unroll
        for (int off = 1; off < 4; off <<= 1) {
            sum0 += __shfl_xor_sync(0xffffffffu, sum0, off);
            sum1 += __shfl_xor_sync(0xffffffffu, sum1, off);
        }
        l0 = l0 * al0 + sum0; m0 = mn0;
        l1 = l1 * al1 + sum1; m1 = mn1;
#pragma unroll
        for (int jn = 0; jn < 8; jn++) {
            oac[jn][0] *= al0; oac[jn][1] *= al0;
            oac[jn][2] *= al1; oac[jn][3] *= al1;
        }

        // ---- O += P V ----
#pragma unroll
        for (int t = 0; t < 4; t++) {
            uint32_t vhf[4][4], vlf[4][4];
#pragma unroll
            for (int db = 0; db < 4; db++) {
                uint32_t voff = ((16 * t + rA) * LKV + 16 * db + cA8) * 2;
                ldmx4t(vhf[db], sb + AVH + voff);
                ldmx4t(vlf[db], sb + AVL + voff);
            }
#pragma unroll
            for (int db = 0; db < 4; db++) {
                mma16816(oac[2 * db],     pfh[t], vhf[db][0], vhf[db][1]);
                mma16816(oac[2 * db + 1], pfh[t], vhf[db][2], vhf[db][3]);
                mma16816(oac[2 * db],     pfh[t], vlf[db][0], vlf[db][1]);
                mma16816(oac[2 * db + 1], pfh[t], vlf[db][2], vlf[db][3]);
                mma16816(oac[2 * db],     pfl[t], vhf[db][0], vhf[db][1]);
                mma16816(oac[2 * db + 1], pfl[t], vhf[db][2], vhf[db][3]);
            }
        }
        __syncthreads();                 // all warps done reading V + bias
        if (kt + 1 < NKT) {
            loadV(kt + 1);
            if (tid < 191) bias_s[tid] = bt[(kt + 1) * 64 + tid];
        }
        cp_commit();
    }

    // ---- epilogue: normalize + split-bf16 store ----
    float inv0 = 1.0f / l0, inv1 = 1.0f / l1;
#pragma unroll
    for (int jn = 0; jn < 8; jn++) {
        int c = jn * 8 + qr;
        store_split2(Ch, Cl, obase + (size_t)(q0 + r0) * INNER + c,
                     oac[jn][0] * inv0, oac[jn][1] * inv0);
        store_split2(Ch, Cl, obase + (size_t)(q0 + r1) * INNER + c,
                     oac[jn][2] * inv1, oac[jn][3] * inv1);
    }
}

// ---------------------------------------------------------------------------
extern "C" void kernel_launch(void* const* d_in, const int* in_sizes, int n_in,
                              void* d_out, int out_size) {
    const float* hidden = (const float*)d_in[0];
    const float* Wq     = (const float*)d_in[1];
    const float* Wk     = (const float*)d_in[2];
    const float* Wv     = (const float*)d_in[3];
    const float* Wo     = (const float*)d_in[4];
    const float* rel    = (const float*)d_in[5];
    float* out = (float*)d_out;

    float* pB;
    __nv_bfloat16 *pHh, *pHl, *pXh, *pXl, *pCh, *pCl;
    __nv_bfloat16 *pWTh, *pWTl, *pWoTh, *pWoTl;
    cudaGetSymbolAddress((void**)&pB, g_biasTab);
    cudaGetSymbolAddress((void**)&pHh, g_Hh);
    cudaGetSymbolAddress((void**)&pHl, g_Hl);
    cudaGetSymbolAddress((void**)&pXh, g_QKVh);
    cudaGetSymbolAddress((void**)&pXl, g_QKVl);
    cudaGetSymbolAddress((void**)&pCh, g_Ch);
    cudaGetSymbolAddress((void**)&pCl, g_Cl);
    cudaGetSymbolAddress((void**)&pWTh, g_WTh);
    cudaGetSymbolAddress((void**)&pWTl, g_WTl);
    cudaGetSymbolAddress((void**)&pWoTh, g_WoTh);
    cudaGetSymbolAddress((void**)&pWoTl, g_WoTl);

    cudaFuncSetAttribute(mma_gemm,
                         cudaFuncAttributeMaxDynamicSharedMemorySize, 2 * STG_SZ);
    cudaFuncSetAttribute(attn_fa2,
                         cudaFuncAttributeMaxDynamicSharedMemorySize, ATTN_SMEM);

    // launch 1: bias table
    bias_table_kernel<<<NH, 256>>>(rel, pB);
    // launch 2: split hidden
    int n4h = BS_TOT * DMODEL / 4;
    split_plain<<<n4h / 256, 256>>>(hidden, pHh, pHl, n4h);
    // launch 3: transpose+split Wq/Wk/Wv -> [3072,1024]
    dim3 tblk(32, 8);
    split_transpose3<<<dim3(32, 32, 3), tblk>>>(Wq, Wk, Wv, pWTh, pWTl);
    // launch 4: transpose+split Wo
    split_transpose1<<<dim3(32, 32), tblk>>>(Wo, pWoTh, pWoTl);
    // launch 5: fused QKV projection -> [8192,3072] split-bf16
    mma_gemm<<<dim3(QSTR / 128, BS_TOT / 128), 256, 2 * STG_SZ>>>(
        pHh, pHl, pWTh, pWTl, nullptr, pXh, pXl, BS_TOT, QSTR, DMODEL, 1);
    // launch 6 (ncu capture target): attention
    attn_fa2<<<dim3(SS / 128, BB * NH), 256, ATTN_SMEM>>>(
        pXh, pXl, pB, pCh, pCl);
    // launch 7: output projection -> f32 out
    mma_gemm<<<dim3(DMODEL / 128, BS_TOT / 128), 256, 2 * STG_SZ>>>(
        pCh, pCl, pWoTh, pWoTl, out, nullptr, nullptr, BS_TOT, DMODEL, INNER, 0);
}

// round 8
// speedup vs baseline: 1.1981x; 1.1515x over previous
#include <cuda_runtime.h>
#include <cuda_fp16.h>
#include <math.h>
#include <stdint.h>

#define BB 4
#define SS 2048
#define DMODEL 1024
#define NH 16
#define DKV 64
#define INNER 1024
#define QSTR 3072              // fused QKV row stride
#define BS_TOT (BB * SS)
#define NREL 4095

// ---------------- scratch (device globals: allocation-free) ----------------
__device__ __align__(256) float g_biasTab[NH * NREL];
__device__ __align__(256) __half g_Hh[BS_TOT * DMODEL];
__device__ __align__(256) __half g_Hl[BS_TOT * DMODEL];
__device__ __align__(256) __half g_QKVh[BS_TOT * QSTR];
__device__ __align__(256) __half g_QKVl[BS_TOT * QSTR];
__device__ __align__(256) __half g_Ch[BS_TOT * INNER];
__device__ __align__(256) __half g_Cl[BS_TOT * INNER];
__device__ __align__(256) __half g_WTh[QSTR * DMODEL];   // [Wq;Wk;Wv]^T
__device__ __align__(256) __half g_WTl[QSTR * DMODEL];
__device__ __align__(256) __half g_WoTh[DMODEL * INNER];
__device__ __align__(256) __half g_WoTl[DMODEL * INNER];

// ---------------------------- PTX helpers ----------------------------------
__device__ __forceinline__ uint32_t smem_u32(const void* p) {
    uint32_t a;
    asm("{ .reg .u64 t; cvta.to.shared.u64 t, %1; cvt.u32.u64 %0, t; }"
        : "=r"(a) : "l"(p));
    return a;
}
__device__ __forceinline__ void cp16(uint32_t dst, const void* src) {
    asm volatile("cp.async.cg.shared.global [%0], [%1], 16;"
                 :: "r"(dst), "l"(src) : "memory");
}
__device__ __forceinline__ void cp_commit() {
    asm volatile("cp.async.commit_group;" ::: "memory");
}
__device__ __forceinline__ void cp_wait0() {
    asm volatile("cp.async.wait_group 0;" ::: "memory");
}
__device__ __forceinline__ void cp_wait1() {
    asm volatile("cp.async.wait_group 1;" ::: "memory");
}
__device__ __forceinline__ void ldmx4(uint32_t* r, uint32_t addr) {
    asm volatile("ldmatrix.sync.aligned.m8n8.x4.shared.b16 {%0,%1,%2,%3}, [%4];"
                 : "=r"(r[0]), "=r"(r[1]), "=r"(r[2]), "=r"(r[3]) : "r"(addr));
}
__device__ __forceinline__ void ldmx4t(uint32_t* r, uint32_t addr) {
    asm volatile("ldmatrix.sync.aligned.m8n8.x4.trans.shared.b16 {%0,%1,%2,%3}, [%4];"
                 : "=r"(r[0]), "=r"(r[1]), "=r"(r[2]), "=r"(r[3]) : "r"(addr));
}
__device__ __forceinline__ void mma16816(float* c, const uint32_t* a,
                                         uint32_t b0, uint32_t b1) {
    asm volatile("mma.sync.aligned.m16n8k16.row.col.f32.f16.f16.f32 "
                 "{%0,%1,%2,%3}, {%4,%5,%6,%7}, {%8,%9}, {%0,%1,%2,%3};"
                 : "+f"(c[0]), "+f"(c[1]), "+f"(c[2]), "+f"(c[3])
                 : "r"(a[0]), "r"(a[1]), "r"(a[2]), "r"(a[3]), "r"(b0), "r"(b1));
}
__device__ __forceinline__ uint32_t pack_hf2(float x, float y) {
    __half2 p = __floats2half2_rn(x, y);
    return *(uint32_t*)&p;
}
__device__ __forceinline__ void store_split2(__half* Ch, __half* Cl,
                                             size_t off, float x, float y) {
    __half hx = __float2half_rn(x), hy = __float2half_rn(y);
    __half lx = __float2half_rn(x - __half2float(hx));
    __half ly = __float2half_rn(y - __half2float(hy));
    *(__half2*)(Ch + off) = __halves2half2(hx, hy);
    *(__half2*)(Cl + off) = __halves2half2(lx, ly);
}

// ---------------------------------------------------------------------------
// Relative-position bias table
// ---------------------------------------------------------------------------
__global__ void bias_table_kernel(const float* __restrict__ rel_emb,
                                  float* __restrict__ biasTab) {
    int h = blockIdx.x;
    for (int idx = threadIdx.x; idx < NREL; idx += blockDim.x) {
        int rel = idx - (SS - 1);
        int n = -rel;
        int ret = 0;
        if (n < 0) { ret = 16; n = -n; }
        int bucket;
        if (n < 8) {
            bucket = ret + n;
        } else {
            float v = logf((float)n / 8.0f) / logf(16.0f) * 8.0f;
            int vi = 8 + (int)v;
            if (vi > 15) vi = 15;
            bucket = ret + vi;
        }
        biasTab[h * NREL + idx] = rel_emb[bucket * NH + h];
    }
}

// ---------------------------------------------------------------------------
// fp32 -> fp16 hi/lo split (row-major)
// ---------------------------------------------------------------------------
__global__ __launch_bounds__(256) void split_plain(const float* __restrict__ X,
                                                   __half* __restrict__ Xh,
                                                   __half* __restrict__ Xl,
                                                   int n4) {
    int i = blockIdx.x * 256 + threadIdx.x;
    if (i >= n4) return;
    float4 v = ((const float4*)X)[i];
    __half h0 = __float2half_rn(v.x), h1 = __float2half_rn(v.y);
    __half h2 = __float2half_rn(v.z), h3 = __float2half_rn(v.w);
    __half l0 = __float2half_rn(v.x - __half2float(h0));
    __half l1 = __float2half_rn(v.y - __half2float(h1));
    __half l2 = __float2half_rn(v.z - __half2float(h2));
    __half l3 = __float2half_rn(v.w - __half2float(h3));
    ((__half2*)Xh)[2 * i]     = __halves2half2(h0, h1);
    ((__half2*)Xh)[2 * i + 1] = __halves2half2(h2, h3);
    ((__half2*)Xl)[2 * i]     = __halves2half2(l0, l1);
    ((__half2*)Xl)[2 * i + 1] = __halves2half2(l2, l3);
}

// ---------------------------------------------------------------------------
// Weight transpose + split. 1024x1024 each.
// ---------------------------------------------------------------------------
__device__ __forceinline__ void transp_tile(const float* __restrict__ W,
                                            __half* __restrict__ Th,
                                            __half* __restrict__ Tl) {
    __shared__ float t[32][33];
    int bx = blockIdx.x * 32, by = blockIdx.y * 32;
    int tx = threadIdx.x, ty = threadIdx.y;
#pragma unroll
    for (int i = 0; i < 32; i += 8)
        t[ty + i][tx] = W[(size_t)(by + ty + i) * DMODEL + bx + tx];
    __syncthreads();
#pragma unroll
    for (int i = 0; i < 32; i += 8) {
        float v = t[tx][ty + i];
        __half h = __float2half_rn(v);
        __half l = __float2half_rn(v - __half2float(h));
        size_t o = (size_t)(bx + ty + i) * DMODEL + by + tx;
        Th[o] = h;
        Tl[o] = l;
    }
}
__global__ __launch_bounds__(256)
void split_transpose3(const float* __restrict__ Wq, const float* __restrict__ Wk,
                      const float* __restrict__ Wv,
                      __half* __restrict__ Th, __half* __restrict__ Tl) {
    const float* W = (blockIdx.z == 0) ? Wq : (blockIdx.z == 1) ? Wk : Wv;
    size_t off = (size_t)blockIdx.z * DMODEL * DMODEL;
    transp_tile(W, Th + off, Tl + off);
}
__global__ __launch_bounds__(256)
void split_transpose1(const float* __restrict__ W,
                      __half* __restrict__ Th, __half* __restrict__ Tl) {
    transp_tile(W, Th, Tl);
}

// ---------------------------------------------------------------------------
// Split-fp16 mma.sync GEMM: C[M,N] = A[M,K] @ BT[N,K]^T
// 128x128 tile, BK=32, 256 threads (8 warps, 2x4), 2-stage cp.async pipeline.
// ---------------------------------------------------------------------------
#define LDS 40
#define STG_A_L 10240
#define STG_B_H 20480
#define STG_B_L 30720
#define STG_SZ  40960

__global__ __launch_bounds__(256)
void mma_gemm(const __half* __restrict__ Ah, const __half* __restrict__ Al,
              const __half* __restrict__ Bh, const __half* __restrict__ Bl,
              float* __restrict__ Cf,
              __half* __restrict__ Ch, __half* __restrict__ Cl,
              int M, int N, int K, int split_out) {
    extern __shared__ __align__(128) char smem[];
    const int tid = threadIdx.x, lane = tid & 31, wid = tid >> 5;
    const int wm = wid >> 2, wn = wid & 3;
    const int rowA0 = blockIdx.y * 128, rowB0 = blockIdx.x * 128;
    const uint32_t sb = smem_u32(smem);
    const int nk = K >> 5;

    float acc[16][4];
#pragma unroll
    for (int i = 0; i < 16; i++)
#pragma unroll
        for (int j = 0; j < 4; j++) acc[i][j] = 0.0f;

    auto load_stage = [&](int stage, int kc) {
        const uint32_t d0 = sb + (uint32_t)stage * STG_SZ;
        const int k0 = kc * 32;
#pragma unroll
        for (int i = 0; i < 8; i++) {
            int id = tid + i * 256;
            int arr = id >> 9;
            int rem = id & 511;
            int row = rem >> 2;
            int ch  = (rem & 3) << 4;
            uint32_t dst = d0 + arr * 10240 + row * 80 + ch;
            const __half* src = (arr == 0) ? Ah : (arr == 1) ? Al
                             : (arr == 2) ? Bh : Bl;
            int grow = ((arr < 2) ? rowA0 : rowB0) + row;
            cp16(dst, (const char*)src + ((size_t)grow * K + k0) * 2 + ch);
        }
        cp_commit();
    };

    load_stage(0, 0);

    const int rA = lane & 15;
    const int cA8 = (lane >> 4) << 3;

    for (int kc = 0; kc < nk; kc++) {
        const int s = kc & 1;
        if (kc + 1 < nk) { load_stage(s ^ 1, kc + 1); cp_wait1(); }
        else             { cp_wait0(); }
        __syncthreads();

        const uint32_t base = sb + (uint32_t)s * STG_SZ;
#pragma unroll
        for (int ks = 0; ks < 32; ks += 16) {
            uint32_t a_h[4][4], b_h[2][4], b_l[2][4];
#pragma unroll
            for (int im = 0; im < 4; im++)
                ldmx4(a_h[im], base + ((64 * wm + im * 16 + rA) * LDS + ks + cA8) * 2);
#pragma unroll
            for (int jb = 0; jb < 2; jb++) {
                uint32_t boff = ((32 * wn + jb * 16 + rA) * LDS + ks + cA8) * 2;
                ldmx4(b_h[jb], base + STG_B_H + boff);
                ldmx4(b_l[jb], base + STG_B_L + boff);
            }
#pragma unroll
            for (int im = 0; im < 4; im++)
#pragma unroll
                for (int jn = 0; jn < 4; jn++) {
                    int jb = jn >> 1, sub = jn & 1;
                    mma16816(acc[im * 4 + jn], a_h[im], b_h[jb][sub], b_h[jb][sub + 2]);
                    mma16816(acc[im * 4 + jn], a_h[im], b_l[jb][sub], b_l[jb][sub + 2]);
                }
#pragma unroll
            for (int im = 0; im < 4; im++) {
                uint32_t a_l[4];
                ldmx4(a_l, base + STG_A_L + ((64 * wm + im * 16 + rA) * LDS + ks + cA8) * 2);
#pragma unroll
                for (int jn = 0; jn < 4; jn++) {
                    int jb = jn >> 1, sub = jn & 1;
                    mma16816(acc[im * 4 + jn], a_l, b_h[jb][sub], b_h[jb][sub + 2]);
                }
            }
        }
        __syncthreads();
    }

    const int er = lane >> 2, ec = (lane & 3) << 1;
#pragma unroll
    for (int im = 0; im < 4; im++) {
        int r0 = rowA0 + 64 * wm + im * 16 + er;
#pragma unroll
        for (int jn = 0; jn < 4; jn++) {
            int c = rowB0 + 32 * wn + jn * 8 + ec;
            float* a = acc[im * 4 + jn];
            if (split_out) {
                store_split2(Ch, Cl, (size_t)r0 * N + c, a[0], a[1]);
                store_split2(Ch, Cl, (size_t)(r0 + 8) * N + c, a[2], a[3]);
            } else {
                *(float2*)(Cf + (size_t)r0 * N + c) = make_float2(a[0], a[1]);
                *(float2*)(Cf + (size_t)(r0 + 8) * N + c) = make_float2(a[2], a[3]);
            }
        }
    }
}

// ---------------------------------------------------------------------------
// Register-resident FA2 flash attention (fp16-split QK, single-product PV).
// Grid (S/128, B*H), 256 threads = 8 warps; each warp: 16 q-rows x 64 keys.
// Q/K/V read from fused [8192,3072] arrays (offsets 0/1024/2048).
// V uses only the hi fp16 array; P is one fp16 fragment (no lo).
// ---------------------------------------------------------------------------
#define LKV 72
#define AQH 0
#define AQL 18432
#define AKH 36864
#define AKL 46080
#define AVH 55296
#define ABIAS 64512
#define ATTN_SMEM 65408
#define NKT (SS / 64)

__global__ __launch_bounds__(256, 2)
void attn_fa2(const __half* __restrict__ Xh, const __half* __restrict__ Xl,
              const float* __restrict__ biasTab,
              __half* __restrict__ Ch, __half* __restrict__ Cl) {
    extern __shared__ __align__(128) char sm[];
    const int tid = threadIdx.x, lane = tid & 31, wid = tid >> 5;
    const int qt = blockIdx.x, bhi = blockIdx.y;
    const int b = bhi >> 4, h = bhi & 15;
    const int q0 = qt * 128;
    const size_t ibase = (size_t)b * SS * QSTR + (size_t)h * DKV;
    const size_t obase = (size_t)b * SS * INNER + (size_t)h * DKV;
    const float* bt = biasTab + h * NREL + (SS - 1) - q0 - 127;   // index by k0+i
    const uint32_t sb = smem_u32(sm);
    float* bias_s = (float*)(sm + ABIAS);

    const int rA = lane & 15, cA8 = (lane >> 4) << 3;
    const int er = lane >> 2, qr = (lane & 3) << 1;
    const int r0 = wid * 16 + er, r1 = r0 + 8;

    auto loadK = [&](int kt) {
        const int k0 = kt * 64;
#pragma unroll
        for (int i = 0; i < 4; i++) {
            int id = tid + i * 256;
            int arr = id >> 9, rem = id & 511;
            int row = rem >> 3, ch = (rem & 7) << 4;
            const __half* src = arr ? Xl : Xh;
            cp16(sb + AKH + arr * 9216 + row * 144 + ch,
                 (const char*)src + (ibase + 1024 + (size_t)(k0 + row) * QSTR) * 2 + ch);
        }
    };
    auto loadV = [&](int kt) {   // hi only
        const int k0 = kt * 64;
#pragma unroll
        for (int i = 0; i < 2; i++) {
            int id = tid + i * 256;
            int row = id >> 3, ch = (id & 7) << 4;
            cp16(sb + AVH + row * 144 + ch,
                 (const char*)Xh + (ibase + 2048 + (size_t)(k0 + row) * QSTR) * 2 + ch);
        }
    };

    // Q tile (hi+lo): 128 rows x 64 cols
#pragma unroll
    for (int i = 0; i < 8; i++) {
        int id = tid + i * 256;
        int arr = id >> 10, rem = id & 1023;
        int row = rem >> 3, ch = (rem & 7) << 4;
        const __half* src = arr ? Xl : Xh;
        cp16(sb + (arr ? AQL : AQH) + row * 144 + ch,
             (const char*)src + (ibase + (size_t)(q0 + row) * QSTR) * 2 + ch);
    }
    loadK(0);
    loadV(0);
    if (tid < 191) bias_s[tid] = bt[tid];     // k0 = 0
    cp_commit();

    float m0 = -1e30f, m1 = -1e30f, l0 = 0.0f, l1 = 0.0f;
    float oac[8][4];
#pragma unroll
    for (int i = 0; i < 8; i++)
#pragma unroll
        for (int j = 0; j < 4; j++) oac[i][j] = 0.0f;

    for (int kt = 0; kt < NKT; kt++) {
        cp_wait0();
        __syncthreads();

        // ---- S = Q K^T (m16 x n64 per warp, in registers, 3 products) ----
        float sac[8][4];
#pragma unroll
        for (int i = 0; i < 8; i++)
#pragma unroll
            for (int j = 0; j < 4; j++) sac[i][j] = 0.0f;
#pragma unroll
        for (int ks = 0; ks < 64; ks += 16) {
            uint32_t qfh[4], qfl[4], khf[4][4], klf[4][4];
            uint32_t aoff = ((wid * 16 + rA) * LKV + ks + cA8) * 2;
            ldmx4(qfh, sb + AQH + aoff);
            ldmx4(qfl, sb + AQL + aoff);
#pragma unroll
            for (int kb = 0; kb < 4; kb++) {
                uint32_t boff = ((16 * kb + rA) * LKV + ks + cA8) * 2;
                ldmx4(khf[kb], sb + AKH + boff);
                ldmx4(klf[kb], sb + AKL + boff);
            }
#pragma unroll
            for (int jn = 0; jn < 8; jn++) {
                int kb = jn >> 1, sub = jn & 1;
                mma16816(sac[jn], qfh, khf[kb][sub], khf[kb][sub + 2]);
                mma16816(sac[jn], qfh, klf[kb][sub], klf[kb][sub + 2]);
                mma16816(sac[jn], qfl, khf[kb][sub], khf[kb][sub + 2]);
            }
        }
        __syncthreads();                 // all warps done reading K
        if (kt + 1 < NKT) loadK(kt + 1); // overlap next-K with softmax+PV
        cp_commit();

        // ---- softmax in registers ----
        float vx0 = -1e30f, vx1 = -1e30f;
#pragma unroll
        for (int jn = 0; jn < 8; jn++) {
            int c = jn * 8 + qr;
            sac[jn][0] += bias_s[c - r0 + 127];
            sac[jn][1] += bias_s[c + 1 - r0 + 127];
            sac[jn][2] += bias_s[c - r1 + 127];
            sac[jn][3] += bias_s[c + 1 - r1 + 127];
            vx0 = fmaxf(vx0, fmaxf(sac[jn][0], sac[jn][1]));
            vx1 = fmaxf(vx1, fmaxf(sac[jn][2], sac[jn][3]));
        }
#pragma unroll
        for (int off = 1; off < 4; off <<= 1) {
            vx0 = fmaxf(vx0, __shfl_xor_sync(0xffffffffu, vx0, off));
            vx1 = fmaxf(vx1, __shfl_xor_sync(0xffffffffu, vx1, off));
        }
        float mn0 = fmaxf(m0, vx0), mn1 = fmaxf(m1, vx1);
        float al0 = __expf(m0 - mn0), al1 = __expf(m1 - mn1);
        float sum0 = 0.0f, sum1 = 0.0f;
        uint32_t pfh[4][4];
#pragma unroll
        for (int t = 0; t < 4; t++) {
#pragma unroll
            for (int half = 0; half < 2; half++) {
                int j = 2 * t + half;
                float e0 = __expf(sac[j][0] - mn0);
                float e1 = __expf(sac[j][1] - mn0);
                float e2 = __expf(sac[j][2] - mn1);
                float e3 = __expf(sac[j][3] - mn1);
                sum0 += e0 + e1;
                sum1 += e2 + e3;
                pfh[t][half * 2 + 0] = pack_hf2(e0, e1);  // row er,  k-cols
                pfh[t][half * 2 + 1] = pack_hf2(e2, e3);  // row er+8
            }
        }
#pragma unroll
        for (int off = 1; off < 4; off <<= 1) {
            sum0 += __shfl_xor_sync(0xffffffffu, sum0, off);
            sum1 += __shfl_xor_sync(0xffffffffu, sum1, off);
        }
        l0 = l0 * al0 + sum0; m0 = mn0;
        l1 = l1 * al1 + sum1; m1 = mn1;
#pragma unroll
        for (int jn = 0; jn < 8; jn++) {
            oac[jn][0] *= al0; oac[jn][1] *= al0;
            oac[jn][2] *= al1; oac[jn][3] *= al1;
        }

        // ---- O += P V (single product: P fp16 x V-hi fp16) ----
#pragma unroll
        for (int t = 0; t < 4; t++) {
            uint32_t vhf[4][4];
#pragma unroll
            for (int db = 0; db < 4; db++) {
                uint32_t voff = ((16 * t + rA) * LKV + 16 * db + cA8) * 2;
                ldmx4t(vhf[db], sb + AVH + voff);
            }
#pragma unroll
            for (int db = 0; db < 4; db++) {
                mma16816(oac[2 * db],     pfh[t], vhf[db][0], vhf[db][1]);
                mma16816(oac[2 * db + 1], pfh[t], vhf[db][2], vhf[db][3]);
            }
        }
        __syncthreads();                 // all warps done reading V + bias
        if (kt + 1 < NKT) {
            loadV(kt + 1);
            if (tid < 191) bias_s[tid] = bt[(kt + 1) * 64 + tid];
        }
        cp_commit();
    }

    // ---- epilogue: normalize + split-fp16 store ----
    float inv0 = 1.0f / l0, inv1 = 1.0f / l1;
#pragma unroll
    for (int jn = 0; jn < 8; jn++) {
        int c = jn * 8 + qr;
        store_split2(Ch, Cl, obase + (size_t)(q0 + r0) * INNER + c,
                     oac[jn][0] * inv0, oac[jn][1] * inv0);
        store_split2(Ch, Cl, obase + (size_t)(q0 + r1) * INNER + c,
                     oac[jn][2] * inv1, oac[jn][3] * inv1);
    }
}

// ---------------------------------------------------------------------------
extern "C" void kernel_launch(void* const* d_in, const int* in_sizes, int n_in,
                              void* d_out, int out_size) {
    const float* hidden = (const float*)d_in[0];
    const float* Wq     = (const float*)d_in[1];
    const float* Wk     = (const float*)d_in[2];
    const float* Wv     = (const float*)d_in[3];
    const float* Wo     = (const float*)d_in[4];
    const float* rel    = (const float*)d_in[5];
    float* out = (float*)d_out;

    float* pB;
    __half *pHh, *pHl, *pXh, *pXl, *pCh, *pCl;
    __half *pWTh, *pWTl, *pWoTh, *pWoTl;
    cudaGetSymbolAddress((void**)&pB, g_biasTab);
    cudaGetSymbolAddress((void**)&pHh, g_Hh);
    cudaGetSymbolAddress((void**)&pHl, g_Hl);
    cudaGetSymbolAddress((void**)&pXh, g_QKVh);
    cudaGetSymbolAddress((void**)&pXl, g_QKVl);
    cudaGetSymbolAddress((void**)&pCh, g_Ch);
    cudaGetSymbolAddress((void**)&pCl, g_Cl);
    cudaGetSymbolAddress((void**)&pWTh, g_WTh);
    cudaGetSymbolAddress((void**)&pWTl, g_WTl);
    cudaGetSymbolAddress((void**)&pWoTh, g_WoTh);
    cudaGetSymbolAddress((void**)&pWoTl, g_WoTl);

    cudaFuncSetAttribute(mma_gemm,
                         cudaFuncAttributeMaxDynamicSharedMemorySize, 2 * STG_SZ);
    cudaFuncSetAttribute(attn_fa2,
                         cudaFuncAttributeMaxDynamicSharedMemorySize, ATTN_SMEM);

    bias_table_kernel<<<NH, 256>>>(rel, pB);
    int n4h = BS_TOT * DMODEL / 4;
    split_plain<<<n4h / 256, 256>>>(hidden, pHh, pHl, n4h);
    dim3 tblk(32, 8);
    split_transpose3<<<dim3(32, 32, 3), tblk>>>(Wq, Wk, Wv, pWTh, pWTl);
    split_transpose1<<<dim3(32, 32), tblk>>>(Wo, pWoTh, pWoTl);
    // fused QKV projection -> [8192,3072] split-fp16
    mma_gemm<<<dim3(QSTR / 128, BS_TOT / 128), 256, 2 * STG_SZ>>>(
        pHh, pHl, pWTh, pWTl, nullptr, pXh, pXl, BS_TOT, QSTR, DMODEL, 1);
    // attention
    attn_fa2<<<dim3(SS / 128, BB * NH), 256, ATTN_SMEM>>>(
        pXh, pXl, pB, pCh, pCl);
    // output projection -> f32 out
    mma_gemm<<<dim3(DMODEL / 128, BS_TOT / 128), 256, 2 * STG_SZ>>>(
        pCh, pCl, pWoTh, pWoTl, out, nullptr, nullptr, BS_TOT, DMODEL, INNER, 0);
}

// round 9
// speedup vs baseline: 1.2361x; 1.0318x over previous
#include <cuda_runtime.h>
#include <cuda_fp16.h>
#include <math.h>
#include <stdint.h>

#define BB 4
#define SS 2048
#define DMODEL 1024
#define NH 16
#define DKV 64
#define INNER 1024
#define QSTR 3072              // fused QKV row stride
#define BS_TOT (BB * SS)
#define NREL 4095

// ---------------- scratch (device globals: allocation-free) ----------------
__device__ __align__(256) float g_biasTab[NH * NREL];
__device__ __align__(256) __half g_Hh[BS_TOT * DMODEL];
__device__ __align__(256) __half g_Hl[BS_TOT * DMODEL];
__device__ __align__(256) __half g_QKVh[BS_TOT * QSTR];
__device__ __align__(256) __half g_QKVl[BS_TOT * QSTR];
__device__ __align__(256) __half g_Ch[BS_TOT * INNER];
__device__ __align__(256) __half g_Cl[BS_TOT * INNER];
__device__ __align__(256) __half g_WTh[QSTR * DMODEL];   // [Wq;Wk;Wv]^T
__device__ __align__(256) __half g_WTl[QSTR * DMODEL];
__device__ __align__(256) __half g_WoTh[DMODEL * INNER];
__device__ __align__(256) __half g_WoTl[DMODEL * INNER];

// ---------------------------- PTX helpers ----------------------------------
__device__ __forceinline__ uint32_t smem_u32(const void* p) {
    uint32_t a;
    asm("{ .reg .u64 t; cvta.to.shared.u64 t, %1; cvt.u32.u64 %0, t; }"
        : "=r"(a) : "l"(p));
    return a;
}
__device__ __forceinline__ void cp16(uint32_t dst, const void* src) {
    asm volatile("cp.async.cg.shared.global [%0], [%1], 16;"
                 :: "r"(dst), "l"(src) : "memory");
}
__device__ __forceinline__ void cp_commit() {
    asm volatile("cp.async.commit_group;" ::: "memory");
}
__device__ __forceinline__ void cp_wait0() {
    asm volatile("cp.async.wait_group 0;" ::: "memory");
}
__device__ __forceinline__ void cp_wait1() {
    asm volatile("cp.async.wait_group 1;" ::: "memory");
}
__device__ __forceinline__ void ldmx4(uint32_t* r, uint32_t addr) {
    asm volatile("ldmatrix.sync.aligned.m8n8.x4.shared.b16 {%0,%1,%2,%3}, [%4];"
                 : "=r"(r[0]), "=r"(r[1]), "=r"(r[2]), "=r"(r[3]) : "r"(addr));
}
__device__ __forceinline__ void ldmx4t(uint32_t* r, uint32_t addr) {
    asm volatile("ldmatrix.sync.aligned.m8n8.x4.trans.shared.b16 {%0,%1,%2,%3}, [%4];"
                 : "=r"(r[0]), "=r"(r[1]), "=r"(r[2]), "=r"(r[3]) : "r"(addr));
}
__device__ __forceinline__ void mma16816(float* c, const uint32_t* a,
                                         uint32_t b0, uint32_t b1) {
    asm volatile("mma.sync.aligned.m16n8k16.row.col.f32.f16.f16.f32 "
                 "{%0,%1,%2,%3}, {%4,%5,%6,%7}, {%8,%9}, {%0,%1,%2,%3};"
                 : "+f"(c[0]), "+f"(c[1]), "+f"(c[2]), "+f"(c[3])
                 : "r"(a[0]), "r"(a[1]), "r"(a[2]), "r"(a[3]), "r"(b0), "r"(b1));
}
__device__ __forceinline__ uint32_t pack_hf2(float x, float y) {
    __half2 p = __floats2half2_rn(x, y);
    return *(uint32_t*)&p;
}
__device__ __forceinline__ void store_split2(__half* Ch, __half* Cl,
                                             size_t off, float x, float y) {
    __half hx = __float2half_rn(x), hy = __float2half_rn(y);
    __half lx = __float2half_rn(x - __half2float(hx));
    __half ly = __float2half_rn(y - __half2float(hy));
    *(__half2*)(Ch + off) = __halves2half2(hx, hy);
    *(__half2*)(Cl + off) = __halves2half2(lx, ly);
}

// ---------------------------------------------------------------------------
// fp32 -> fp16 hi/lo split (row-major)
// ---------------------------------------------------------------------------
__global__ __launch_bounds__(256) void split_plain(const float* __restrict__ X,
                                                   __half* __restrict__ Xh,
                                                   __half* __restrict__ Xl,
                                                   int n4) {
    int i = blockIdx.x * 256 + threadIdx.x;
    if (i >= n4) return;
    float4 v = ((const float4*)X)[i];
    __half h0 = __float2half_rn(v.x), h1 = __float2half_rn(v.y);
    __half h2 = __float2half_rn(v.z), h3 = __float2half_rn(v.w);
    __half l0 = __float2half_rn(v.x - __half2float(h0));
    __half l1 = __float2half_rn(v.y - __half2float(h1));
    __half l2 = __float2half_rn(v.z - __half2float(h2));
    __half l3 = __float2half_rn(v.w - __half2float(h3));
    ((__half2*)Xh)[2 * i]     = __halves2half2(h0, h1);
    ((__half2*)Xh)[2 * i + 1] = __halves2half2(h2, h3);
    ((__half2*)Xl)[2 * i]     = __halves2half2(l0, l1);
    ((__half2*)Xl)[2 * i + 1] = __halves2half2(l2, l3);
}

// ---------------------------------------------------------------------------
// Weight transpose + split, with T5 bias table fused in (z==3 blocks).
// ---------------------------------------------------------------------------
__device__ __forceinline__ void transp_tile(const float* __restrict__ W,
                                            __half* __restrict__ Th,
                                            __half* __restrict__ Tl) {
    __shared__ float t[32][33];
    int bx = blockIdx.x * 32, by = blockIdx.y * 32;
    int tx = threadIdx.x, ty = threadIdx.y;
#pragma unroll
    for (int i = 0; i < 32; i += 8)
        t[ty + i][tx] = W[(size_t)(by + ty + i) * DMODEL + bx + tx];
    __syncthreads();
#pragma unroll
    for (int i = 0; i < 32; i += 8) {
        float v = t[tx][ty + i];
        __half h = __float2half_rn(v);
        __half l = __float2half_rn(v - __half2float(h));
        size_t o = (size_t)(bx + ty + i) * DMODEL + by + tx;
        Th[o] = h;
        Tl[o] = l;
    }
}
__global__ __launch_bounds__(256)
void split_transpose3b(const float* __restrict__ Wq, const float* __restrict__ Wk,
                       const float* __restrict__ Wv, const float* __restrict__ rel_emb,
                       __half* __restrict__ Th, __half* __restrict__ Tl,
                       float* __restrict__ biasTab) {
    if (blockIdx.z < 3) {
        const float* W = (blockIdx.z == 0) ? Wq : (blockIdx.z == 1) ? Wk : Wv;
        size_t off = (size_t)blockIdx.z * DMODEL * DMODEL;
        transp_tile(W, Th + off, Tl + off);
        return;
    }
    // z == 3: relative-position bias table, one entry per thread
    int tid = threadIdx.y * 32 + threadIdx.x;
    int idx = (blockIdx.y * 32 + blockIdx.x) * 256 + tid;
    if (idx >= NH * NREL) return;
    int h = idx / NREL;
    int pos = idx - h * NREL;
    int rel = pos - (SS - 1);
    int n = -rel;
    int ret = 0;
    if (n < 0) { ret = 16; n = -n; }
    int bucket;
    if (n < 8) {
        bucket = ret + n;
    } else {
        float v = logf((float)n / 8.0f) / logf(16.0f) * 8.0f;
        int vi = 8 + (int)v;
        if (vi > 15) vi = 15;
        bucket = ret + vi;
    }
    biasTab[h * NREL + pos] = rel_emb[bucket * NH + h];
}
__global__ __launch_bounds__(256)
void split_transpose1(const float* __restrict__ W,
                      __half* __restrict__ Th, __half* __restrict__ Tl) {
    transp_tile(W, Th, Tl);
}

// ---------------------------------------------------------------------------
// Split-fp16 mma.sync GEMM: C[M,N] = A[M,K] @ BT[N,K]^T
// 128x128 tile, BK=32, 256 threads (8 warps, 2x4), 2-stage cp.async pipeline.
// Column-blocks with blockIdx.x >= n2_start use 2 products (A*Bh only):
// skips the Ah*Bl mma AND the Bl smem loads.
// ---------------------------------------------------------------------------
#define LDS 40
#define STG_A_L 10240
#define STG_B_H 20480
#define STG_B_L 30720
#define STG_SZ  40960

__global__ __launch_bounds__(256)
void mma_gemm(const __half* __restrict__ Ah, const __half* __restrict__ Al,
              const __half* __restrict__ Bh, const __half* __restrict__ Bl,
              float* __restrict__ Cf,
              __half* __restrict__ Ch, __half* __restrict__ Cl,
              int M, int N, int K, int split_out, int n2_start) {
    extern __shared__ __align__(128) char smem[];
    const int tid = threadIdx.x, lane = tid & 31, wid = tid >> 5;
    const int wm = wid >> 2, wn = wid & 3;
    const int rowA0 = blockIdx.y * 128, rowB0 = blockIdx.x * 128;
    const uint32_t sb = smem_u32(smem);
    const int nk = K >> 5;
    const bool np3 = ((int)blockIdx.x < n2_start);

    float acc[16][4];
#pragma unroll
    for (int i = 0; i < 16; i++)
#pragma unroll
        for (int j = 0; j < 4; j++) acc[i][j] = 0.0f;

    auto load_stage = [&](int stage, int kc) {
        const uint32_t d0 = sb + (uint32_t)stage * STG_SZ;
        const int k0 = kc * 32;
#pragma unroll
        for (int i = 0; i < 8; i++) {
            int id = tid + i * 256;
            int arr = id >> 9;
            int rem = id & 511;
            int row = rem >> 2;
            int ch  = (rem & 3) << 4;
            if (arr == 3 && !np3) continue;   // Bl not needed in 2-product mode
            uint32_t dst = d0 + arr * 10240 + row * 80 + ch;
            const __half* src = (arr == 0) ? Ah : (arr == 1) ? Al
                             : (arr == 2) ? Bh : Bl;
            int grow = ((arr < 2) ? rowA0 : rowB0) + row;
            cp16(dst, (const char*)src + ((size_t)grow * K + k0) * 2 + ch);
        }
        cp_commit();
    };

    load_stage(0, 0);

    const int rA = lane & 15;
    const int cA8 = (lane >> 4) << 3;

    for (int kc = 0; kc < nk; kc++) {
        const int s = kc & 1;
        if (kc + 1 < nk) { load_stage(s ^ 1, kc + 1); cp_wait1(); }
        else             { cp_wait0(); }
        __syncthreads();

        const uint32_t base = sb + (uint32_t)s * STG_SZ;
#pragma unroll
        for (int ks = 0; ks < 32; ks += 16) {
            uint32_t a_h[4][4], b_h[2][4], b_l[2][4];
#pragma unroll
            for (int im = 0; im < 4; im++)
                ldmx4(a_h[im], base + ((64 * wm + im * 16 + rA) * LDS + ks + cA8) * 2);
#pragma unroll
            for (int jb = 0; jb < 2; jb++) {
                uint32_t boff = ((32 * wn + jb * 16 + rA) * LDS + ks + cA8) * 2;
                ldmx4(b_h[jb], base + STG_B_H + boff);
                if (np3) ldmx4(b_l[jb], base + STG_B_L + boff);
            }
#pragma unroll
            for (int im = 0; im < 4; im++)
#pragma unroll
                for (int jn = 0; jn < 4; jn++) {
                    int jb = jn >> 1, sub = jn & 1;
                    mma16816(acc[im * 4 + jn], a_h[im], b_h[jb][sub], b_h[jb][sub + 2]);
                    if (np3)
                        mma16816(acc[im * 4 + jn], a_h[im], b_l[jb][sub], b_l[jb][sub + 2]);
                }
#pragma unroll
            for (int im = 0; im < 4; im++) {
                uint32_t a_l[4];
                ldmx4(a_l, base + STG_A_L + ((64 * wm + im * 16 + rA) * LDS + ks + cA8) * 2);
#pragma unroll
                for (int jn = 0; jn < 4; jn++) {
                    int jb = jn >> 1, sub = jn & 1;
                    mma16816(acc[im * 4 + jn], a_l, b_h[jb][sub], b_h[jb][sub + 2]);
                }
            }
        }
        __syncthreads();
    }

    const int er = lane >> 2, ec = (lane & 3) << 1;
#pragma unroll
    for (int im = 0; im < 4; im++) {
        int r0 = rowA0 + 64 * wm + im * 16 + er;
#pragma unroll
        for (int jn = 0; jn < 4; jn++) {
            int c = rowB0 + 32 * wn + jn * 8 + ec;
            float* a = acc[im * 4 + jn];
            if (split_out) {
                store_split2(Ch, Cl, (size_t)r0 * N + c, a[0], a[1]);
                store_split2(Ch, Cl, (size_t)(r0 + 8) * N + c, a[2], a[3]);
            } else {
                *(float2*)(Cf + (size_t)r0 * N + c) = make_float2(a[0], a[1]);
                *(float2*)(Cf + (size_t)(r0 + 8) * N + c) = make_float2(a[2], a[3]);
            }
        }
    }
}

// ---------------------------------------------------------------------------
// Register-resident FA2 flash attention (fp16-split QK, single-product PV).
// Grid (S/128, B*H), 256 threads = 8 warps; each warp: 16 q-rows x 64 keys.
// ---------------------------------------------------------------------------
#define LKV 72
#define AQH 0
#define AQL 18432
#define AKH 36864
#define AKL 46080
#define AVH 55296
#define ABIAS 64512
#define ATTN_SMEM 65408
#define NKT (SS / 64)

__global__ __launch_bounds__(256, 2)
void attn_fa2(const __half* __restrict__ Xh, const __half* __restrict__ Xl,
              const float* __restrict__ biasTab,
              __half* __restrict__ Ch, __half* __restrict__ Cl) {
    extern __shared__ __align__(128) char sm[];
    const int tid = threadIdx.x, lane = tid & 31, wid = tid >> 5;
    const int qt = blockIdx.x, bhi = blockIdx.y;
    const int b = bhi >> 4, h = bhi & 15;
    const int q0 = qt * 128;
    const size_t ibase = (size_t)b * SS * QSTR + (size_t)h * DKV;
    const size_t obase = (size_t)b * SS * INNER + (size_t)h * DKV;
    const float* bt = biasTab + h * NREL + (SS - 1) - q0 - 127;   // index by k0+i
    const uint32_t sb = smem_u32(sm);
    float* bias_s = (float*)(sm + ABIAS);

    const int rA = lane & 15, cA8 = (lane >> 4) << 3;
    const int er = lane >> 2, qr = (lane & 3) << 1;
    const int r0 = wid * 16 + er, r1 = r0 + 8;

    auto loadK = [&](int kt) {
        const int k0 = kt * 64;
#pragma unroll
        for (int i = 0; i < 4; i++) {
            int id = tid + i * 256;
            int arr = id >> 9, rem = id & 511;
            int row = rem >> 3, ch = (rem & 7) << 4;
            const __half* src = arr ? Xl : Xh;
            cp16(sb + AKH + arr * 9216 + row * 144 + ch,
                 (const char*)src + (ibase + 1024 + (size_t)(k0 + row) * QSTR) * 2 + ch);
        }
    };
    auto loadV = [&](int kt) {   // hi only
        const int k0 = kt * 64;
#pragma unroll
        for (int i = 0; i < 2; i++) {
            int id = tid + i * 256;
            int row = id >> 3, ch = (id & 7) << 4;
            cp16(sb + AVH + row * 144 + ch,
                 (const char*)Xh + (ibase + 2048 + (size_t)(k0 + row) * QSTR) * 2 + ch);
        }
    };

    // Q tile (hi+lo): 128 rows x 64 cols
#pragma unroll
    for (int i = 0; i < 8; i++) {
        int id = tid + i * 256;
        int arr = id >> 10, rem = id & 1023;
        int row = rem >> 3, ch = (rem & 7) << 4;
        const __half* src = arr ? Xl : Xh;
        cp16(sb + (arr ? AQL : AQH) + row * 144 + ch,
             (const char*)src + (ibase + (size_t)(q0 + row) * QSTR) * 2 + ch);
    }
    loadK(0);
    loadV(0);
    if (tid < 191) bias_s[tid] = bt[tid];     // k0 = 0
    cp_commit();

    float m0 = -1e30f, m1 = -1e30f, l0 = 0.0f, l1 = 0.0f;
    float oac[8][4];
#pragma unroll
    for (int i = 0; i < 8; i++)
#pragma unroll
        for (int j = 0; j < 4; j++) oac[i][j] = 0.0f;

    for (int kt = 0; kt < NKT; kt++) {
        cp_wait0();
        __syncthreads();

        // ---- S = Q K^T (m16 x n64 per warp, in registers, 3 products) ----
        float sac[8][4];
#pragma unroll
        for (int i = 0; i < 8; i++)
#pragma unroll
            for (int j = 0; j < 4; j++) sac[i][j] = 0.0f;
#pragma unroll
        for (int ks = 0; ks < 64; ks += 16) {
            uint32_t qfh[4], qfl[4], khf[4][4], klf[4][4];
            uint32_t aoff = ((wid * 16 + rA) * LKV + ks + cA8) * 2;
            ldmx4(qfh, sb + AQH + aoff);
            ldmx4(qfl, sb + AQL + aoff);
#pragma unroll
            for (int kb = 0; kb < 4; kb++) {
                uint32_t boff = ((16 * kb + rA) * LKV + ks + cA8) * 2;
                ldmx4(khf[kb], sb + AKH + boff);
                ldmx4(klf[kb], sb + AKL + boff);
            }
#pragma unroll
            for (int jn = 0; jn < 8; jn++) {
                int kb = jn >> 1, sub = jn & 1;
                mma16816(sac[jn], qfh, khf[kb][sub], khf[kb][sub + 2]);
                mma16816(sac[jn], qfh, klf[kb][sub], klf[kb][sub + 2]);
                mma16816(sac[jn], qfl, khf[kb][sub], khf[kb][sub + 2]);
            }
        }
        __syncthreads();                 // all warps done reading K
        if (kt + 1 < NKT) loadK(kt + 1); // overlap next-K with softmax+PV
        cp_commit();

        // ---- softmax in registers ----
        float vx0 = -1e30f, vx1 = -1e30f;
#pragma unroll
        for (int jn = 0; jn < 8; jn++) {
            int c = jn * 8 + qr;
            sac[jn][0] += bias_s[c - r0 + 127];
            sac[jn][1] += bias_s[c + 1 - r0 + 127];
            sac[jn][2] += bias_s[c - r1 + 127];
            sac[jn][3] += bias_s[c + 1 - r1 + 127];
            vx0 = fmaxf(vx0, fmaxf(sac[jn][0], sac[jn][1]));
            vx1 = fmaxf(vx1, fmaxf(sac[jn][2], sac[jn][3]));
        }
#pragma unroll
        for (int off = 1; off < 4; off <<= 1) {
            vx0 = fmaxf(vx0, __shfl_xor_sync(0xffffffffu, vx0, off));
            vx1 = fmaxf(vx1, __shfl_xor_sync(0xffffffffu, vx1, off));
        }
        float mn0 = fmaxf(m0, vx0), mn1 = fmaxf(m1, vx1);
        float al0 = __expf(m0 - mn0), al1 = __expf(m1 - mn1);
        float sum0 = 0.0f, sum1 = 0.0f;
        uint32_t pfh[4][4];
#pragma unroll
        for (int t = 0; t < 4; t++) {
#pragma unroll
            for (int half = 0; half < 2; half++) {
                int j = 2 * t + half;
                float e0 = __expf(sac[j][0] - mn0);
                float e1 = __expf(sac[j][1] - mn0);
                float e2 = __expf(sac[j][2] - mn1);
                float e3 = __expf(sac[j][3] - mn1);
                sum0 += e0 + e1;
                sum1 += e2 + e3;
                pfh[t][half * 2 + 0] = pack_hf2(e0, e1);  // row er,  k-cols
                pfh[t][half * 2 + 1] = pack_hf2(e2, e3);  // row er+8
            }
        }
#pragma unroll
        for (int off = 1; off < 4; off <<= 1) {
            sum0 += __shfl_xor_sync(0xffffffffu, sum0, off);
            sum1 += __shfl_xor_sync(0xffffffffu, sum1, off);
        }
        l0 = l0 * al0 + sum0; m0 = mn0;
        l1 = l1 * al1 + sum1; m1 = mn1;
#pragma unroll
        for (int jn = 0; jn < 8; jn++) {
            oac[jn][0] *= al0; oac[jn][1] *= al0;
            oac[jn][2] *= al1; oac[jn][3] *= al1;
        }

        // ---- O += P V (single product: P fp16 x V-hi fp16) ----
#pragma unroll
        for (int t = 0; t < 4; t++) {
            uint32_t vhf[4][4];
#pragma unroll
            for (int db = 0; db < 4; db++) {
                uint32_t voff = ((16 * t + rA) * LKV + 16 * db + cA8) * 2;
                ldmx4t(vhf[db], sb + AVH + voff);
            }
#pragma unroll
            for (int db = 0; db < 4; db++) {
                mma16816(oac[2 * db],     pfh[t], vhf[db][0], vhf[db][1]);
                mma16816(oac[2 * db + 1], pfh[t], vhf[db][2], vhf[db][3]);
            }
        }
        __syncthreads();                 // all warps done reading V + bias
        if (kt + 1 < NKT) {
            loadV(kt + 1);
            if (tid < 191) bias_s[tid] = bt[(kt + 1) * 64 + tid];
        }
        cp_commit();
    }

    // ---- epilogue: normalize + split-fp16 store ----
    float inv0 = 1.0f / l0, inv1 = 1.0f / l1;
#pragma unroll
    for (int jn = 0; jn < 8; jn++) {
        int c = jn * 8 + qr;
        store_split2(Ch, Cl, obase + (size_t)(q0 + r0) * INNER + c,
                     oac[jn][0] * inv0, oac[jn][1] * inv0);
        store_split2(Ch, Cl, obase + (size_t)(q0 + r1) * INNER + c,
                     oac[jn][2] * inv1, oac[jn][3] * inv1);
    }
}

// ---------------------------------------------------------------------------
extern "C" void kernel_launch(void* const* d_in, const int* in_sizes, int n_in,
                              void* d_out, int out_size) {
    const float* hidden = (const float*)d_in[0];
    const float* Wq     = (const float*)d_in[1];
    const float* Wk     = (const float*)d_in[2];
    const float* Wv     = (const float*)d_in[3];
    const float* Wo     = (const float*)d_in[4];
    const float* rel    = (const float*)d_in[5];
    float* out = (float*)d_out;

    float* pB;
    __half *pHh, *pHl, *pXh, *pXl, *pCh, *pCl;
    __half *pWTh, *pWTl, *pWoTh, *pWoTl;
    cudaGetSymbolAddress((void**)&pB, g_biasTab);
    cudaGetSymbolAddress((void**)&pHh, g_Hh);
    cudaGetSymbolAddress((void**)&pHl, g_Hl);
    cudaGetSymbolAddress((void**)&pXh, g_QKVh);
    cudaGetSymbolAddress((void**)&pXl, g_QKVl);
    cudaGetSymbolAddress((void**)&pCh, g_Ch);
    cudaGetSymbolAddress((void**)&pCl, g_Cl);
    cudaGetSymbolAddress((void**)&pWTh, g_WTh);
    cudaGetSymbolAddress((void**)&pWTl, g_WTl);
    cudaGetSymbolAddress((void**)&pWoTh, g_WoTh);
    cudaGetSymbolAddress((void**)&pWoTl, g_WoTl);

    cudaFuncSetAttribute(mma_gemm,
                         cudaFuncAttributeMaxDynamicSharedMemorySize, 2 * STG_SZ);
    cudaFuncSetAttribute(attn_fa2,
                         cudaFuncAttributeMaxDynamicSharedMemorySize, ATTN_SMEM);

    // launch 1: split hidden to fp16 hi/lo
    int n4h = BS_TOT * DMODEL / 4;
    split_plain<<<n4h / 256, 256>>>(hidden, pHh, pHl, n4h);
    // launch 2: transpose+split Wq/Wk/Wv + fused bias table (z==3)
    dim3 tblk(32, 8);
    split_transpose3b<<<dim3(32, 32, 4), tblk>>>(Wq, Wk, Wv, rel, pWTh, pWTl, pB);
    // launch 3: fused QKV projection (V columns >= blk 16 use 2 products)
    mma_gemm<<<dim3(QSTR / 128, BS_TOT / 128), 256, 2 * STG_SZ>>>(
        pHh, pHl, pWTh, pWTl, nullptr, pXh, pXl, BS_TOT, QSTR, DMODEL, 1, 16);
    // launch 4 (ncu capture slot): attention
    attn_fa2<<<dim3(SS / 128, BB * NH), 256, ATTN_SMEM>>>(
        pXh, pXl, pB, pCh, pCl);
    // launch 5: transpose+split Wo
    split_transpose1<<<dim3(32, 32), tblk>>>(Wo, pWoTh, pWoTl);
    // launch 6: output projection, 2 products everywhere -> f32 out
    mma_gemm<<<dim3(DMODEL / 128, BS_TOT / 128), 256, 2 * STG_SZ>>>(
        pCh, pCl, pWoTh, pWoTl, out, nullptr, nullptr, BS_TOT, DMODEL, INNER, 0, 0);
}

// round 10
// speedup vs baseline: 1.2660x; 1.0242x over previous
#include <cuda_runtime.h>
#include <cuda_fp16.h>
#include <math.h>
#include <stdint.h>

#define BB 4
#define SS 2048
#define DMODEL 1024
#define NH 16
#define DKV 64
#define INNER 1024
#define QSTR 3072              // fused QKV row stride
#define BS_TOT (BB * SS)
#define NREL 4095

// ---------------- scratch (device globals: allocation-free) ----------------
__device__ __align__(256) float g_biasTab[NH * NREL];
__device__ __align__(256) __half g_Hh[BS_TOT * DMODEL];
__device__ __align__(256) __half g_Hl[BS_TOT * DMODEL];
__device__ __align__(256) __half g_QKVh[BS_TOT * QSTR];
__device__ __align__(256) __half g_QKVl[BS_TOT * QSTR];
__device__ __align__(256) __half g_Ch[BS_TOT * INNER];
__device__ __align__(256) __half g_Cl[BS_TOT * INNER];
__device__ __align__(256) __half g_WTh[QSTR * DMODEL];   // [Wq;Wk;Wv]^T
__device__ __align__(256) __half g_WTl[QSTR * DMODEL];
__device__ __align__(256) __half g_WoTh[DMODEL * INNER];
__device__ __align__(256) __half g_WoTl[DMODEL * INNER];

// ---------------------------- PTX helpers ----------------------------------
__device__ __forceinline__ uint32_t smem_u32(const void* p) {
    uint32_t a;
    asm("{ .reg .u64 t; cvta.to.shared.u64 t, %1; cvt.u32.u64 %0, t; }"
        : "=r"(a) : "l"(p));
    return a;
}
__device__ __forceinline__ void cp16(uint32_t dst, const void* src) {
    asm volatile("cp.async.cg.shared.global [%0], [%1], 16;"
                 :: "r"(dst), "l"(src) : "memory");
}
__device__ __forceinline__ void cp4(uint32_t dst, const void* src) {
    asm volatile("cp.async.ca.shared.global [%0], [%1], 4;"
                 :: "r"(dst), "l"(src) : "memory");
}
__device__ __forceinline__ void cp_commit() {
    asm volatile("cp.async.commit_group;" ::: "memory");
}
__device__ __forceinline__ void cp_wait0() {
    asm volatile("cp.async.wait_group 0;" ::: "memory");
}
__device__ __forceinline__ void ldmx4(uint32_t* r, uint32_t addr) {
    asm volatile("ldmatrix.sync.aligned.m8n8.x4.shared.b16 {%0,%1,%2,%3}, [%4];"
                 : "=r"(r[0]), "=r"(r[1]), "=r"(r[2]), "=r"(r[3]) : "r"(addr));
}
__device__ __forceinline__ void ldmx4t(uint32_t* r, uint32_t addr) {
    asm volatile("ldmatrix.sync.aligned.m8n8.x4.trans.shared.b16 {%0,%1,%2,%3}, [%4];"
                 : "=r"(r[0]), "=r"(r[1]), "=r"(r[2]), "=r"(r[3]) : "r"(addr));
}
__device__ __forceinline__ void mma16816(float* c, const uint32_t* a,
                                         uint32_t b0, uint32_t b1) {
    asm volatile("mma.sync.aligned.m16n8k16.row.col.f32.f16.f16.f32 "
                 "{%0,%1,%2,%3}, {%4,%5,%6,%7}, {%8,%9}, {%0,%1,%2,%3};"
                 : "+f"(c[0]), "+f"(c[1]), "+f"(c[2]), "+f"(c[3])
                 : "r"(a[0]), "r"(a[1]), "r"(a[2]), "r"(a[3]), "r"(b0), "r"(b1));
}
__device__ __forceinline__ uint32_t pack_hf2(float x, float y) {
    __half2 p = __floats2half2_rn(x, y);
    return *(uint32_t*)&p;
}
__device__ __forceinline__ void store_split2(__half* Ch, __half* Cl,
                                             size_t off, float x, float y) {
    __half hx = __float2half_rn(x), hy = __float2half_rn(y);
    __half lx = __float2half_rn(x - __half2float(hx));
    __half ly = __float2half_rn(y - __half2float(hy));
    *(__half2*)(Ch + off) = __halves2half2(hx, hy);
    *(__half2*)(Cl + off) = __halves2half2(lx, ly);
}

// ---------------------------------------------------------------------------
// fp32 -> fp16 hi/lo split (row-major)
// ---------------------------------------------------------------------------
__global__ __launch_bounds__(256) void split_plain(const float* __restrict__ X,
                                                   __half* __restrict__ Xh,
                                                   __half* __restrict__ Xl,
                                                   int n4) {
    int i = blockIdx.x * 256 + threadIdx.x;
    if (i >= n4) return;
    float4 v = ((const float4*)X)[i];
    __half h0 = __float2half_rn(v.x), h1 = __float2half_rn(v.y);
    __half h2 = __float2half_rn(v.z), h3 = __float2half_rn(v.w);
    __half l0 = __float2half_rn(v.x - __half2float(h0));
    __half l1 = __float2half_rn(v.y - __half2float(h1));
    __half l2 = __float2half_rn(v.z - __half2float(h2));
    __half l3 = __float2half_rn(v.w - __half2float(h3));
    ((__half2*)Xh)[2 * i]     = __halves2half2(h0, h1);
    ((__half2*)Xh)[2 * i + 1] = __halves2half2(h2, h3);
    ((__half2*)Xl)[2 * i]     = __halves2half2(l0, l1);
    ((__half2*)Xl)[2 * i + 1] = __halves2half2(l2, l3);
}

// ---------------------------------------------------------------------------
// Weight transpose + split, with T5 bias table fused in (z==3 blocks).
// ---------------------------------------------------------------------------
__device__ __forceinline__ void transp_tile(const float* __restrict__ W,
                                            __half* __restrict__ Th,
                                            __half* __restrict__ Tl) {
    __shared__ float t[32][33];
    int bx = blockIdx.x * 32, by = blockIdx.y * 32;
    int tx = threadIdx.x, ty = threadIdx.y;
#pragma unroll
    for (int i = 0; i < 32; i += 8)
        t[ty + i][tx] = W[(size_t)(by + ty + i) * DMODEL + bx + tx];
    __syncthreads();
#pragma unroll
    for (int i = 0; i < 32; i += 8) {
        float v = t[tx][ty + i];
        __half h = __float2half_rn(v);
        __half l = __float2half_rn(v - __half2float(h));
        size_t o = (size_t)(bx + ty + i) * DMODEL + by + tx;
        Th[o] = h;
        Tl[o] = l;
    }
}
__global__ __launch_bounds__(256)
void split_transpose3b(const float* __restrict__ Wq, const float* __restrict__ Wk,
                       const float* __restrict__ Wv, const float* __restrict__ rel_emb,
                       __half* __restrict__ Th, __half* __restrict__ Tl,
                       float* __restrict__ biasTab) {
    if (blockIdx.z < 3) {
        const float* W = (blockIdx.z == 0) ? Wq : (blockIdx.z == 1) ? Wk : Wv;
        size_t off = (size_t)blockIdx.z * DMODEL * DMODEL;
        transp_tile(W, Th + off, Tl + off);
        return;
    }
    int tid = threadIdx.y * 32 + threadIdx.x;
    int idx = (blockIdx.y * 32 + blockIdx.x) * 256 + tid;
    if (idx >= NH * NREL) return;
    int h = idx / NREL;
    int pos = idx - h * NREL;
    int rel = pos - (SS - 1);
    int n = -rel;
    int ret = 0;
    if (n < 0) { ret = 16; n = -n; }
    int bucket;
    if (n < 8) {
        bucket = ret + n;
    } else {
        float v = logf((float)n / 8.0f) / logf(16.0f) * 8.0f;
        int vi = 8 + (int)v;
        if (vi > 15) vi = 15;
        bucket = ret + vi;
    }
    biasTab[h * NREL + pos] = rel_emb[bucket * NH + h];
}
__global__ __launch_bounds__(256)
void split_transpose1(const float* __restrict__ W,
                      __half* __restrict__ Th, __half* __restrict__ Tl) {
    transp_tile(W, Th, Tl);
}

// ---------------------------------------------------------------------------
// Split-fp16 mma.sync GEMM: C[M,N] = A[M,K] @ BT[N,K]^T
// 128x128 tile, BK=32, 256 threads (8 warps, 2x4).
// Single-barrier double-buffered cp.async pipeline (1 sync per chunk).
// Column-blocks with blockIdx.x >= n2_start use 2 products (A*Bh only).
// ---------------------------------------------------------------------------
#define LDS 40
#define STG_A_L 10240
#define STG_B_H 20480
#define STG_B_L 30720
#define STG_SZ  40960

__global__ __launch_bounds__(256)
void mma_gemm(const __half* __restrict__ Ah, const __half* __restrict__ Al,
              const __half* __restrict__ Bh, const __half* __restrict__ Bl,
              float* __restrict__ Cf,
              __half* __restrict__ Ch, __half* __restrict__ Cl,
              int M, int N, int K, int split_out, int n2_start) {
    extern __shared__ __align__(128) char smem[];
    const int tid = threadIdx.x, lane = tid & 31, wid = tid >> 5;
    const int wm = wid >> 2, wn = wid & 3;
    const int rowA0 = blockIdx.y * 128, rowB0 = blockIdx.x * 128;
    const uint32_t sb = smem_u32(smem);
    const int nk = K >> 5;
    const bool np3 = ((int)blockIdx.x < n2_start);

    float acc[16][4];
#pragma unroll
    for (int i = 0; i < 16; i++)
#pragma unroll
        for (int j = 0; j < 4; j++) acc[i][j] = 0.0f;

    auto load_stage = [&](int stage, int kc) {
        const uint32_t d0 = sb + (uint32_t)stage * STG_SZ;
        const int k0 = kc * 32;
#pragma unroll
        for (int i = 0; i < 8; i++) {
            int id = tid + i * 256;
            int arr = id >> 9;
            int rem = id & 511;
            int row = rem >> 2;
            int ch  = (rem & 3) << 4;
            if (arr == 3 && !np3) continue;   // Bl not needed in 2-product mode
            uint32_t dst = d0 + arr * 10240 + row * 80 + ch;
            const __half* src = (arr == 0) ? Ah : (arr == 1) ? Al
                             : (arr == 2) ? Bh : Bl;
            int grow = ((arr < 2) ? rowA0 : rowB0) + row;
            cp16(dst, (const char*)src + ((size_t)grow * K + k0) * 2 + ch);
        }
        cp_commit();
    };

    load_stage(0, 0);

    const int rA = lane & 15;
    const int cA8 = (lane >> 4) << 3;

    for (int kc = 0; kc < nk; kc++) {
        const int s = kc & 1;
        cp_wait0();
        __syncthreads();
        if (kc + 1 < nk) load_stage(s ^ 1, kc + 1);

        const uint32_t base = sb + (uint32_t)s * STG_SZ;
#pragma unroll
        for (int ks = 0; ks < 32; ks += 16) {
            uint32_t a_h[4][4], b_h[2][4], b_l[2][4];
#pragma unroll
            for (int im = 0; im < 4; im++)
                ldmx4(a_h[im], base + ((64 * wm + im * 16 + rA) * LDS + ks + cA8) * 2);
#pragma unroll
            for (int jb = 0; jb < 2; jb++) {
                uint32_t boff = ((32 * wn + jb * 16 + rA) * LDS + ks + cA8) * 2;
                ldmx4(b_h[jb], base + STG_B_H + boff);
                if (np3) ldmx4(b_l[jb], base + STG_B_L + boff);
            }
#pragma unroll
            for (int im = 0; im < 4; im++)
#pragma unroll
                for (int jn = 0; jn < 4; jn++) {
                    int jb = jn >> 1, sub = jn & 1;
                    mma16816(acc[im * 4 + jn], a_h[im], b_h[jb][sub], b_h[jb][sub + 2]);
                    if (np3)
                        mma16816(acc[im * 4 + jn], a_h[im], b_l[jb][sub], b_l[jb][sub + 2]);
                }
#pragma unroll
            for (int im = 0; im < 4; im++) {
                uint32_t a_l[4];
                ldmx4(a_l, base + STG_A_L + ((64 * wm + im * 16 + rA) * LDS + ks + cA8) * 2);
#pragma unroll
                for (int jn = 0; jn < 4; jn++) {
                    int jb = jn >> 1, sub = jn & 1;
                    mma16816(acc[im * 4 + jn], a_l, b_h[jb][sub], b_h[jb][sub + 2]);
                }
            }
        }
    }

    const int er = lane >> 2, ec = (lane & 3) << 1;
#pragma unroll
    for (int im = 0; im < 4; im++) {
        int r0 = rowA0 + 64 * wm + im * 16 + er;
#pragma unroll
        for (int jn = 0; jn < 4; jn++) {
            int c = rowB0 + 32 * wn + jn * 8 + ec;
            float* a = acc[im * 4 + jn];
            if (split_out) {
                store_split2(Ch, Cl, (size_t)r0 * N + c, a[0], a[1]);
                store_split2(Ch, Cl, (size_t)(r0 + 8) * N + c, a[2], a[3]);
            } else {
                *(float2*)(Cf + (size_t)r0 * N + c) = make_float2(a[0], a[1]);
                *(float2*)(Cf + (size_t)(r0 + 8) * N + c) = make_float2(a[2], a[3]);
            }
        }
    }
}

// ---------------------------------------------------------------------------
// Register-resident FA2 flash attention (fp16-split QK, single-product PV).
// Double-buffered K/V/bias, ONE __syncthreads per 64-key tile.
// Grid (S/128, B*H), 256 threads = 8 warps; each warp: 16 q-rows x 64 keys.
// ---------------------------------------------------------------------------
#define LKV 72
#define KBUF 18432
#define VBUF 9216
#define AQH 0
#define AQL 18432
#define AKB 36864          // K buffers: buf*KBUF (hi +0, lo +9216)
#define AVB 73728          // V buffers: buf*VBUF (hi only)
#define ABI 92160          // bias buffers: buf*768
#define ATTN_SMEM 93696
#define NKT (SS / 64)

__global__ __launch_bounds__(256, 2)
void attn_fa2(const __half* __restrict__ Xh, const __half* __restrict__ Xl,
              const float* __restrict__ biasTab,
              __half* __restrict__ Ch, __half* __restrict__ Cl) {
    extern __shared__ __align__(128) char sm[];
    const int tid = threadIdx.x, lane = tid & 31, wid = tid >> 5;
    const int qt = blockIdx.x, bhi = blockIdx.y;
    const int b = bhi >> 4, h = bhi & 15;
    const int q0 = qt * 128;
    const size_t ibase = (size_t)b * SS * QSTR + (size_t)h * DKV;
    const size_t obase = (size_t)b * SS * INNER + (size_t)h * DKV;
    const uint32_t sb = smem_u32(sm);

    const int rA = lane & 15, cA8 = (lane >> 4) << 3;
    const int er = lane >> 2, qr = (lane & 3) << 1;
    const int r0 = wid * 16 + er, r1 = r0 + 8;

    // ---- per-thread load geometry (constants for the whole kernel) ----
    const int lrow = tid >> 3;
    const int lch  = (tid & 7) << 4;
    const uint32_t goffA = (uint32_t)lrow * (QSTR * 2) + lch;
    const uint32_t goffB = goffA + 32 * QSTR * 2;
    const uint32_t sA = (uint32_t)lrow * 144 + lch;
    const uint32_t sB = sA + 32 * 144;
    const char* srcKh = (const char*)Xh + (ibase + 1024) * 2;
    const char* srcKl = (const char*)Xl + (ibase + 1024) * 2;
    const char* srcV  = (const char*)Xh + (ibase + 2048) * 2;
    const float* srcB = biasTab + h * NREL + (SS - 1) - q0 - 127;

    auto loadKV = [&](int buf) {
        uint32_t kd = sb + AKB + (uint32_t)buf * KBUF;
        uint32_t vd = sb + AVB + (uint32_t)buf * VBUF;
        cp16(kd + sA, srcKh + goffA);
        cp16(kd + sB, srcKh + goffB);
        cp16(kd + 9216 + sA, srcKl + goffA);
        cp16(kd + 9216 + sB, srcKl + goffB);
        cp16(vd + sA, srcV + goffA);
        cp16(vd + sB, srcV + goffB);
        if (tid < 191)
            cp4(sb + ABI + (uint32_t)buf * 768 + tid * 4, srcB + tid);
        srcKh += (size_t)64 * QSTR * 2;
        srcKl += (size_t)64 * QSTR * 2;
        srcV  += (size_t)64 * QSTR * 2;
        srcB  += 64;
        cp_commit();
    };

    // ---- prologue: Q tile (hi+lo, 128x64) + tile 0 K/V/bias, one group ----
#pragma unroll
    for (int i = 0; i < 8; i++) {
        int id = tid + i * 256;
        int arr = id >> 10, rem = id & 1023;
        int row = rem >> 3, ch = (rem & 7) << 4;
        const __half* src = arr ? Xl : Xh;
        cp16(sb + (arr ? AQL : AQH) + row * 144 + ch,
             (const char*)src + (ibase + (size_t)(q0 + row) * QSTR) * 2 + ch);
    }
    loadKV(0);

    float m0 = -1e30f, m1 = -1e30f, l0 = 0.0f, l1 = 0.0f;
    float oac[8][4];
#pragma unroll
    for (int i = 0; i < 8; i++)
#pragma unroll
        for (int j = 0; j < 4; j++) oac[i][j] = 0.0f;

    for (int kt = 0; kt < NKT; kt++) {
        const int buf = kt & 1;
        cp_wait0();
        __syncthreads();                       // ONE barrier per tile
        if (kt + 1 < NKT) loadKV(buf ^ 1);     // overlap loads with ALL compute

        const uint32_t kb0 = sb + AKB + (uint32_t)buf * KBUF;   // K hi
        const uint32_t kb1 = kb0 + 9216;                        // K lo
        const uint32_t vb  = sb + AVB + (uint32_t)buf * VBUF;
        const float* bias_s = (const float*)(sm + ABI + buf * 768);

        // ---- S = Q K^T (m16 x n64 per warp, in registers, 3 products) ----
        float sac[8][4];
#pragma unroll
        for (int i = 0; i < 8; i++)
#pragma unroll
            for (int j = 0; j < 4; j++) sac[i][j] = 0.0f;
#pragma unroll
        for (int ks = 0; ks < 64; ks += 16) {
            uint32_t qfh[4], qfl[4], khf[4][4], klf[4][4];
            uint32_t aoff = ((wid * 16 + rA) * LKV + ks + cA8) * 2;
            ldmx4(qfh, sb + AQH + aoff);
            ldmx4(qfl, sb + AQL + aoff);
#pragma unroll
            for (int kb = 0; kb < 4; kb++) {
                uint32_t boff = ((16 * kb + rA) * LKV + ks + cA8) * 2;
                ldmx4(khf[kb], kb0 + boff);
                ldmx4(klf[kb], kb1 + boff);
            }
#pragma unroll
            for (int jn = 0; jn < 8; jn++) {
                int kb = jn >> 1, sub = jn & 1;
                mma16816(sac[jn], qfh, khf[kb][sub], khf[kb][sub + 2]);
                mma16816(sac[jn], qfh, klf[kb][sub], klf[kb][sub + 2]);
                mma16816(sac[jn], qfl, khf[kb][sub], khf[kb][sub + 2]);
            }
        }

        // ---- softmax in registers ----
        float vx0 = -1e30f, vx1 = -1e30f;
#pragma unroll
        for (int jn = 0; jn < 8; jn++) {
            int c = jn * 8 + qr;
            sac[jn][0] += bias_s[c - r0 + 127];
            sac[jn][1] += bias_s[c + 1 - r0 + 127];
            sac[jn][2] += bias_s[c - r1 + 127];
            sac[jn][3] += bias_s[c + 1 - r1 + 127];
            vx0 = fmaxf(vx0, fmaxf(sac[jn][0], sac[jn][1]));
            vx1 = fmaxf(vx1, fmaxf(sac[jn][2], sac[jn][3]));
        }
#pragma unroll
        for (int off = 1; off < 4; off <<= 1) {
            vx0 = fmaxf(vx0, __shfl_xor_sync(0xffffffffu, vx0, off));
            vx1 = fmaxf(vx1, __shfl_xor_sync(0xffffffffu, vx1, off));
        }
        float mn0 = fmaxf(m0, vx0), mn1 = fmaxf(m1, vx1);
        float al0 = __expf(m0 - mn0), al1 = __expf(m1 - mn1);
        float sum0 = 0.0f, sum1 = 0.0f;
        uint32_t pfh[4][4];
#pragma unroll
        for (int t = 0; t < 4; t++) {
#pragma unroll
            for (int half = 0; half < 2; half++) {
                int j = 2 * t + half;
                float e0 = __expf(sac[j][0] - mn0);
                float e1 = __expf(sac[j][1] - mn0);
                float e2 = __expf(sac[j][2] - mn1);
                float e3 = __expf(sac[j][3] - mn1);
                sum0 += e0 + e1;
                sum1 += e2 + e3;
                pfh[t][half * 2 + 0] = pack_hf2(e0, e1);  // row er,  k-cols
                pfh[t][half * 2 + 1] = pack_hf2(e2, e3);  // row er+8
            }
        }
#pragma unroll
        for (int off = 1; off < 4; off <<= 1) {
            sum0 += __shfl_xor_sync(0xffffffffu, sum0, off);
            sum1 += __shfl_xor_sync(0xffffffffu, sum1, off);
        }
        l0 = l0 * al0 + sum0; m0 = mn0;
        l1 = l1 * al1 + sum1; m1 = mn1;
#pragma unroll
        for (int jn = 0; jn < 8; jn++) {
            oac[jn][0] *= al0; oac[jn][1] *= al0;
            oac[jn][2] *= al1; oac[jn][3] *= al1;
        }

        // ---- O += P V (single product: P fp16 x V-hi fp16) ----
#pragma unroll
        for (int t = 0; t < 4; t++) {
            uint32_t vhf[4][4];
#pragma unroll
            for (int db = 0; db < 4; db++) {
                uint32_t voff = ((16 * t + rA) * LKV + 16 * db + cA8) * 2;
                ldmx4t(vhf[db], vb + voff);
            }
#pragma unroll
            for (int db = 0; db < 4; db++) {
                mma16816(oac[2 * db],     pfh[t], vhf[db][0], vhf[db][1]);
                mma16816(oac[2 * db + 1], pfh[t], vhf[db][2], vhf[db][3]);
            }
        }
    }

    // ---- epilogue: normalize + split-fp16 store ----
    float inv0 = 1.0f / l0, inv1 = 1.0f / l1;
#pragma unroll
    for (int jn = 0; jn < 8; jn++) {
        int c = jn * 8 + qr;
        store_split2(Ch, Cl, obase + (size_t)(q0 + r0) * INNER + c,
                     oac[jn][0] * inv0, oac[jn][1] * inv0);
        store_split2(Ch, Cl, obase + (size_t)(q0 + r1) * INNER + c,
                     oac[jn][2] * inv1, oac[jn][3] * inv1);
    }
}

// ---------------------------------------------------------------------------
extern "C" void kernel_launch(void* const* d_in, const int* in_sizes, int n_in,
                              void* d_out, int out_size) {
    const float* hidden = (const float*)d_in[0];
    const float* Wq     = (const float*)d_in[1];
    const float* Wk     = (const float*)d_in[2];
    const float* Wv     = (const float*)d_in[3];
    const float* Wo     = (const float*)d_in[4];
    const float* rel    = (const float*)d_in[5];
    float* out = (float*)d_out;

    float* pB;
    __half *pHh, *pHl, *pXh, *pXl, *pCh, *pCl;
    __half *pWTh, *pWTl, *pWoTh, *pWoTl;
    cudaGetSymbolAddress((void**)&pB, g_biasTab);
    cudaGetSymbolAddress((void**)&pHh, g_Hh);
    cudaGetSymbolAddress((void**)&pHl, g_Hl);
    cudaGetSymbolAddress((void**)&pXh, g_QKVh);
    cudaGetSymbolAddress((void**)&pXl, g_QKVl);
    cudaGetSymbolAddress((void**)&pCh, g_Ch);
    cudaGetSymbolAddress((void**)&pCl, g_Cl);
    cudaGetSymbolAddress((void**)&pWTh, g_WTh);
    cudaGetSymbolAddress((void**)&pWTl, g_WTl);
    cudaGetSymbolAddress((void**)&pWoTh, g_WoTh);
    cudaGetSymbolAddress((void**)&pWoTl, g_WoTl);

    cudaFuncSetAttribute(mma_gemm,
                         cudaFuncAttributeMaxDynamicSharedMemorySize, 2 * STG_SZ);
    cudaFuncSetAttribute(attn_fa2,
                         cudaFuncAttributeMaxDynamicSharedMemorySize, ATTN_SMEM);

    // launch 1: split hidden to fp16 hi/lo
    int n4h = BS_TOT * DMODEL / 4;
    split_plain<<<n4h / 256, 256>>>(hidden, pHh, pHl, n4h);
    // launch 2: transpose+split Wq/Wk/Wv + fused bias table (z==3)
    dim3 tblk(32, 8);
    split_transpose3b<<<dim3(32, 32, 4), tblk>>>(Wq, Wk, Wv, rel, pWTh, pWTl, pB);
    // launch 3: fused QKV projection (V columns >= blk 16 use 2 products)
    mma_gemm<<<dim3(QSTR / 128, BS_TOT / 128), 256, 2 * STG_SZ>>>(
        pHh, pHl, pWTh, pWTl, nullptr, pXh, pXl, BS_TOT, QSTR, DMODEL, 1, 16);
    // launch 4 (ncu capture slot): attention
    attn_fa2<<<dim3(SS / 128, BB * NH), 256, ATTN_SMEM>>>(
        pXh, pXl, pB, pCh, pCl);
    // launch 5: transpose+split Wo
    split_transpose1<<<dim3(32, 32), tblk>>>(Wo, pWoTh, pWoTl);
    // launch 6: output projection, 2 products everywhere -> f32 out
    mma_gemm<<<dim3(DMODEL / 128, BS_TOT / 128), 256, 2 * STG_SZ>>>(
        pCh, pCl, pWoTh, pWoTl, out, nullptr, nullptr, BS_TOT, DMODEL, INNER, 0, 0);
}

// round 11
// speedup vs baseline: 1.2947x; 1.0226x over previous
#include <cuda_runtime.h>
#include <cuda_fp16.h>
#include <math.h>
#include <stdint.h>

#define BB 4
#define SS 2048
#define DMODEL 1024
#define NH 16
#define DKV 64
#define INNER 1024
#define QSTR 3072              // fused QKV row stride
#define BS_TOT (BB * SS)
#define NREL 4095
#define LOG2E 1.4426950408889634f

// ---------------- scratch (device globals: allocation-free) ----------------
__device__ __align__(256) float g_biasTab[NH * NREL];
__device__ __align__(256) __half g_Hh[BS_TOT * DMODEL];
__device__ __align__(256) __half g_Hl[BS_TOT * DMODEL];
__device__ __align__(256) __half g_QKVh[BS_TOT * QSTR];
__device__ __align__(256) __half g_QKVl[BS_TOT * QSTR];
__device__ __align__(256) __half g_Ch[BS_TOT * INNER];
__device__ __align__(256) __half g_Cl[BS_TOT * INNER];
__device__ __align__(256) __half g_WTh[QSTR * DMODEL];   // [Wq*log2e;Wk;Wv]^T
__device__ __align__(256) __half g_WTl[QSTR * DMODEL];
__device__ __align__(256) __half g_WoTh[DMODEL * INNER];
__device__ __align__(256) __half g_WoTl[DMODEL * INNER];

// ---------------------------- PTX helpers ----------------------------------
__device__ __forceinline__ uint32_t smem_u32(const void* p) {
    uint32_t a;
    asm("{ .reg .u64 t; cvta.to.shared.u64 t, %1; cvt.u32.u64 %0, t; }"
        : "=r"(a) : "l"(p));
    return a;
}
__device__ __forceinline__ void cp16(uint32_t dst, const void* src) {
    asm volatile("cp.async.cg.shared.global [%0], [%1], 16;"
                 :: "r"(dst), "l"(src) : "memory");
}
__device__ __forceinline__ void cp4(uint32_t dst, const void* src) {
    asm volatile("cp.async.ca.shared.global [%0], [%1], 4;"
                 :: "r"(dst), "l"(src) : "memory");
}
__device__ __forceinline__ void cp_commit() {
    asm volatile("cp.async.commit_group;" ::: "memory");
}
__device__ __forceinline__ void cp_wait0() {
    asm volatile("cp.async.wait_group 0;" ::: "memory");
}
__device__ __forceinline__ void ldmx4(uint32_t* r, uint32_t addr) {
    asm volatile("ldmatrix.sync.aligned.m8n8.x4.shared.b16 {%0,%1,%2,%3}, [%4];"
                 : "=r"(r[0]), "=r"(r[1]), "=r"(r[2]), "=r"(r[3]) : "r"(addr));
}
__device__ __forceinline__ void ldmx4t(uint32_t* r, uint32_t addr) {
    asm volatile("ldmatrix.sync.aligned.m8n8.x4.trans.shared.b16 {%0,%1,%2,%3}, [%4];"
                 : "=r"(r[0]), "=r"(r[1]), "=r"(r[2]), "=r"(r[3]) : "r"(addr));
}
__device__ __forceinline__ void mma16816(float* c, const uint32_t* a,
                                         uint32_t b0, uint32_t b1) {
    asm volatile("mma.sync.aligned.m16n8k16.row.col.f32.f16.f16.f32 "
                 "{%0,%1,%2,%3}, {%4,%5,%6,%7}, {%8,%9}, {%0,%1,%2,%3};"
                 : "+f"(c[0]), "+f"(c[1]), "+f"(c[2]), "+f"(c[3])
                 : "r"(a[0]), "r"(a[1]), "r"(a[2]), "r"(a[3]), "r"(b0), "r"(b1));
}
__device__ __forceinline__ float ex2f(float x) {
    float y;
    asm("ex2.approx.ftz.f32 %0, %1;" : "=f"(y) : "f"(x));
    return y;
}
__device__ __forceinline__ uint32_t pack_hf2(float x, float y) {
    __half2 p = __floats2half2_rn(x, y);
    return *(uint32_t*)&p;
}
__device__ __forceinline__ void store_split2(__half* Ch, __half* Cl,
                                             size_t off, float x, float y) {
    __half hx = __float2half_rn(x), hy = __float2half_rn(y);
    __half lx = __float2half_rn(x - __half2float(hx));
    __half ly = __float2half_rn(y - __half2float(hy));
    *(__half2*)(Ch + off) = __halves2half2(hx, hy);
    *(__half2*)(Cl + off) = __halves2half2(lx, ly);
}

// ---------------------------------------------------------------------------
// fp32 -> fp16 hi/lo split (row-major)
// ---------------------------------------------------------------------------
__global__ __launch_bounds__(256) void split_plain(const float* __restrict__ X,
                                                   __half* __restrict__ Xh,
                                                   __half* __restrict__ Xl,
                                                   int n4) {
    int i = blockIdx.x * 256 + threadIdx.x;
    if (i >= n4) return;
    float4 v = ((const float4*)X)[i];
    __half h0 = __float2half_rn(v.x), h1 = __float2half_rn(v.y);
    __half h2 = __float2half_rn(v.z), h3 = __float2half_rn(v.w);
    __half l0 = __float2half_rn(v.x - __half2float(h0));
    __half l1 = __float2half_rn(v.y - __half2float(h1));
    __half l2 = __float2half_rn(v.z - __half2float(h2));
    __half l3 = __float2half_rn(v.w - __half2float(h3));
    ((__half2*)Xh)[2 * i]     = __halves2half2(h0, h1);
    ((__half2*)Xh)[2 * i + 1] = __halves2half2(h2, h3);
    ((__half2*)Xl)[2 * i]     = __halves2half2(l0, l1);
    ((__half2*)Xl)[2 * i + 1] = __halves2half2(l2, l3);
}

// ---------------------------------------------------------------------------
// Weight transpose + split, with T5 bias table fused in (z==3 blocks).
// Wq (z==0) and the bias table are pre-scaled by log2(e): scores are computed
// in the log2 domain so softmax uses raw ex2.
// ---------------------------------------------------------------------------
__device__ __forceinline__ void transp_tile(const float* __restrict__ W,
                                            __half* __restrict__ Th,
                                            __half* __restrict__ Tl,
                                            float scale) {
    __shared__ float t[32][33];
    int bx = blockIdx.x * 32, by = blockIdx.y * 32;
    int tx = threadIdx.x, ty = threadIdx.y;
#pragma unroll
    for (int i = 0; i < 32; i += 8)
        t[ty + i][tx] = W[(size_t)(by + ty + i) * DMODEL + bx + tx];
    __syncthreads();
#pragma unroll
    for (int i = 0; i < 32; i += 8) {
        float v = t[tx][ty + i] * scale;
        __half h = __float2half_rn(v);
        __half l = __float2half_rn(v - __half2float(h));
        size_t o = (size_t)(bx + ty + i) * DMODEL + by + tx;
        Th[o] = h;
        Tl[o] = l;
    }
}
__global__ __launch_bounds__(256)
void split_transpose3b(const float* __restrict__ Wq, const float* __restrict__ Wk,
                       const float* __restrict__ Wv, const float* __restrict__ rel_emb,
                       __half* __restrict__ Th, __half* __restrict__ Tl,
                       float* __restrict__ biasTab) {
    if (blockIdx.z < 3) {
        const float* W = (blockIdx.z == 0) ? Wq : (blockIdx.z == 1) ? Wk : Wv;
        float sc = (blockIdx.z == 0) ? LOG2E : 1.0f;
        size_t off = (size_t)blockIdx.z * DMODEL * DMODEL;
        transp_tile(W, Th + off, Tl + off, sc);
        return;
    }
    int tid = threadIdx.y * 32 + threadIdx.x;
    int idx = (blockIdx.y * 32 + blockIdx.x) * 256 + tid;
    if (idx >= NH * NREL) return;
    int h = idx / NREL;
    int pos = idx - h * NREL;
    int rel = pos - (SS - 1);
    int n = -rel;
    int ret = 0;
    if (n < 0) { ret = 16; n = -n; }
    int bucket;
    if (n < 8) {
        bucket = ret + n;
    } else {
        float v = logf((float)n / 8.0f) / logf(16.0f) * 8.0f;
        int vi = 8 + (int)v;
        if (vi > 15) vi = 15;
        bucket = ret + vi;
    }
    biasTab[h * NREL + pos] = rel_emb[bucket * NH + h] * LOG2E;
}
__global__ __launch_bounds__(256)
void split_transpose1(const float* __restrict__ W,
                      __half* __restrict__ Th, __half* __restrict__ Tl) {
    transp_tile(W, Th, Tl, 1.0f);
}

// ---------------------------------------------------------------------------
// Split-fp16 mma.sync GEMM: C[M,N] = A[M,K] @ BT[N,K]^T
// 128x128 tile, BK=32, 256 threads (8 warps, 2x4).
// Single-barrier double-buffered cp.async pipeline.
// Column-blocks with blockIdx.x >= n2_start use 2 products (A*Bh only).
// ---------------------------------------------------------------------------
#define LDS 40
#define STG_A_L 10240
#define STG_B_H 20480
#define STG_B_L 30720
#define STG_SZ  40960

__global__ __launch_bounds__(256)
void mma_gemm(const __half* __restrict__ Ah, const __half* __restrict__ Al,
              const __half* __restrict__ Bh, const __half* __restrict__ Bl,
              float* __restrict__ Cf,
              __half* __restrict__ Ch, __half* __restrict__ Cl,
              int M, int N, int K, int split_out, int n2_start) {
    extern __shared__ __align__(128) char smem[];
    const int tid = threadIdx.x, lane = tid & 31, wid = tid >> 5;
    const int wm = wid >> 2, wn = wid & 3;
    const int rowA0 = blockIdx.y * 128, rowB0 = blockIdx.x * 128;
    const uint32_t sb = smem_u32(smem);
    const int nk = K >> 5;
    const bool np3 = ((int)blockIdx.x < n2_start);

    float acc[16][4];
#pragma unroll
    for (int i = 0; i < 16; i++)
#pragma unroll
        for (int j = 0; j < 4; j++) acc[i][j] = 0.0f;

    auto load_stage = [&](int stage, int kc) {
        const uint32_t d0 = sb + (uint32_t)stage * STG_SZ;
        const int k0 = kc * 32;
#pragma unroll
        for (int i = 0; i < 8; i++) {
            int id = tid + i * 256;
            int arr = id >> 9;
            int rem = id & 511;
            int row = rem >> 2;
            int ch  = (rem & 3) << 4;
            if (arr == 3 && !np3) continue;
            uint32_t dst = d0 + arr * 10240 + row * 80 + ch;
            const __half* src = (arr == 0) ? Ah : (arr == 1) ? Al
                             : (arr == 2) ? Bh : Bl;
            int grow = ((arr < 2) ? rowA0 : rowB0) + row;
            cp16(dst, (const char*)src + ((size_t)grow * K + k0) * 2 + ch);
        }
        cp_commit();
    };

    load_stage(0, 0);

    const int rA = lane & 15;
    const int cA8 = (lane >> 4) << 3;

    for (int kc = 0; kc < nk; kc++) {
        const int s = kc & 1;
        cp_wait0();
        __syncthreads();
        if (kc + 1 < nk) load_stage(s ^ 1, kc + 1);

        const uint32_t base = sb + (uint32_t)s * STG_SZ;
#pragma unroll
        for (int ks = 0; ks < 32; ks += 16) {
            uint32_t a_h[4][4], b_h[2][4], b_l[2][4];
#pragma unroll
            for (int im = 0; im < 4; im++)
                ldmx4(a_h[im], base + ((64 * wm + im * 16 + rA) * LDS + ks + cA8) * 2);
#pragma unroll
            for (int jb = 0; jb < 2; jb++) {
                uint32_t boff = ((32 * wn + jb * 16 + rA) * LDS + ks + cA8) * 2;
                ldmx4(b_h[jb], base + STG_B_H + boff);
                if (np3) ldmx4(b_l[jb], base + STG_B_L + boff);
            }
#pragma unroll
            for (int im = 0; im < 4; im++)
#pragma unroll
                for (int jn = 0; jn < 4; jn++) {
                    int jb = jn >> 1, sub = jn & 1;
                    mma16816(acc[im * 4 + jn], a_h[im], b_h[jb][sub], b_h[jb][sub + 2]);
                    if (np3)
                        mma16816(acc[im * 4 + jn], a_h[im], b_l[jb][sub], b_l[jb][sub + 2]);
                }
#pragma unroll
            for (int im = 0; im < 4; im++) {
                uint32_t a_l[4];
                ldmx4(a_l, base + STG_A_L + ((64 * wm + im * 16 + rA) * LDS + ks + cA8) * 2);
#pragma unroll
                for (int jn = 0; jn < 4; jn++) {
                    int jb = jn >> 1, sub = jn & 1;
                    mma16816(acc[im * 4 + jn], a_l, b_h[jb][sub], b_h[jb][sub + 2]);
                }
            }
        }
    }

    const int er = lane >> 2, ec = (lane & 3) << 1;
#pragma unroll
    for (int im = 0; im < 4; im++) {
        int r0 = rowA0 + 64 * wm + im * 16 + er;
#pragma unroll
        for (int jn = 0; jn < 4; jn++) {
            int c = rowB0 + 32 * wn + jn * 8 + ec;
            float* a = acc[im * 4 + jn];
            if (split_out) {
                store_split2(Ch, Cl, (size_t)r0 * N + c, a[0], a[1]);
                store_split2(Ch, Cl, (size_t)(r0 + 8) * N + c, a[2], a[3]);
            } else {
                *(float2*)(Cf + (size_t)r0 * N + c) = make_float2(a[0], a[1]);
                *(float2*)(Cf + (size_t)(r0 + 8) * N + c) = make_float2(a[2], a[3]);
            }
        }
    }
}

// ---------------------------------------------------------------------------
// Register-resident FA2 flash attention.
// log2-domain scores (Wq,bias pre-scaled); ex2.approx interleaved with PV mma;
// per-lane deferred l-reduction. Double-buffered K/V/bias, 1 barrier/tile.
// Grid (S/128, B*H), 256 threads = 8 warps; warp tile 16 q-rows x 64 keys.
// ---------------------------------------------------------------------------
#define LKV 72
#define KBUF 18432
#define VBUF 9216
#define AQH 0
#define AQL 18432
#define AKB 36864          // K buffers: buf*KBUF (hi +0, lo +9216)
#define AVB 73728          // V buffers: buf*VBUF (hi only)
#define ABI 92160          // bias buffers: buf*768
#define ATTN_SMEM 93696
#define NKT (SS / 64)

__global__ __launch_bounds__(256, 2)
void attn_fa2(const __half* __restrict__ Xh, const __half* __restrict__ Xl,
              const float* __restrict__ biasTab,
              __half* __restrict__ Ch, __half* __restrict__ Cl) {
    extern __shared__ __align__(128) char sm[];
    const int tid = threadIdx.x, lane = tid & 31, wid = tid >> 5;
    const int qt = blockIdx.x, bhi = blockIdx.y;
    const int b = bhi >> 4, h = bhi & 15;
    const int q0 = qt * 128;
    const size_t ibase = (size_t)b * SS * QSTR + (size_t)h * DKV;
    const size_t obase = (size_t)b * SS * INNER + (size_t)h * DKV;
    const uint32_t sb = smem_u32(sm);

    const int rA = lane & 15, cA8 = (lane >> 4) << 3;
    const int er = lane >> 2, qr = (lane & 3) << 1;
    const int r0 = wid * 16 + er, r1 = r0 + 8;

    // ---- per-thread load geometry ----
    const int lrow = tid >> 3;
    const int lch  = (tid & 7) << 4;
    const uint32_t goffA = (uint32_t)lrow * (QSTR * 2) + lch;
    const uint32_t goffB = goffA + 32 * QSTR * 2;
    const uint32_t sA = (uint32_t)lrow * 144 + lch;
    const uint32_t sB = sA + 32 * 144;
    const char* srcKh = (const char*)Xh + (ibase + 1024) * 2;
    const char* srcKl = (const char*)Xl + (ibase + 1024) * 2;
    const char* srcV  = (const char*)Xh + (ibase + 2048) * 2;
    const float* srcB = biasTab + h * NREL + (SS - 1) - q0 - 127;

    auto loadKV = [&](int buf) {
        uint32_t kd = sb + AKB + (uint32_t)buf * KBUF;
        uint32_t vd = sb + AVB + (uint32_t)buf * VBUF;
        cp16(kd + sA, srcKh + goffA);
        cp16(kd + sB, srcKh + goffB);
        cp16(kd + 9216 + sA, srcKl + goffA);
        cp16(kd + 9216 + sB, srcKl + goffB);
        cp16(vd + sA, srcV + goffA);
        cp16(vd + sB, srcV + goffB);
        if (tid < 191)
            cp4(sb + ABI + (uint32_t)buf * 768 + tid * 4, srcB + tid);
        srcKh += (size_t)64 * QSTR * 2;
        srcKl += (size_t)64 * QSTR * 2;
        srcV  += (size_t)64 * QSTR * 2;
        srcB  += 64;
        cp_commit();
    };

    // ---- prologue: Q tile + tile-0 K/V/bias ----
#pragma unroll
    for (int i = 0; i < 8; i++) {
        int id = tid + i * 256;
        int arr = id >> 10, rem = id & 1023;
        int row = rem >> 3, ch = (rem & 7) << 4;
        const __half* src = arr ? Xl : Xh;
        cp16(sb + (arr ? AQL : AQH) + row * 144 + ch,
             (const char*)src + (ibase + (size_t)(q0 + row) * QSTR) * 2 + ch);
    }
    loadKV(0);

    float m0 = -1e30f, m1 = -1e30f, l0 = 0.0f, l1 = 0.0f;
    float oac[8][4];
#pragma unroll
    for (int i = 0; i < 8; i++)
#pragma unroll
        for (int j = 0; j < 4; j++) oac[i][j] = 0.0f;

    for (int kt = 0; kt < NKT; kt++) {
        const int buf = kt & 1;
        cp_wait0();
        __syncthreads();                       // ONE barrier per tile
        if (kt + 1 < NKT) loadKV(buf ^ 1);

        const uint32_t kb0 = sb + AKB + (uint32_t)buf * KBUF;
        const uint32_t kb1 = kb0 + 9216;
        const uint32_t vb  = sb + AVB + (uint32_t)buf * VBUF;
        const float* bias_s = (const float*)(sm + ABI + buf * 768);

        // ---- S = Q K^T (log2 domain; 3 products) ----
        float sac[8][4];
#pragma unroll
        for (int i = 0; i < 8; i++)
#pragma unroll
            for (int j = 0; j < 4; j++) sac[i][j] = 0.0f;
#pragma unroll
        for (int ks = 0; ks < 64; ks += 16) {
            uint32_t qfh[4], qfl[4], khf[4][4], klf[4][4];
            uint32_t aoff = ((wid * 16 + rA) * LKV + ks + cA8) * 2;
            ldmx4(qfh, sb + AQH + aoff);
            ldmx4(qfl, sb + AQL + aoff);
#pragma unroll
            for (int kb = 0; kb < 4; kb++) {
                uint32_t boff = ((16 * kb + rA) * LKV + ks + cA8) * 2;
                ldmx4(khf[kb], kb0 + boff);
                ldmx4(klf[kb], kb1 + boff);
            }
#pragma unroll
            for (int jn = 0; jn < 8; jn++) {
                int kb = jn >> 1, sub = jn & 1;
                mma16816(sac[jn], qfh, khf[kb][sub], khf[kb][sub + 2]);
                mma16816(sac[jn], qfh, klf[kb][sub], klf[kb][sub + 2]);
                mma16816(sac[jn], qfl, khf[kb][sub], khf[kb][sub + 2]);
            }
        }

        // ---- max phase (no exps yet) ----
        float vx0 = -1e30f, vx1 = -1e30f;
#pragma unroll
        for (int jn = 0; jn < 8; jn++) {
            int c = jn * 8 + qr;
            sac[jn][0] += bias_s[c - r0 + 127];
            sac[jn][1] += bias_s[c + 1 - r0 + 127];
            sac[jn][2] += bias_s[c - r1 + 127];
            sac[jn][3] += bias_s[c + 1 - r1 + 127];
            vx0 = fmaxf(vx0, fmaxf(sac[jn][0], sac[jn][1]));
            vx1 = fmaxf(vx1, fmaxf(sac[jn][2], sac[jn][3]));
        }
#pragma unroll
        for (int off = 1; off < 4; off <<= 1) {
            vx0 = fmaxf(vx0, __shfl_xor_sync(0xffffffffu, vx0, off));
            vx1 = fmaxf(vx1, __shfl_xor_sync(0xffffffffu, vx1, off));
        }
        float mn0 = fmaxf(m0, vx0), mn1 = fmaxf(m1, vx1);
        float al0 = ex2f(m0 - mn0), al1 = ex2f(m1 - mn1);
        m0 = mn0; m1 = mn1;
        l0 *= al0; l1 *= al1;                 // lane-partial l, deferred reduce
#pragma unroll
        for (int jn = 0; jn < 8; jn++) {
            oac[jn][0] *= al0; oac[jn][1] *= al0;
            oac[jn][2] *= al1; oac[jn][3] *= al1;
        }

        // ---- interleaved exp + PV: per k16-tile {ldsmt V, 8 ex2, pack, 8 mma}
#pragma unroll
        for (int t = 0; t < 4; t++) {
            uint32_t vhf[4][4];
#pragma unroll
            for (int db = 0; db < 4; db++) {
                uint32_t voff = ((16 * t + rA) * LKV + 16 * db + cA8) * 2;
                ldmx4t(vhf[db], vb + voff);
            }
            uint32_t pfh[4];
#pragma unroll
            for (int half = 0; half < 2; half++) {
                int j = 2 * t + half;
                float e0 = ex2f(sac[j][0] - mn0);
                float e1 = ex2f(sac[j][1] - mn0);
                float e2 = ex2f(sac[j][2] - mn1);
                float e3 = ex2f(sac[j][3] - mn1);
                l0 += e0 + e1;
                l1 += e2 + e3;
                pfh[half * 2 + 0] = pack_hf2(e0, e1);
                pfh[half * 2 + 1] = pack_hf2(e2, e3);
            }
#pragma unroll
            for (int db = 0; db < 4; db++) {
                mma16816(oac[2 * db],     pfh, vhf[db][0], vhf[db][1]);
                mma16816(oac[2 * db + 1], pfh, vhf[db][2], vhf[db][3]);
            }
        }
    }

    // ---- deferred l reduction across the 4 lanes of each row ----
#pragma unroll
    for (int off = 1; off < 4; off <<= 1) {
        l0 += __shfl_xor_sync(0xffffffffu, l0, off);
        l1 += __shfl_xor_sync(0xffffffffu, l1, off);
    }

    // ---- epilogue: normalize + split-fp16 store ----
    float inv0 = 1.0f / l0, inv1 = 1.0f / l1;
#pragma unroll
    for (int jn = 0; jn < 8; jn++) {
        int c = jn * 8 + qr;
        store_split2(Ch, Cl, obase + (size_t)(q0 + r0) * INNER + c,
                     oac[jn][0] * inv0, oac[jn][1] * inv0);
        store_split2(Ch, Cl, obase + (size_t)(q0 + r1) * INNER + c,
                     oac[jn][2] * inv1, oac[jn][3] * inv1);
    }
}

// ---------------------------------------------------------------------------
extern "C" void kernel_launch(void* const* d_in, const int* in_sizes, int n_in,
                              void* d_out, int out_size) {
    const float* hidden = (const float*)d_in[0];
    const float* Wq     = (const float*)d_in[1];
    const float* Wk     = (const float*)d_in[2];
    const float* Wv     = (const float*)d_in[3];
    const float* Wo     = (const float*)d_in[4];
    const float* rel    = (const float*)d_in[5];
    float* out = (float*)d_out;

    float* pB;
    __half *pHh, *pHl, *pXh, *pXl, *pCh, *pCl;
    __half *pWTh, *pWTl, *pWoTh, *pWoTl;
    cudaGetSymbolAddress((void**)&pB, g_biasTab);
    cudaGetSymbolAddress((void**)&pHh, g_Hh);
    cudaGetSymbolAddress((void**)&pHl, g_Hl);
    cudaGetSymbolAddress((void**)&pXh, g_QKVh);
    cudaGetSymbolAddress((void**)&pXl, g_QKVl);
    cudaGetSymbolAddress((void**)&pCh, g_Ch);
    cudaGetSymbolAddress((void**)&pCl, g_Cl);
    cudaGetSymbolAddress((void**)&pWTh, g_WTh);
    cudaGetSymbolAddress((void**)&pWTl, g_WTl);
    cudaGetSymbolAddress((void**)&pWoTh, g_WoTh);
    cudaGetSymbolAddress((void**)&pWoTl, g_WoTl);

    cudaFuncSetAttribute(mma_gemm,
                         cudaFuncAttributeMaxDynamicSharedMemorySize, 2 * STG_SZ);
    cudaFuncSetAttribute(attn_fa2,
                         cudaFuncAttributeMaxDynamicSharedMemorySize, ATTN_SMEM);

    // launch 1: split hidden to fp16 hi/lo
    int n4h = BS_TOT * DMODEL / 4;
    split_plain<<<n4h / 256, 256>>>(hidden, pHh, pHl, n4h);
    // launch 2: transpose+split Wq(*log2e)/Wk/Wv + bias table (*log2e)
    dim3 tblk(32, 8);
    split_transpose3b<<<dim3(32, 32, 4), tblk>>>(Wq, Wk, Wv, rel, pWTh, pWTl, pB);
    // launch 3: fused QKV projection (V columns >= blk 16 use 2 products)
    mma_gemm<<<dim3(QSTR / 128, BS_TOT / 128), 256, 2 * STG_SZ>>>(
        pHh, pHl, pWTh, pWTl, nullptr, pXh, pXl, BS_TOT, QSTR, DMODEL, 1, 16);
    // launch 4 (ncu capture slot): attention
    attn_fa2<<<dim3(SS / 128, BB * NH), 256, ATTN_SMEM>>>(
        pXh, pXl, pB, pCh, pCl);
    // launch 5: transpose+split Wo
    split_transpose1<<<dim3(32, 32), tblk>>>(Wo, pWoTh, pWoTl);
    // launch 6: output projection, 2 products everywhere -> f32 out
    mma_gemm<<<dim3(DMODEL / 128, BS_TOT / 128), 256, 2 * STG_SZ>>>(
        pCh, pCl, pWoTh, pWoTl, out, nullptr, nullptr, BS_TOT, DMODEL, INNER, 0, 0);
}

// round 12
// speedup vs baseline: 1.3162x; 1.0166x over previous
#include <cuda_runtime.h>
#include <cuda_fp16.h>
#include <math.h>
#include <stdint.h>

#define BB 4
#define SS 2048
#define DMODEL 1024
#define NH 16
#define DKV 64
#define INNER 1024
#define QSTR 3072              // fused QKV row stride
#define BS_TOT (BB * SS)
#define NREL 4095
#define LOG2E 1.4426950408889634f

// ---------------- scratch (device globals: allocation-free) ----------------
__device__ __align__(256) float g_biasTab[NH * NREL];
__device__ __align__(256) __half g_Hh[BS_TOT * DMODEL];
__device__ __align__(256) __half g_Hl[BS_TOT * DMODEL];
__device__ __align__(256) __half g_QKVh[BS_TOT * QSTR];
__device__ __align__(256) __half g_QKVl[BS_TOT * QSTR];
__device__ __align__(256) __half g_Ch[BS_TOT * INNER];
__device__ __align__(256) __half g_Cl[BS_TOT * INNER];
__device__ __align__(256) __half g_WTh[QSTR * DMODEL];   // [Wq*log2e;Wk;Wv]^T
__device__ __align__(256) __half g_WTl[QSTR * DMODEL];
__device__ __align__(256) __half g_WoTh[DMODEL * INNER];
__device__ __align__(256) __half g_WoTl[DMODEL * INNER];

// ---------------------------- PTX helpers ----------------------------------
__device__ __forceinline__ uint32_t smem_u32(const void* p) {
    uint32_t a;
    asm("{ .reg .u64 t; cvta.to.shared.u64 t, %1; cvt.u32.u64 %0, t; }"
        : "=r"(a) : "l"(p));
    return a;
}
__device__ __forceinline__ void cp16(uint32_t dst, const void* src) {
    asm volatile("cp.async.cg.shared.global [%0], [%1], 16;"
                 :: "r"(dst), "l"(src) : "memory");
}
__device__ __forceinline__ void cp4(uint32_t dst, const void* src) {
    asm volatile("cp.async.ca.shared.global [%0], [%1], 4;"
                 :: "r"(dst), "l"(src) : "memory");
}
__device__ __forceinline__ void cp_commit() {
    asm volatile("cp.async.commit_group;" ::: "memory");
}
__device__ __forceinline__ void cp_wait0() {
    asm volatile("cp.async.wait_group 0;" ::: "memory");
}
__device__ __forceinline__ void ldmx4(uint32_t* r, uint32_t addr) {
    asm volatile("ldmatrix.sync.aligned.m8n8.x4.shared.b16 {%0,%1,%2,%3}, [%4];"
                 : "=r"(r[0]), "=r"(r[1]), "=r"(r[2]), "=r"(r[3]) : "r"(addr));
}
__device__ __forceinline__ void ldmx4t(uint32_t* r, uint32_t addr) {
    asm volatile("ldmatrix.sync.aligned.m8n8.x4.trans.shared.b16 {%0,%1,%2,%3}, [%4];"
                 : "=r"(r[0]), "=r"(r[1]), "=r"(r[2]), "=r"(r[3]) : "r"(addr));
}
__device__ __forceinline__ void mma16816(float* c, const uint32_t* a,
                                         uint32_t b0, uint32_t b1) {
    asm volatile("mma.sync.aligned.m16n8k16.row.col.f32.f16.f16.f32 "
                 "{%0,%1,%2,%3}, {%4,%5,%6,%7}, {%8,%9}, {%0,%1,%2,%3};"
                 : "+f"(c[0]), "+f"(c[1]), "+f"(c[2]), "+f"(c[3])
                 : "r"(a[0]), "r"(a[1]), "r"(a[2]), "r"(a[3]), "r"(b0), "r"(b1));
}
__device__ __forceinline__ float ex2f(float x) {
    float y;
    asm("ex2.approx.ftz.f32 %0, %1;" : "=f"(y) : "f"(x));
    return y;
}
__device__ __forceinline__ uint32_t pack_hf2(float x, float y) {
    __half2 p = __floats2half2_rn(x, y);
    return *(uint32_t*)&p;
}
__device__ __forceinline__ void store_split2(__half* Ch, __half* Cl,
                                             size_t off, float x, float y) {
    __half hx = __float2half_rn(x), hy = __float2half_rn(y);
    __half lx = __float2half_rn(x - __half2float(hx));
    __half ly = __float2half_rn(y - __half2float(hy));
    *(__half2*)(Ch + off) = __halves2half2(hx, hy);
    *(__half2*)(Cl + off) = __halves2half2(lx, ly);
}

// ---------------------------------------------------------------------------
// fp32 -> fp16 hi/lo split (row-major)
// ---------------------------------------------------------------------------
__global__ __launch_bounds__(256) void split_plain(const float* __restrict__ X,
                                                   __half* __restrict__ Xh,
                                                   __half* __restrict__ Xl,
                                                   int n4) {
    int i = blockIdx.x * 256 + threadIdx.x;
    if (i >= n4) return;
    float4 v = ((const float4*)X)[i];
    __half h0 = __float2half_rn(v.x), h1 = __float2half_rn(v.y);
    __half h2 = __float2half_rn(v.z), h3 = __float2half_rn(v.w);
    __half l0 = __float2half_rn(v.x - __half2float(h0));
    __half l1 = __float2half_rn(v.y - __half2float(h1));
    __half l2 = __float2half_rn(v.z - __half2float(h2));
    __half l3 = __float2half_rn(v.w - __half2float(h3));
    ((__half2*)Xh)[2 * i]     = __halves2half2(h0, h1);
    ((__half2*)Xh)[2 * i + 1] = __halves2half2(h2, h3);
    ((__half2*)Xl)[2 * i]     = __halves2half2(l0, l1);
    ((__half2*)Xl)[2 * i + 1] = __halves2half2(l2, l3);
}

// ---------------------------------------------------------------------------
// Weight transpose + split, with T5 bias table fused in (z==3 blocks).
// Wq (z==0) and the bias table are pre-scaled by log2(e).
// ---------------------------------------------------------------------------
__device__ __forceinline__ void transp_tile(const float* __restrict__ W,
                                            __half* __restrict__ Th,
                                            __half* __restrict__ Tl,
                                            float scale) {
    __shared__ float t[32][33];
    int bx = blockIdx.x * 32, by = blockIdx.y * 32;
    int tx = threadIdx.x, ty = threadIdx.y;
#pragma unroll
    for (int i = 0; i < 32; i += 8)
        t[ty + i][tx] = W[(size_t)(by + ty + i) * DMODEL + bx + tx];
    __syncthreads();
#pragma unroll
    for (int i = 0; i < 32; i += 8) {
        float v = t[tx][ty + i] * scale;
        __half h = __float2half_rn(v);
        __half l = __float2half_rn(v - __half2float(h));
        size_t o = (size_t)(bx + ty + i) * DMODEL + by + tx;
        Th[o] = h;
        Tl[o] = l;
    }
}
__global__ __launch_bounds__(256)
void split_transpose3b(const float* __restrict__ Wq, const float* __restrict__ Wk,
                       const float* __restrict__ Wv, const float* __restrict__ rel_emb,
                       __half* __restrict__ Th, __half* __restrict__ Tl,
                       float* __restrict__ biasTab) {
    if (blockIdx.z < 3) {
        const float* W = (blockIdx.z == 0) ? Wq : (blockIdx.z == 1) ? Wk : Wv;
        float sc = (blockIdx.z == 0) ? LOG2E : 1.0f;
        size_t off = (size_t)blockIdx.z * DMODEL * DMODEL;
        transp_tile(W, Th + off, Tl + off, sc);
        return;
    }
    int tid = threadIdx.y * 32 + threadIdx.x;
    int idx = (blockIdx.y * 32 + blockIdx.x) * 256 + tid;
    if (idx >= NH * NREL) return;
    int h = idx / NREL;
    int pos = idx - h * NREL;
    int rel = pos - (SS - 1);
    int n = -rel;
    int ret = 0;
    if (n < 0) { ret = 16; n = -n; }
    int bucket;
    if (n < 8) {
        bucket = ret + n;
    } else {
        float v = logf((float)n / 8.0f) / logf(16.0f) * 8.0f;
        int vi = 8 + (int)v;
        if (vi > 15) vi = 15;
        bucket = ret + vi;
    }
    biasTab[h * NREL + pos] = rel_emb[bucket * NH + h] * LOG2E;
}
__global__ __launch_bounds__(256)
void split_transpose1(const float* __restrict__ W,
                      __half* __restrict__ Th, __half* __restrict__ Tl) {
    transp_tile(W, Th, Tl, 1.0f);
}

// ---------------------------------------------------------------------------
// Split-fp16 mma.sync GEMM: C[M,N] = A[M,K] @ BT[N,K]^T
// 128x128 tile, BK=32, 256 threads (8 warps, 2x4).
// __launch_bounds__(256,2): cap regs at 128 so 2 CTAs/SM always fit.
// Column-blocks with blockIdx.x >= n2_start use 2 products (A*Bh only) and,
// when split_out, skip the never-consumed lo-half store (V columns).
// ---------------------------------------------------------------------------
#define LDS 40
#define STG_A_L 10240
#define STG_B_H 20480
#define STG_B_L 30720
#define STG_SZ  40960

__global__ __launch_bounds__(256, 2)
void mma_gemm(const __half* __restrict__ Ah, const __half* __restrict__ Al,
              const __half* __restrict__ Bh, const __half* __restrict__ Bl,
              float* __restrict__ Cf,
              __half* __restrict__ Ch, __half* __restrict__ Cl,
              int M, int N, int K, int split_out, int n2_start) {
    extern __shared__ __align__(128) char smem[];
    const int tid = threadIdx.x, lane = tid & 31, wid = tid >> 5;
    const int wm = wid >> 2, wn = wid & 3;
    const int rowA0 = blockIdx.y * 128, rowB0 = blockIdx.x * 128;
    const uint32_t sb = smem_u32(smem);
    const int nk = K >> 5;
    const bool np3 = ((int)blockIdx.x < n2_start);

    float acc[16][4];
#pragma unroll
    for (int i = 0; i < 16; i++)
#pragma unroll
        for (int j = 0; j < 4; j++) acc[i][j] = 0.0f;

    auto load_stage = [&](int stage, int kc) {
        const uint32_t d0 = sb + (uint32_t)stage * STG_SZ;
        const int k0 = kc * 32;
#pragma unroll
        for (int i = 0; i < 8; i++) {
            int id = tid + i * 256;
            int arr = id >> 9;
            int rem = id & 511;
            int row = rem >> 2;
            int ch  = (rem & 3) << 4;
            if (arr == 3 && !np3) continue;
            uint32_t dst = d0 + arr * 10240 + row * 80 + ch;
            const __half* src = (arr == 0) ? Ah : (arr == 1) ? Al
                             : (arr == 2) ? Bh : Bl;
            int grow = ((arr < 2) ? rowA0 : rowB0) + row;
            cp16(dst, (const char*)src + ((size_t)grow * K + k0) * 2 + ch);
        }
        cp_commit();
    };

    load_stage(0, 0);

    const int rA = lane & 15;
    const int cA8 = (lane >> 4) << 3;

    for (int kc = 0; kc < nk; kc++) {
        const int s = kc & 1;
        cp_wait0();
        __syncthreads();
        if (kc + 1 < nk) load_stage(s ^ 1, kc + 1);

        const uint32_t base = sb + (uint32_t)s * STG_SZ;
#pragma unroll
        for (int ks = 0; ks < 32; ks += 16) {
            uint32_t a_h[4][4], b_h[2][4], b_l[2][4];
#pragma unroll
            for (int im = 0; im < 4; im++)
                ldmx4(a_h[im], base + ((64 * wm + im * 16 + rA) * LDS + ks + cA8) * 2);
#pragma unroll
            for (int jb = 0; jb < 2; jb++) {
                uint32_t boff = ((32 * wn + jb * 16 + rA) * LDS + ks + cA8) * 2;
                ldmx4(b_h[jb], base + STG_B_H + boff);
                if (np3) ldmx4(b_l[jb], base + STG_B_L + boff);
            }
#pragma unroll
            for (int im = 0; im < 4; im++)
#pragma unroll
                for (int jn = 0; jn < 4; jn++) {
                    int jb = jn >> 1, sub = jn & 1;
                    mma16816(acc[im * 4 + jn], a_h[im], b_h[jb][sub], b_h[jb][sub + 2]);
                    if (np3)
                        mma16816(acc[im * 4 + jn], a_h[im], b_l[jb][sub], b_l[jb][sub + 2]);
                }
#pragma unroll
            for (int im = 0; im < 4; im++) {
                uint32_t a_l[4];
                ldmx4(a_l, base + STG_A_L + ((64 * wm + im * 16 + rA) * LDS + ks + cA8) * 2);
#pragma unroll
                for (int jn = 0; jn < 4; jn++) {
                    int jb = jn >> 1, sub = jn & 1;
                    mma16816(acc[im * 4 + jn], a_l, b_h[jb][sub], b_h[jb][sub + 2]);
                }
            }
        }
    }

    const int er = lane >> 2, ec = (lane & 3) << 1;
#pragma unroll
    for (int im = 0; im < 4; im++) {
        int r0 = rowA0 + 64 * wm + im * 16 + er;
#pragma unroll
        for (int jn = 0; jn < 4; jn++) {
            int c = rowB0 + 32 * wn + jn * 8 + ec;
            float* a = acc[im * 4 + jn];
            if (split_out) {
                if (np3) {
                    store_split2(Ch, Cl, (size_t)r0 * N + c, a[0], a[1]);
                    store_split2(Ch, Cl, (size_t)(r0 + 8) * N + c, a[2], a[3]);
                } else {
                    // V columns: lo half never consumed downstream
                    *(__half2*)(Ch + (size_t)r0 * N + c) =
                        __floats2half2_rn(a[0], a[1]);
                    *(__half2*)(Ch + (size_t)(r0 + 8) * N + c) =
                        __floats2half2_rn(a[2], a[3]);
                }
            } else {
                *(float2*)(Cf + (size_t)r0 * N + c) = make_float2(a[0], a[1]);
                *(float2*)(Cf + (size_t)(r0 + 8) * N + c) = make_float2(a[2], a[3]);
            }
        }
    }
}

// ---------------------------------------------------------------------------
// Register-resident FA2 flash attention.
// log2-domain scores; ex2 interleaved with PV mma; deferred l-reduction.
// Double-buffered K/V/bias, 1 barrier/tile. 256 threads = 8 warps.
// ---------------------------------------------------------------------------
#define LKV 72
#define KBUF 18432
#define VBUF 9216
#define AQH 0
#define AQL 18432
#define AKB 36864          // K buffers: buf*KBUF (hi +0, lo +9216)
#define AVB 73728          // V buffers: buf*VBUF (hi only)
#define ABI 92160          // bias buffers: buf*768
#define ATTN_SMEM 93696
#define NKT (SS / 64)

__global__ __launch_bounds__(256, 2)
void attn_fa2(const __half* __restrict__ Xh, const __half* __restrict__ Xl,
              const float* __restrict__ biasTab,
              __half* __restrict__ Ch, __half* __restrict__ Cl) {
    extern __shared__ __align__(128) char sm[];
    const int tid = threadIdx.x, lane = tid & 31, wid = tid >> 5;
    const int qt = blockIdx.x, bhi = blockIdx.y;
    const int b = bhi >> 4, h = bhi & 15;
    const int q0 = qt * 128;
    const size_t ibase = (size_t)b * SS * QSTR + (size_t)h * DKV;
    const size_t obase = (size_t)b * SS * INNER + (size_t)h * DKV;
    const uint32_t sb = smem_u32(sm);

    const int rA = lane & 15, cA8 = (lane >> 4) << 3;
    const int er = lane >> 2, qr = (lane & 3) << 1;
    const int r0 = wid * 16 + er, r1 = r0 + 8;

    const int lrow = tid >> 3;
    const int lch  = (tid & 7) << 4;
    const uint32_t goffA = (uint32_t)lrow * (QSTR * 2) + lch;
    const uint32_t goffB = goffA + 32 * QSTR * 2;
    const uint32_t sA = (uint32_t)lrow * 144 + lch;
    const uint32_t sB = sA + 32 * 144;
    const char* srcKh = (const char*)Xh + (ibase + 1024) * 2;
    const char* srcKl = (const char*)Xl + (ibase + 1024) * 2;
    const char* srcV  = (const char*)Xh + (ibase + 2048) * 2;
    const float* srcB = biasTab + h * NREL + (SS - 1) - q0 - 127;

    auto loadKV = [&](int buf) {
        uint32_t kd = sb + AKB + (uint32_t)buf * KBUF;
        uint32_t vd = sb + AVB + (uint32_t)buf * VBUF;
        cp16(kd + sA, srcKh + goffA);
        cp16(kd + sB, srcKh + goffB);
        cp16(kd + 9216 + sA, srcKl + goffA);
        cp16(kd + 9216 + sB, srcKl + goffB);
        cp16(vd + sA, srcV + goffA);
        cp16(vd + sB, srcV + goffB);
        if (tid < 191)
            cp4(sb + ABI + (uint32_t)buf * 768 + tid * 4, srcB + tid);
        srcKh += (size_t)64 * QSTR * 2;
        srcKl += (size_t)64 * QSTR * 2;
        srcV  += (size_t)64 * QSTR * 2;
        srcB  += 64;
        cp_commit();
    };

#pragma unroll
    for (int i = 0; i < 8; i++) {
        int id = tid + i * 256;
        int arr = id >> 10, rem = id & 1023;
        int row = rem >> 3, ch = (rem & 7) << 4;
        const __half* src = arr ? Xl : Xh;
        cp16(sb + (arr ? AQL : AQH) + row * 144 + ch,
             (const char*)src + (ibase + (size_t)(q0 + row) * QSTR) * 2 + ch);
    }
    loadKV(0);

    float m0 = -1e30f, m1 = -1e30f, l0 = 0.0f, l1 = 0.0f;
    float oac[8][4];
#pragma unroll
    for (int i = 0; i < 8; i++)
#pragma unroll
        for (int j = 0; j < 4; j++) oac[i][j] = 0.0f;

    for (int kt = 0; kt < NKT; kt++) {
        const int buf = kt & 1;
        cp_wait0();
        __syncthreads();                       // ONE barrier per tile
        if (kt + 1 < NKT) loadKV(buf ^ 1);

        const uint32_t kb0 = sb + AKB + (uint32_t)buf * KBUF;
        const uint32_t kb1 = kb0 + 9216;
        const uint32_t vb  = sb + AVB + (uint32_t)buf * VBUF;
        const float* bias_s = (const float*)(sm + ABI + buf * 768);

        float sac[8][4];
#pragma unroll
        for (int i = 0; i < 8; i++)
#pragma unroll
            for (int j = 0; j < 4; j++) sac[i][j] = 0.0f;
#pragma unroll
        for (int ks = 0; ks < 64; ks += 16) {
            uint32_t qfh[4], qfl[4], khf[4][4], klf[4][4];
            uint32_t aoff = ((wid * 16 + rA) * LKV + ks + cA8) * 2;
            ldmx4(qfh, sb + AQH + aoff);
            ldmx4(qfl, sb + AQL + aoff);
#pragma unroll
            for (int kb = 0; kb < 4; kb++) {
                uint32_t boff = ((16 * kb + rA) * LKV + ks + cA8) * 2;
                ldmx4(khf[kb], kb0 + boff);
                ldmx4(klf[kb], kb1 + boff);
            }
#pragma unroll
            for (int jn = 0; jn < 8; jn++) {
                int kb = jn >> 1, sub = jn & 1;
                mma16816(sac[jn], qfh, khf[kb][sub], khf[kb][sub + 2]);
                mma16816(sac[jn], qfh, klf[kb][sub], klf[kb][sub + 2]);
                mma16816(sac[jn], qfl, khf[kb][sub], khf[kb][sub + 2]);
            }
        }

        float vx0 = -1e30f, vx1 = -1e30f;
#pragma unroll
        for (int jn = 0; jn < 8; jn++) {
            int c = jn * 8 + qr;
            sac[jn][0] += bias_s[c - r0 + 127];
            sac[jn][1] += bias_s[c + 1 - r0 + 127];
            sac[jn][2] += bias_s[c - r1 + 127];
            sac[jn][3] += bias_s[c + 1 - r1 + 127];
            vx0 = fmaxf(vx0, fmaxf(sac[jn][0], sac[jn][1]));
            vx1 = fmaxf(vx1, fmaxf(sac[jn][2], sac[jn][3]));
        }
#pragma unroll
        for (int off = 1; off < 4; off <<= 1) {
            vx0 = fmaxf(vx0, __shfl_xor_sync(0xffffffffu, vx0, off));
            vx1 = fmaxf(vx1, __shfl_xor_sync(0xffffffffu, vx1, off));
        }
        float mn0 = fmaxf(m0, vx0), mn1 = fmaxf(m1, vx1);
        float al0 = ex2f(m0 - mn0), al1 = ex2f(m1 - mn1);
        m0 = mn0; m1 = mn1;
        l0 *= al0; l1 *= al1;
#pragma unroll
        for (int jn = 0; jn < 8; jn++) {
            oac[jn][0] *= al0; oac[jn][1] *= al0;
            oac[jn][2] *= al1; oac[jn][3] *= al1;
        }

#pragma unroll
        for (int t = 0; t < 4; t++) {
            uint32_t vhf[4][4];
#pragma unroll
            for (int db = 0; db < 4; db++) {
                uint32_t voff = ((16 * t + rA) * LKV + 16 * db + cA8) * 2;
                ldmx4t(vhf[db], vb + voff);
            }
            uint32_t pfh[4];
#pragma unroll
            for (int half = 0; half < 2; half++) {
                int j = 2 * t + half;
                float e0 = ex2f(sac[j][0] - mn0);
                float e1 = ex2f(sac[j][1] - mn0);
                float e2 = ex2f(sac[j][2] - mn1);
                float e3 = ex2f(sac[j][3] - mn1);
                l0 += e0 + e1;
                l1 += e2 + e3;
                pfh[half * 2 + 0] = pack_hf2(e0, e1);
                pfh[half * 2 + 1] = pack_hf2(e2, e3);
            }
#pragma unroll
            for (int db = 0; db < 4; db++) {
                mma16816(oac[2 * db],     pfh, vhf[db][0], vhf[db][1]);
                mma16816(oac[2 * db + 1], pfh, vhf[db][2], vhf[db][3]);
            }
        }
    }

#pragma unroll
    for (int off = 1; off < 4; off <<= 1) {
        l0 += __shfl_xor_sync(0xffffffffu, l0, off);
        l1 += __shfl_xor_sync(0xffffffffu, l1, off);
    }

    float inv0 = 1.0f / l0, inv1 = 1.0f / l1;
#pragma unroll
    for (int jn = 0; jn < 8; jn++) {
        int c = jn * 8 + qr;
        store_split2(Ch, Cl, obase + (size_t)(q0 + r0) * INNER + c,
                     oac[jn][0] * inv0, oac[jn][1] * inv0);
        store_split2(Ch, Cl, obase + (size_t)(q0 + r1) * INNER + c,
                     oac[jn][2] * inv1, oac[jn][3] * inv1);
    }
}

// ---------------------------------------------------------------------------
extern "C" void kernel_launch(void* const* d_in, const int* in_sizes, int n_in,
                              void* d_out, int out_size) {
    const float* hidden = (const float*)d_in[0];
    const float* Wq     = (const float*)d_in[1];
    const float* Wk     = (const float*)d_in[2];
    const float* Wv     = (const float*)d_in[3];
    const float* Wo     = (const float*)d_in[4];
    const float* rel    = (const float*)d_in[5];
    float* out = (float*)d_out;

    float* pB;
    __half *pHh, *pHl, *pXh, *pXl, *pCh, *pCl;
    __half *pWTh, *pWTl, *pWoTh, *pWoTl;
    cudaGetSymbolAddress((void**)&pB, g_biasTab);
    cudaGetSymbolAddress((void**)&pHh, g_Hh);
    cudaGetSymbolAddress((void**)&pHl, g_Hl);
    cudaGetSymbolAddress((void**)&pXh, g_QKVh);
    cudaGetSymbolAddress((void**)&pXl, g_QKVl);
    cudaGetSymbolAddress((void**)&pCh, g_Ch);
    cudaGetSymbolAddress((void**)&pCl, g_Cl);
    cudaGetSymbolAddress((void**)&pWTh, g_WTh);
    cudaGetSymbolAddress((void**)&pWTl, g_WTl);
    cudaGetSymbolAddress((void**)&pWoTh, g_WoTh);
    cudaGetSymbolAddress((void**)&pWoTl, g_WoTl);

    cudaFuncSetAttribute(mma_gemm,
                         cudaFuncAttributeMaxDynamicSharedMemorySize, 2 * STG_SZ);
    cudaFuncSetAttribute(attn_fa2,
                         cudaFuncAttributeMaxDynamicSharedMemorySize, ATTN_SMEM);

    // launch 1: split hidden to fp16 hi/lo
    int n4h = BS_TOT * DMODEL / 4;
    split_plain<<<n4h / 256, 256>>>(hidden, pHh, pHl, n4h);
    // launch 2: transpose+split Wq(*log2e)/Wk/Wv + bias table (*log2e)
    dim3 tblk(32, 8);
    split_transpose3b<<<dim3(32, 32, 4), tblk>>>(Wq, Wk, Wv, rel, pWTh, pWTl, pB);
    // launch 3: transpose+split Wo (hoisted off the attn->WoGEMM serial path)
    split_transpose1<<<dim3(32, 32), tblk>>>(Wo, pWoTh, pWoTl);
    // launch 4 (ncu capture slot): fused QKV projection
    mma_gemm<<<dim3(QSTR / 128, BS_TOT / 128), 256, 2 * STG_SZ>>>(
        pHh, pHl, pWTh, pWTl, nullptr, pXh, pXl, BS_TOT, QSTR, DMODEL, 1, 16);
    // launch 5: attention
    attn_fa2<<<dim3(SS / 128, BB * NH), 256, ATTN_SMEM>>>(
        pXh, pXl, pB, pCh, pCl);
    // launch 6: output projection, 2 products -> f32 out
    mma_gemm<<<dim3(DMODEL / 128, BS_TOT / 128), 256, 2 * STG_SZ>>>(
        pCh, pCl, pWoTh, pWoTl, out, nullptr, nullptr, BS_TOT, DMODEL, INNER, 0, 0);
}

// round 13
// speedup vs baseline: 1.3337x; 1.0133x over previous
#include <cuda_runtime.h>
#include <cuda_fp16.h>
#include <math.h>
#include <stdint.h>

#define BB 4
#define SS 2048
#define DMODEL 1024
#define NH 16
#define DKV 64
#define INNER 1024
#define QSTR 3072              // fused QKV row stride
#define BS_TOT (BB * SS)
#define NREL 4095
#define LOG2E 1.4426950408889634f

// ---------------- scratch (device globals: allocation-free) ----------------
__device__ __align__(256) float g_biasTab[NH * NREL];
__device__ __align__(256) __half g_Hh[BS_TOT * DMODEL];
__device__ __align__(256) __half g_Hl[BS_TOT * DMODEL];
__device__ __align__(256) __half g_QKVh[BS_TOT * QSTR];
__device__ __align__(256) __half g_QKVl[BS_TOT * QSTR];
__device__ __align__(256) __half g_Ch[BS_TOT * INNER];
__device__ __align__(256) __half g_Cl[BS_TOT * INNER];
__device__ __align__(256) __half g_WTh[QSTR * DMODEL];   // [Wq*log2e;Wk;Wv]^T
__device__ __align__(256) __half g_WTl[QSTR * DMODEL];
__device__ __align__(256) __half g_WoTh[DMODEL * INNER];
__device__ __align__(256) __half g_WoTl[DMODEL * INNER];

// ---------------------------- PTX helpers ----------------------------------
__device__ __forceinline__ uint32_t smem_u32(const void* p) {
    uint32_t a;
    asm("{ .reg .u64 t; cvta.to.shared.u64 t, %1; cvt.u32.u64 %0, t; }"
        : "=r"(a) : "l"(p));
    return a;
}
__device__ __forceinline__ void cp16(uint32_t dst, const void* src) {
    asm volatile("cp.async.cg.shared.global [%0], [%1], 16;"
                 :: "r"(dst), "l"(src) : "memory");
}
__device__ __forceinline__ void cp4(uint32_t dst, const void* src) {
    asm volatile("cp.async.ca.shared.global [%0], [%1], 4;"
                 :: "r"(dst), "l"(src) : "memory");
}
__device__ __forceinline__ void cp_commit() {
    asm volatile("cp.async.commit_group;" ::: "memory");
}
__device__ __forceinline__ void cp_wait0() {
    asm volatile("cp.async.wait_group 0;" ::: "memory");
}
__device__ __forceinline__ void ldmx4(uint32_t* r, uint32_t addr) {
    asm volatile("ldmatrix.sync.aligned.m8n8.x4.shared.b16 {%0,%1,%2,%3}, [%4];"
                 : "=r"(r[0]), "=r"(r[1]), "=r"(r[2]), "=r"(r[3]) : "r"(addr));
}
__device__ __forceinline__ void ldmx4t(uint32_t* r, uint32_t addr) {
    asm volatile("ldmatrix.sync.aligned.m8n8.x4.trans.shared.b16 {%0,%1,%2,%3}, [%4];"
                 : "=r"(r[0]), "=r"(r[1]), "=r"(r[2]), "=r"(r[3]) : "r"(addr));
}
__device__ __forceinline__ void mma16816(float* c, const uint32_t* a,
                                         uint32_t b0, uint32_t b1) {
    asm volatile("mma.sync.aligned.m16n8k16.row.col.f32.f16.f16.f32 "
                 "{%0,%1,%2,%3}, {%4,%5,%6,%7}, {%8,%9}, {%0,%1,%2,%3};"
                 : "+f"(c[0]), "+f"(c[1]), "+f"(c[2]), "+f"(c[3])
                 : "r"(a[0]), "r"(a[1]), "r"(a[2]), "r"(a[3]), "r"(b0), "r"(b1));
}
__device__ __forceinline__ float ex2f(float x) {
    float y;
    asm("ex2.approx.ftz.f32 %0, %1;" : "=f"(y) : "f"(x));
    return y;
}
__device__ __forceinline__ uint32_t pack_hf2(float x, float y) {
    __half2 p = __floats2half2_rn(x, y);
    return *(uint32_t*)&p;
}
__device__ __forceinline__ void store_split2(__half* Ch, __half* Cl,
                                             size_t off, float x, float y) {
    __half hx = __float2half_rn(x), hy = __float2half_rn(y);
    __half lx = __float2half_rn(x - __half2float(hx));
    __half ly = __float2half_rn(y - __half2float(hy));
    *(__half2*)(Ch + off) = __halves2half2(hx, hy);
    *(__half2*)(Cl + off) = __halves2half2(lx, ly);
}

// ---------------------------------------------------------------------------
// fp32 -> fp16 hi/lo split (row-major)
// ---------------------------------------------------------------------------
__global__ __launch_bounds__(256) void split_plain(const float* __restrict__ X,
                                                   __half* __restrict__ Xh,
                                                   __half* __restrict__ Xl,
                                                   int n4) {
    int i = blockIdx.x * 256 + threadIdx.x;
    if (i >= n4) return;
    float4 v = ((const float4*)X)[i];
    __half h0 = __float2half_rn(v.x), h1 = __float2half_rn(v.y);
    __half h2 = __float2half_rn(v.z), h3 = __float2half_rn(v.w);
    __half l0 = __float2half_rn(v.x - __half2float(h0));
    __half l1 = __float2half_rn(v.y - __half2float(h1));
    __half l2 = __float2half_rn(v.z - __half2float(h2));
    __half l3 = __float2half_rn(v.w - __half2float(h3));
    ((__half2*)Xh)[2 * i]     = __halves2half2(h0, h1);
    ((__half2*)Xh)[2 * i + 1] = __halves2half2(h2, h3);
    ((__half2*)Xl)[2 * i]     = __halves2half2(l0, l1);
    ((__half2*)Xl)[2 * i + 1] = __halves2half2(l2, l3);
}

// ---------------------------------------------------------------------------
// Weight transpose + split, with T5 bias table fused in (z==3 blocks).
// Wq (z==0) and the bias table are pre-scaled by log2(e).
// ---------------------------------------------------------------------------
__device__ __forceinline__ void transp_tile(const float* __restrict__ W,
                                            __half* __restrict__ Th,
                                            __half* __restrict__ Tl,
                                            float scale) {
    __shared__ float t[32][33];
    int bx = blockIdx.x * 32, by = blockIdx.y * 32;
    int tx = threadIdx.x, ty = threadIdx.y;
#pragma unroll
    for (int i = 0; i < 32; i += 8)
        t[ty + i][tx] = W[(size_t)(by + ty + i) * DMODEL + bx + tx];
    __syncthreads();
#pragma unroll
    for (int i = 0; i < 32; i += 8) {
        float v = t[tx][ty + i] * scale;
        __half h = __float2half_rn(v);
        __half l = __float2half_rn(v - __half2float(h));
        size_t o = (size_t)(bx + ty + i) * DMODEL + by + tx;
        Th[o] = h;
        Tl[o] = l;
    }
}
__global__ __launch_bounds__(256)
void split_transpose3b(const float* __restrict__ Wq, const float* __restrict__ Wk,
                       const float* __restrict__ Wv, const float* __restrict__ rel_emb,
                       __half* __restrict__ Th, __half* __restrict__ Tl,
                       float* __restrict__ biasTab) {
    if (blockIdx.z < 3) {
        const float* W = (blockIdx.z == 0) ? Wq : (blockIdx.z == 1) ? Wk : Wv;
        float sc = (blockIdx.z == 0) ? LOG2E : 1.0f;
        size_t off = (size_t)blockIdx.z * DMODEL * DMODEL;
        transp_tile(W, Th + off, Tl + off, sc);
        return;
    }
    int tid = threadIdx.y * 32 + threadIdx.x;
    int idx = (blockIdx.y * 32 + blockIdx.x) * 256 + tid;
    if (idx >= NH * NREL) return;
    int h = idx / NREL;
    int pos = idx - h * NREL;
    int rel = pos - (SS - 1);
    int n = -rel;
    int ret = 0;
    if (n < 0) { ret = 16; n = -n; }
    int bucket;
    if (n < 8) {
        bucket = ret + n;
    } else {
        float v = logf((float)n / 8.0f) / logf(16.0f) * 8.0f;
        int vi = 8 + (int)v;
        if (vi > 15) vi = 15;
        bucket = ret + vi;
    }
    biasTab[h * NREL + pos] = rel_emb[bucket * NH + h] * LOG2E;
}
__global__ __launch_bounds__(256)
void split_transpose1(const float* __restrict__ W,
                      __half* __restrict__ Th, __half* __restrict__ Tl) {
    transp_tile(W, Th, Tl, 1.0f);
}

// ---------------------------------------------------------------------------
// Split-fp16 mma.sync GEMM: C[M,N] = A[M,K] @ BT[N,K]^T
// CTA tile 128(M) x 64(N), BK=32, 256 threads = 8 warps (4x2), warp 32x32.
// __launch_bounds__(256,3): 3 CTAs/SM = 24 warps for latency hiding.
// Column-blocks with blockIdx.x >= n2_start use 2 products (A*Bh only) and,
// when split_out, skip the never-consumed lo-half store (V columns).
// ---------------------------------------------------------------------------
#define LDS 40
#define STG_A_L 10240
#define STG_B_H 20480
#define STG_B_L 25600
#define STG_SZ  30720

__global__ __launch_bounds__(256, 3)
void mma_gemm(const __half* __restrict__ Ah, const __half* __restrict__ Al,
              const __half* __restrict__ Bh, const __half* __restrict__ Bl,
              float* __restrict__ Cf,
              __half* __restrict__ Ch, __half* __restrict__ Cl,
              int M, int N, int K, int split_out, int n2_start) {
    extern __shared__ __align__(128) char smem[];
    const int tid = threadIdx.x, lane = tid & 31, wid = tid >> 5;
    const int wm = wid >> 1, wn = wid & 1;           // 4 x 2 warp grid
    const int rowA0 = blockIdx.y * 128, rowB0 = blockIdx.x * 64;
    const uint32_t sb = smem_u32(smem);
    const int nk = K >> 5;
    const bool np3 = ((int)blockIdx.x < n2_start);

    float acc[8][4];
#pragma unroll
    for (int i = 0; i < 8; i++)
#pragma unroll
        for (int j = 0; j < 4; j++) acc[i][j] = 0.0f;

    // stage layout: A hi [0,10240) A lo [10240,20480) B hi [20480,25600) B lo [25600,30720)
    auto load_stage = [&](int stage, int kc) {
        const uint32_t d0 = sb + (uint32_t)stage * STG_SZ;
        const int k0 = kc * 32;
#pragma unroll
        for (int i = 0; i < 6; i++) {
            int id = tid + i * 256;          // 0..1535
            if (id < 1024) {                 // A hi/lo: 128 rows x 4 chunks
                int arr = id >> 9;           // 0=hi 1=lo
                int rem = id & 511;
                int row = rem >> 2;
                int ch  = (rem & 3) << 4;
                const __half* src = arr ? Al : Ah;
                cp16(d0 + arr * 10240 + row * 80 + ch,
                     (const char*)src + ((size_t)(rowA0 + row) * K + k0) * 2 + ch);
            } else {                         // B hi/lo: 64 rows x 4 chunks
                int id2 = id - 1024;
                int arr = id2 >> 8;          // 0=hi 1=lo
                if (arr == 1 && !np3) continue;
                int rem = id2 & 255;
                int row = rem >> 2;
                int ch  = (rem & 3) << 4;
                const __half* src = arr ? Bl : Bh;
                cp16(d0 + 20480 + arr * 5120 + row * 80 + ch,
                     (const char*)src + ((size_t)(rowB0 + row) * K + k0) * 2 + ch);
            }
        }
        cp_commit();
    };

    load_stage(0, 0);

    const int rA = lane & 15;
    const int cA8 = (lane >> 4) << 3;

    for (int kc = 0; kc < nk; kc++) {
        const int s = kc & 1;
        cp_wait0();
        __syncthreads();
        if (kc + 1 < nk) load_stage(s ^ 1, kc + 1);

        const uint32_t base = sb + (uint32_t)s * STG_SZ;
#pragma unroll
        for (int ks = 0; ks < 32; ks += 16) {
            uint32_t b_h[2][4], b_l[2][4];
#pragma unroll
            for (int jb = 0; jb < 2; jb++) {
                uint32_t boff = ((32 * wn + jb * 16 + rA) * LDS + ks + cA8) * 2;
                ldmx4(b_h[jb], base + STG_B_H + boff);
                if (np3) ldmx4(b_l[jb], base + STG_B_L + boff);
            }
#pragma unroll
            for (int im = 0; im < 2; im++) {
                uint32_t a_h[4], a_l[4];
                uint32_t aoff = ((32 * wm + im * 16 + rA) * LDS + ks + cA8) * 2;
                ldmx4(a_h, base + aoff);
                ldmx4(a_l, base + STG_A_L + aoff);
#pragma unroll
                for (int jn = 0; jn < 4; jn++) {
                    int jb = jn >> 1, sub = jn & 1;
                    float* a = acc[im * 4 + jn];
                    mma16816(a, a_h, b_h[jb][sub], b_h[jb][sub + 2]);
                    if (np3)
                        mma16816(a, a_h, b_l[jb][sub], b_l[jb][sub + 2]);
                    mma16816(a, a_l, b_h[jb][sub], b_h[jb][sub + 2]);
                }
            }
        }
    }

    const int er = lane >> 2, ec = (lane & 3) << 1;
#pragma unroll
    for (int im = 0; im < 2; im++) {
        int r0 = rowA0 + 32 * wm + im * 16 + er;
#pragma unroll
        for (int jn = 0; jn < 4; jn++) {
            int c = rowB0 + 32 * wn + jn * 8 + ec;
            float* a = acc[im * 4 + jn];
            if (split_out) {
                if (np3) {
                    store_split2(Ch, Cl, (size_t)r0 * N + c, a[0], a[1]);
                    store_split2(Ch, Cl, (size_t)(r0 + 8) * N + c, a[2], a[3]);
                } else {
                    // V columns: lo half never consumed downstream
                    *(__half2*)(Ch + (size_t)r0 * N + c) =
                        __floats2half2_rn(a[0], a[1]);
                    *(__half2*)(Ch + (size_t)(r0 + 8) * N + c) =
                        __floats2half2_rn(a[2], a[3]);
                }
            } else {
                *(float2*)(Cf + (size_t)r0 * N + c) = make_float2(a[0], a[1]);
                *(float2*)(Cf + (size_t)(r0 + 8) * N + c) = make_float2(a[2], a[3]);
            }
        }
    }
}

// ---------------------------------------------------------------------------
// Register-resident FA2 flash attention (unchanged from round 12).
// ---------------------------------------------------------------------------
#define LKV 72
#define KBUF 18432
#define VBUF 9216
#define AQH 0
#define AQL 18432
#define AKB 36864          // K buffers: buf*KBUF (hi +0, lo +9216)
#define AVB 73728          // V buffers: buf*VBUF (hi only)
#define ABI 92160          // bias buffers: buf*768
#define ATTN_SMEM 93696
#define NKT (SS / 64)

__global__ __launch_bounds__(256, 2)
void attn_fa2(const __half* __restrict__ Xh, const __half* __restrict__ Xl,
              const float* __restrict__ biasTab,
              __half* __restrict__ Ch, __half* __restrict__ Cl) {
    extern __shared__ __align__(128) char sm[];
    const int tid = threadIdx.x, lane = tid & 31, wid = tid >> 5;
    const int qt = blockIdx.x, bhi = blockIdx.y;
    const int b = bhi >> 4, h = bhi & 15;
    const int q0 = qt * 128;
    const size_t ibase = (size_t)b * SS * QSTR + (size_t)h * DKV;
    const size_t obase = (size_t)b * SS * INNER + (size_t)h * DKV;
    const uint32_t sb = smem_u32(sm);

    const int rA = lane & 15, cA8 = (lane >> 4) << 3;
    const int er = lane >> 2, qr = (lane & 3) << 1;
    const int r0 = wid * 16 + er, r1 = r0 + 8;

    const int lrow = tid >> 3;
    const int lch  = (tid & 7) << 4;
    const uint32_t goffA = (uint32_t)lrow * (QSTR * 2) + lch;
    const uint32_t goffB = goffA + 32 * QSTR * 2;
    const uint32_t sA = (uint32_t)lrow * 144 + lch;
    const uint32_t sB = sA + 32 * 144;
    const char* srcKh = (const char*)Xh + (ibase + 1024) * 2;
    const char* srcKl = (const char*)Xl + (ibase + 1024) * 2;
    const char* srcV  = (const char*)Xh + (ibase + 2048) * 2;
    const float* srcB = biasTab + h * NREL + (SS - 1) - q0 - 127;

    auto loadKV = [&](int buf) {
        uint32_t kd = sb + AKB + (uint32_t)buf * KBUF;
        uint32_t vd = sb + AVB + (uint32_t)buf * VBUF;
        cp16(kd + sA, srcKh + goffA);
        cp16(kd + sB, srcKh + goffB);
        cp16(kd + 9216 + sA, srcKl + goffA);
        cp16(kd + 9216 + sB, srcKl + goffB);
        cp16(vd + sA, srcV + goffA);
        cp16(vd + sB, srcV + goffB);
        if (tid < 191)
            cp4(sb + ABI + (uint32_t)buf * 768 + tid * 4, srcB + tid);
        srcKh += (size_t)64 * QSTR * 2;
        srcKl += (size_t)64 * QSTR * 2;
        srcV  += (size_t)64 * QSTR * 2;
        srcB  += 64;
        cp_commit();
    };

#pragma unroll
    for (int i = 0; i < 8; i++) {
        int id = tid + i * 256;
        int arr = id >> 10, rem = id & 1023;
        int row = rem >> 3, ch = (rem & 7) << 4;
        const __half* src = arr ? Xl : Xh;
        cp16(sb + (arr ? AQL : AQH) + row * 144 + ch,
             (const char*)src + (ibase + (size_t)(q0 + row) * QSTR) * 2 + ch);
    }
    loadKV(0);

    float m0 = -1e30f, m1 = -1e30f, l0 = 0.0f, l1 = 0.0f;
    float oac[8][4];
#pragma unroll
    for (int i = 0; i < 8; i++)
#pragma unroll
        for (int j = 0; j < 4; j++) oac[i][j] = 0.0f;

    for (int kt = 0; kt < NKT; kt++) {
        const int buf = kt & 1;
        cp_wait0();
        __syncthreads();                       // ONE barrier per tile
        if (kt + 1 < NKT) loadKV(buf ^ 1);

        const uint32_t kb0 = sb + AKB + (uint32_t)buf * KBUF;
        const uint32_t kb1 = kb0 + 9216;
        const uint32_t vb  = sb + AVB + (uint32_t)buf * VBUF;
        const float* bias_s = (const float*)(sm + ABI + buf * 768);

        float sac[8][4];
#pragma unroll
        for (int i = 0; i < 8; i++)
#pragma unroll
            for (int j = 0; j < 4; j++) sac[i][j] = 0.0f;
#pragma unroll
        for (int ks = 0; ks < 64; ks += 16) {
            uint32_t qfh[4], qfl[4], khf[4][4], klf[4][4];
            uint32_t aoff = ((wid * 16 + rA) * LKV + ks + cA8) * 2;
            ldmx4(qfh, sb + AQH + aoff);
            ldmx4(qfl, sb + AQL + aoff);
#pragma unroll
            for (int kb = 0; kb < 4; kb++) {
                uint32_t boff = ((16 * kb + rA) * LKV + ks + cA8) * 2;
                ldmx4(khf[kb], kb0 + boff);
                ldmx4(klf[kb], kb1 + boff);
            }
#pragma unroll
            for (int jn = 0; jn < 8; jn++) {
                int kb = jn >> 1, sub = jn & 1;
                mma16816(sac[jn], qfh, khf[kb][sub], khf[kb][sub + 2]);
                mma16816(sac[jn], qfh, klf[kb][sub], klf[kb][sub + 2]);
                mma16816(sac[jn], qfl, khf[kb][sub], khf[kb][sub + 2]);
            }
        }

        float vx0 = -1e30f, vx1 = -1e30f;
#pragma unroll
        for (int jn = 0; jn < 8; jn++) {
            int c = jn * 8 + qr;
            sac[jn][0] += bias_s[c - r0 + 127];
            sac[jn][1] += bias_s[c + 1 - r0 + 127];
            sac[jn][2] += bias_s[c - r1 + 127];
            sac[jn][3] += bias_s[c + 1 - r1 + 127];
            vx0 = fmaxf(vx0, fmaxf(sac[jn][0], sac[jn][1]));
            vx1 = fmaxf(vx1, fmaxf(sac[jn][2], sac[jn][3]));
        }
#pragma unroll
        for (int off = 1; off < 4; off <<= 1) {
            vx0 = fmaxf(vx0, __shfl_xor_sync(0xffffffffu, vx0, off));
            vx1 = fmaxf(vx1, __shfl_xor_sync(0xffffffffu, vx1, off));
        }
        float mn0 = fmaxf(m0, vx0), mn1 = fmaxf(m1, vx1);
        float al0 = ex2f(m0 - mn0), al1 = ex2f(m1 - mn1);
        m0 = mn0; m1 = mn1;
        l0 *= al0; l1 *= al1;
#pragma unroll
        for (int jn = 0; jn < 8; jn++) {
            oac[jn][0] *= al0; oac[jn][1] *= al0;
            oac[jn][2] *= al1; oac[jn][3] *= al1;
        }

#pragma unroll
        for (int t = 0; t < 4; t++) {
            uint32_t vhf[4][4];
#pragma unroll
            for (int db = 0; db < 4; db++) {
                uint32_t voff = ((16 * t + rA) * LKV + 16 * db + cA8) * 2;
                ldmx4t(vhf[db], vb + voff);
            }
            uint32_t pfh[4];
#pragma unroll
            for (int half = 0; half < 2; half++) {
                int j = 2 * t + half;
                float e0 = ex2f(sac[j][0] - mn0);
                float e1 = ex2f(sac[j][1] - mn0);
                float e2 = ex2f(sac[j][2] - mn1);
                float e3 = ex2f(sac[j][3] - mn1);
                l0 += e0 + e1;
                l1 += e2 + e3;
                pfh[half * 2 + 0] = pack_hf2(e0, e1);
                pfh[half * 2 + 1] = pack_hf2(e2, e3);
            }
#pragma unroll
            for (int db = 0; db < 4; db++) {
                mma16816(oac[2 * db],     pfh, vhf[db][0], vhf[db][1]);
                mma16816(oac[2 * db + 1], pfh, vhf[db][2], vhf[db][3]);
            }
        }
    }

#pragma unroll
    for (int off = 1; off < 4; off <<= 1) {
        l0 += __shfl_xor_sync(0xffffffffu, l0, off);
        l1 += __shfl_xor_sync(0xffffffffu, l1, off);
    }

    float inv0 = 1.0f / l0, inv1 = 1.0f / l1;
#pragma unroll
    for (int jn = 0; jn < 8; jn++) {
        int c = jn * 8 + qr;
        store_split2(Ch, Cl, obase + (size_t)(q0 + r0) * INNER + c,
                     oac[jn][0] * inv0, oac[jn][1] * inv0);
        store_split2(Ch, Cl, obase + (size_t)(q0 + r1) * INNER + c,
                     oac[jn][2] * inv1, oac[jn][3] * inv1);
    }
}

// ---------------------------------------------------------------------------
extern "C" void kernel_launch(void* const* d_in, const int* in_sizes, int n_in,
                              void* d_out, int out_size) {
    const float* hidden = (const float*)d_in[0];
    const float* Wq     = (const float*)d_in[1];
    const float* Wk     = (const float*)d_in[2];
    const float* Wv     = (const float*)d_in[3];
    const float* Wo     = (const float*)d_in[4];
    const float* rel    = (const float*)d_in[5];
    float* out = (float*)d_out;

    float* pB;
    __half *pHh, *pHl, *pXh, *pXl, *pCh, *pCl;
    __half *pWTh, *pWTl, *pWoTh, *pWoTl;
    cudaGetSymbolAddress((void**)&pB, g_biasTab);
    cudaGetSymbolAddress((void**)&pHh, g_Hh);
    cudaGetSymbolAddress((void**)&pHl, g_Hl);
    cudaGetSymbolAddress((void**)&pXh, g_QKVh);
    cudaGetSymbolAddress((void**)&pXl, g_QKVl);
    cudaGetSymbolAddress((void**)&pCh, g_Ch);
    cudaGetSymbolAddress((void**)&pCl, g_Cl);
    cudaGetSymbolAddress((void**)&pWTh, g_WTh);
    cudaGetSymbolAddress((void**)&pWTl, g_WTl);
    cudaGetSymbolAddress((void**)&pWoTh, g_WoTh);
    cudaGetSymbolAddress((void**)&pWoTl, g_WoTl);

    cudaFuncSetAttribute(mma_gemm,
                         cudaFuncAttributeMaxDynamicSharedMemorySize, 2 * STG_SZ);
    cudaFuncSetAttribute(attn_fa2,
                         cudaFuncAttributeMaxDynamicSharedMemorySize, ATTN_SMEM);

    // launch 1: split hidden to fp16 hi/lo
    int n4h = BS_TOT * DMODEL / 4;
    split_plain<<<n4h / 256, 256>>>(hidden, pHh, pHl, n4h);
    // launch 2: transpose+split Wq(*log2e)/Wk/Wv + bias table (*log2e)
    dim3 tblk(32, 8);
    split_transpose3b<<<dim3(32, 32, 4), tblk>>>(Wq, Wk, Wv, rel, pWTh, pWTl, pB);
    // launch 3: transpose+split Wo
    split_transpose1<<<dim3(32, 32), tblk>>>(Wo, pWoTh, pWoTl);
    // launch 4 (ncu capture slot): fused QKV projection
    //   col-blocks >= 32 (byte cols >= 2048) are V -> 2 products, hi-only store
    mma_gemm<<<dim3(QSTR / 64, BS_TOT / 128), 256, 2 * STG_SZ>>>(
        pHh, pHl, pWTh, pWTl, nullptr, pXh, pXl, BS_TOT, QSTR, DMODEL, 1, 32);
    // launch 5: attention
    attn_fa2<<<dim3(SS / 128, BB * NH), 256, ATTN_SMEM>>>(
        pXh, pXl, pB, pCh, pCl);
    // launch 6: output projection, 2 products -> f32 out
    mma_gemm<<<dim3(DMODEL / 64, BS_TOT / 128), 256, 2 * STG_SZ>>>(
        pCh, pCl, pWoTh, pWoTl, out, nullptr, nullptr, BS_TOT, DMODEL, INNER, 0, 0);
}

// round 14
// speedup vs baseline: 1.3590x; 1.0190x over previous
#include <cuda_runtime.h>
#include <cuda_fp16.h>
#include <math.h>
#include <stdint.h>

#define BB 4
#define SS 2048
#define DMODEL 1024
#define NH 16
#define DKV 64
#define INNER 1024
#define QSTR 3072              // fused QKV row stride
#define BS_TOT (BB * SS)
#define NREL 4095
#define LOG2E 1.4426950408889634f

// ---------------- scratch (device globals: allocation-free) ----------------
__device__ __align__(256) float g_biasTab[NH * NREL];
__device__ __align__(256) __half g_Hh[BS_TOT * DMODEL];
__device__ __align__(256) __half g_Hl[BS_TOT * DMODEL];
__device__ __align__(256) __half g_QKVh[BS_TOT * QSTR];
__device__ __align__(256) __half g_QKVl[BS_TOT * QSTR];
__device__ __align__(256) __half g_Ch[BS_TOT * INNER];
__device__ __align__(256) __half g_Cl[BS_TOT * INNER];
__device__ __align__(256) __half g_WTh[QSTR * DMODEL];   // [Wq*log2e;Wk;Wv]^T
__device__ __align__(256) __half g_WTl[QSTR * DMODEL];
__device__ __align__(256) __half g_WoTh[DMODEL * INNER];
__device__ __align__(256) __half g_WoTl[DMODEL * INNER];

// ---------------------------- PTX helpers ----------------------------------
__device__ __forceinline__ uint32_t smem_u32(const void* p) {
    uint32_t a;
    asm("{ .reg .u64 t; cvta.to.shared.u64 t, %1; cvt.u32.u64 %0, t; }"
        : "=r"(a) : "l"(p));
    return a;
}
__device__ __forceinline__ void cp16(uint32_t dst, const void* src) {
    asm volatile("cp.async.cg.shared.global [%0], [%1], 16;"
                 :: "r"(dst), "l"(src) : "memory");
}
__device__ __forceinline__ void cp4(uint32_t dst, const void* src) {
    asm volatile("cp.async.ca.shared.global [%0], [%1], 4;"
                 :: "r"(dst), "l"(src) : "memory");
}
__device__ __forceinline__ void cp_commit() {
    asm volatile("cp.async.commit_group;" ::: "memory");
}
__device__ __forceinline__ void cp_wait0() {
    asm volatile("cp.async.wait_group 0;" ::: "memory");
}
__device__ __forceinline__ void ldmx4(uint32_t* r, uint32_t addr) {
    asm volatile("ldmatrix.sync.aligned.m8n8.x4.shared.b16 {%0,%1,%2,%3}, [%4];"
                 : "=r"(r[0]), "=r"(r[1]), "=r"(r[2]), "=r"(r[3]) : "r"(addr));
}
__device__ __forceinline__ void ldmx4t(uint32_t* r, uint32_t addr) {
    asm volatile("ldmatrix.sync.aligned.m8n8.x4.trans.shared.b16 {%0,%1,%2,%3}, [%4];"
                 : "=r"(r[0]), "=r"(r[1]), "=r"(r[2]), "=r"(r[3]) : "r"(addr));
}
__device__ __forceinline__ void mma16816(float* c, const uint32_t* a,
                                         uint32_t b0, uint32_t b1) {
    asm volatile("mma.sync.aligned.m16n8k16.row.col.f32.f16.f16.f32 "
                 "{%0,%1,%2,%3}, {%4,%5,%6,%7}, {%8,%9}, {%0,%1,%2,%3};"
                 : "+f"(c[0]), "+f"(c[1]), "+f"(c[2]), "+f"(c[3])
                 : "r"(a[0]), "r"(a[1]), "r"(a[2]), "r"(a[3]), "r"(b0), "r"(b1));
}
__device__ __forceinline__ float ex2f(float x) {
    float y;
    asm("ex2.approx.ftz.f32 %0, %1;" : "=f"(y) : "f"(x));
    return y;
}
__device__ __forceinline__ uint32_t pack_hf2(float x, float y) {
    __half2 p = __floats2half2_rn(x, y);
    return *(uint32_t*)&p;
}
__device__ __forceinline__ void store_split2(__half* Ch, __half* Cl,
                                             size_t off, float x, float y) {
    __half hx = __float2half_rn(x), hy = __float2half_rn(y);
    __half lx = __float2half_rn(x - __half2float(hx));
    __half ly = __float2half_rn(y - __half2float(hy));
    *(__half2*)(Ch + off) = __halves2half2(hx, hy);
    *(__half2*)(Cl + off) = __halves2half2(lx, ly);
}

// ---------------------------------------------------------------------------
// fp32 -> fp16 hi/lo split (row-major)
// ---------------------------------------------------------------------------
__global__ __launch_bounds__(256) void split_plain(const float* __restrict__ X,
                                                   __half* __restrict__ Xh,
                                                   __half* __restrict__ Xl,
                                                   int n4) {
    int i = blockIdx.x * 256 + threadIdx.x;
    if (i >= n4) return;
    float4 v = ((const float4*)X)[i];
    __half h0 = __float2half_rn(v.x), h1 = __float2half_rn(v.y);
    __half h2 = __float2half_rn(v.z), h3 = __float2half_rn(v.w);
    __half l0 = __float2half_rn(v.x - __half2float(h0));
    __half l1 = __float2half_rn(v.y - __half2float(h1));
    __half l2 = __float2half_rn(v.z - __half2float(h2));
    __half l3 = __float2half_rn(v.w - __half2float(h3));
    ((__half2*)Xh)[2 * i]     = __halves2half2(h0, h1);
    ((__half2*)Xh)[2 * i + 1] = __halves2half2(h2, h3);
    ((__half2*)Xl)[2 * i]     = __halves2half2(l0, l1);
    ((__half2*)Xl)[2 * i + 1] = __halves2half2(l2, l3);
}

// ---------------------------------------------------------------------------
// Weight transpose + split, with T5 bias table fused in (z==3 blocks).
// Wq (z==0) and the bias table are pre-scaled by log2(e).
// ---------------------------------------------------------------------------
__device__ __forceinline__ void transp_tile(const float* __restrict__ W,
                                            __half* __restrict__ Th,
                                            __half* __restrict__ Tl,
                                            float scale) {
    __shared__ float t[32][33];
    int bx = blockIdx.x * 32, by = blockIdx.y * 32;
    int tx = threadIdx.x, ty = threadIdx.y;
#pragma unroll
    for (int i = 0; i < 32; i += 8)
        t[ty + i][tx] = W[(size_t)(by + ty + i) * DMODEL + bx + tx];
    __syncthreads();
#pragma unroll
    for (int i = 0; i < 32; i += 8) {
        float v = t[tx][ty + i] * scale;
        __half h = __float2half_rn(v);
        __half l = __float2half_rn(v - __half2float(h));
        size_t o = (size_t)(bx + ty + i) * DMODEL + by + tx;
        Th[o] = h;
        Tl[o] = l;
    }
}
__global__ __launch_bounds__(256)
void split_transpose3b(const float* __restrict__ Wq, const float* __restrict__ Wk,
                       const float* __restrict__ Wv, const float* __restrict__ rel_emb,
                       __half* __restrict__ Th, __half* __restrict__ Tl,
                       float* __restrict__ biasTab) {
    if (blockIdx.z < 3) {
        const float* W = (blockIdx.z == 0) ? Wq : (blockIdx.z == 1) ? Wk : Wv;
        float sc = (blockIdx.z == 0) ? LOG2E : 1.0f;
        size_t off = (size_t)blockIdx.z * DMODEL * DMODEL;
        transp_tile(W, Th + off, Tl + off, sc);
        return;
    }
    int tid = threadIdx.y * 32 + threadIdx.x;
    int idx = (blockIdx.y * 32 + blockIdx.x) * 256 + tid;
    if (idx >= NH * NREL) return;
    int h = idx / NREL;
    int pos = idx - h * NREL;
    int rel = pos - (SS - 1);
    int n = -rel;
    int ret = 0;
    if (n < 0) { ret = 16; n = -n; }
    int bucket;
    if (n < 8) {
        bucket = ret + n;
    } else {
        float v = logf((float)n / 8.0f) / logf(16.0f) * 8.0f;
        int vi = 8 + (int)v;
        if (vi > 15) vi = 15;
        bucket = ret + vi;
    }
    biasTab[h * NREL + pos] = rel_emb[bucket * NH + h] * LOG2E;
}
__global__ __launch_bounds__(256)
void split_transpose1(const float* __restrict__ W,
                      __half* __restrict__ Th, __half* __restrict__ Tl) {
    transp_tile(W, Th, Tl, 1.0f);
}

// ---------------------------------------------------------------------------
// Split-fp16 mma.sync GEMM: C[M,N] = A[M,K] @ BT[N,K]^T
// CTA tile 128(M) x 64(N), BK=32, 256 threads = 8 warps (4x2), warp 32x32.
// Product-outer mma ordering: no back-to-back same-accumulator HMMA chains.
// Per-thread pointer-incremented cp.async addressing (no per-chunk decode).
// ---------------------------------------------------------------------------
#define LDS 40
#define STG_A_L 10240
#define STG_B_H 20480
#define STG_B_L 25600
#define STG_SZ  30720

__global__ __launch_bounds__(256, 3)
void mma_gemm(const __half* __restrict__ Ah, const __half* __restrict__ Al,
              const __half* __restrict__ Bh, const __half* __restrict__ Bl,
              float* __restrict__ Cf,
              __half* __restrict__ Ch, __half* __restrict__ Cl,
              int M, int N, int K, int split_out, int n2_start) {
    extern __shared__ __align__(128) char smem[];
    const int tid = threadIdx.x, lane = tid & 31, wid = tid >> 5;
    const int wm = wid >> 1, wn = wid & 1;           // 4 x 2 warp grid
    const int rowA0 = blockIdx.y * 128, rowB0 = blockIdx.x * 64;
    const uint32_t sb = smem_u32(smem);
    const int nk = K >> 5;
    const bool np3 = ((int)blockIdx.x < n2_start);

    float acc[8][4];
#pragma unroll
    for (int i = 0; i < 8; i++)
#pragma unroll
        for (int j = 0; j < 4; j++) acc[i][j] = 0.0f;

    // ---- per-thread load geometry (constant): row=tid>>2, ch=(tid&3)*16 ----
    const int lr = tid >> 2;              // 0..63
    const int lc = (tid & 3) << 4;        // byte col 0..48
    const char* pAh0 = (const char*)Ah + ((size_t)(rowA0 + lr) * K) * 2 + lc;
    const char* pAh1 = pAh0 + (size_t)64 * K * 2;
    const char* pAl0 = (const char*)Al + ((size_t)(rowA0 + lr) * K) * 2 + lc;
    const char* pAl1 = pAl0 + (size_t)64 * K * 2;
    const char* pBh  = (const char*)Bh + ((size_t)(rowB0 + lr) * K) * 2 + lc;
    const char* pBl  = (const char*)Bl + ((size_t)(rowB0 + lr) * K) * 2 + lc;
    const uint32_t dA0 = (uint32_t)lr * 80 + lc;
    const uint32_t dA1 = dA0 + 64 * 80;
    const uint32_t dB  = STG_B_H + (uint32_t)lr * 80 + lc;

    auto load_stage = [&](int stage) {
        const uint32_t d0 = sb + (uint32_t)stage * STG_SZ;
        cp16(d0 + dA0, pAh0);
        cp16(d0 + dA1, pAh1);
        cp16(d0 + STG_A_L + dA0, pAl0);
        cp16(d0 + STG_A_L + dA1, pAl1);
        cp16(d0 + dB, pBh);
        if (np3) cp16(d0 + dB + 5120, pBl);
        pAh0 += 64; pAh1 += 64; pAl0 += 64; pAl1 += 64; pBh += 64; pBl += 64;
        cp_commit();
    };

    load_stage(0);

    const int rA = lane & 15;
    const int cA8 = (lane >> 4) << 3;

    for (int kc = 0; kc < nk; kc++) {
        const int s = kc & 1;
        cp_wait0();
        __syncthreads();
        if (kc + 1 < nk) load_stage(s ^ 1);

        const uint32_t base = sb + (uint32_t)s * STG_SZ;
#pragma unroll
        for (int ks = 0; ks < 32; ks += 16) {
            uint32_t a_h[2][4], a_l[2][4], b_h[2][4], b_l[2][4];
#pragma unroll
            for (int jb = 0; jb < 2; jb++) {
                uint32_t boff = ((32 * wn + jb * 16 + rA) * LDS + ks + cA8) * 2;
                ldmx4(b_h[jb], base + STG_B_H + boff);
                if (np3) ldmx4(b_l[jb], base + STG_B_L + boff);
            }
#pragma unroll
            for (int im = 0; im < 2; im++) {
                uint32_t aoff = ((32 * wm + im * 16 + rA) * LDS + ks + cA8) * 2;
                ldmx4(a_h[im], base + aoff);
                ldmx4(a_l[im], base + STG_A_L + aoff);
            }
            // product 1: Ah x Bh  (8 independent accumulators back-to-back)
#pragma unroll
            for (int im = 0; im < 2; im++)
#pragma unroll
                for (int jn = 0; jn < 4; jn++) {
                    int jb = jn >> 1, sub = jn & 1;
                    mma16816(acc[im * 4 + jn], a_h[im], b_h[jb][sub], b_h[jb][sub + 2]);
                }
            // product 2: Ah x Bl
            if (np3) {
#pragma unroll
                for (int im = 0; im < 2; im++)
#pragma unroll
                    for (int jn = 0; jn < 4; jn++) {
                        int jb = jn >> 1, sub = jn & 1;
                        mma16816(acc[im * 4 + jn], a_h[im], b_l[jb][sub], b_l[jb][sub + 2]);
                    }
            }
            // product 3: Al x Bh
#pragma unroll
            for (int im = 0; im < 2; im++)
#pragma unroll
                for (int jn = 0; jn < 4; jn++) {
                    int jb = jn >> 1, sub = jn & 1;
                    mma16816(acc[im * 4 + jn], a_l[im], b_h[jb][sub], b_h[jb][sub + 2]);
                }
        }
    }

    const int er = lane >> 2, ec = (lane & 3) << 1;
#pragma unroll
    for (int im = 0; im < 2; im++) {
        int r0 = rowA0 + 32 * wm + im * 16 + er;
#pragma unroll
        for (int jn = 0; jn < 4; jn++) {
            int c = rowB0 + 32 * wn + jn * 8 + ec;
            float* a = acc[im * 4 + jn];
            if (split_out) {
                if (np3) {
                    store_split2(Ch, Cl, (size_t)r0 * N + c, a[0], a[1]);
                    store_split2(Ch, Cl, (size_t)(r0 + 8) * N + c, a[2], a[3]);
                } else {
                    *(__half2*)(Ch + (size_t)r0 * N + c) =
                        __floats2half2_rn(a[0], a[1]);
                    *(__half2*)(Ch + (size_t)(r0 + 8) * N + c) =
                        __floats2half2_rn(a[2], a[3]);
                }
            } else {
                *(float2*)(Cf + (size_t)r0 * N + c) = make_float2(a[0], a[1]);
                *(float2*)(Cf + (size_t)(r0 + 8) * N + c) = make_float2(a[2], a[3]);
            }
        }
    }
}

// ---------------------------------------------------------------------------
// Register-resident FA2 flash attention.
// Product-outer QK mma ordering (no same-acc HMMA chains); log2-domain scores;
// ex2 interleaved with PV mma; deferred l-reduction; 1 barrier/tile.
// ---------------------------------------------------------------------------
#define LKV 72
#define KBUF 18432
#define VBUF 9216
#define AQH 0
#define AQL 18432
#define AKB 36864
#define AVB 73728
#define ABI 92160
#define ATTN_SMEM 93696
#define NKT (SS / 64)

__global__ __launch_bounds__(256, 2)
void attn_fa2(const __half* __restrict__ Xh, const __half* __restrict__ Xl,
              const float* __restrict__ biasTab,
              __half* __restrict__ Ch, __half* __restrict__ Cl) {
    extern __shared__ __align__(128) char sm[];
    const int tid = threadIdx.x, lane = tid & 31, wid = tid >> 5;
    const int qt = blockIdx.x, bhi = blockIdx.y;
    const int b = bhi >> 4, h = bhi & 15;
    const int q0 = qt * 128;
    const size_t ibase = (size_t)b * SS * QSTR + (size_t)h * DKV;
    const size_t obase = (size_t)b * SS * INNER + (size_t)h * DKV;
    const uint32_t sb = smem_u32(sm);

    const int rA = lane & 15, cA8 = (lane >> 4) << 3;
    const int er = lane >> 2, qr = (lane & 3) << 1;
    const int r0 = wid * 16 + er, r1 = r0 + 8;

    const int lrow = tid >> 3;
    const int lch  = (tid & 7) << 4;
    const uint32_t goffA = (uint32_t)lrow * (QSTR * 2) + lch;
    const uint32_t goffB = goffA + 32 * QSTR * 2;
    const uint32_t sA = (uint32_t)lrow * 144 + lch;
    const uint32_t sB = sA + 32 * 144;
    const char* srcKh = (const char*)Xh + (ibase + 1024) * 2;
    const char* srcKl = (const char*)Xl + (ibase + 1024) * 2;
    const char* srcV  = (const char*)Xh + (ibase + 2048) * 2;
    const float* srcB = biasTab + h * NREL + (SS - 1) - q0 - 127;

    auto loadKV = [&](int buf) {
        uint32_t kd = sb + AKB + (uint32_t)buf * KBUF;
        uint32_t vd = sb + AVB + (uint32_t)buf * VBUF;
        cp16(kd + sA, srcKh + goffA);
        cp16(kd + sB, srcKh + goffB);
        cp16(kd + 9216 + sA, srcKl + goffA);
        cp16(kd + 9216 + sB, srcKl + goffB);
        cp16(vd + sA, srcV + goffA);
        cp16(vd + sB, srcV + goffB);
        if (tid < 191)
            cp4(sb + ABI + (uint32_t)buf * 768 + tid * 4, srcB + tid);
        srcKh += (size_t)64 * QSTR * 2;
        srcKl += (size_t)64 * QSTR * 2;
        srcV  += (size_t)64 * QSTR * 2;
        srcB  += 64;
        cp_commit();
    };

#pragma unroll
    for (int i = 0; i < 8; i++) {
        int id = tid + i * 256;
        int arr = id >> 10, rem = id & 1023;
        int row = rem >> 3, ch = (rem & 7) << 4;
        const __half* src = arr ? Xl : Xh;
        cp16(sb + (arr ? AQL : AQH) + row * 144 + ch,
             (const char*)src + (ibase + (size_t)(q0 + row) * QSTR) * 2 + ch);
    }
    loadKV(0);

    float m0 = -1e30f, m1 = -1e30f, l0 = 0.0f, l1 = 0.0f;
    float oac[8][4];
#pragma unroll
    for (int i = 0; i < 8; i++)
#pragma unroll
        for (int j = 0; j < 4; j++) oac[i][j] = 0.0f;

    for (int kt = 0; kt < NKT; kt++) {
        const int buf = kt & 1;
        cp_wait0();
        __syncthreads();                       // ONE barrier per tile
        if (kt + 1 < NKT) loadKV(buf ^ 1);

        const uint32_t kb0 = sb + AKB + (uint32_t)buf * KBUF;
        const uint32_t kb1 = kb0 + 9216;
        const uint32_t vb  = sb + AVB + (uint32_t)buf * VBUF;
        const float* bias_s = (const float*)(sm + ABI + buf * 768);

        float sac[8][4];
#pragma unroll
        for (int i = 0; i < 8; i++)
#pragma unroll
            for (int j = 0; j < 4; j++) sac[i][j] = 0.0f;
#pragma unroll
        for (int ks = 0; ks < 64; ks += 16) {
            uint32_t qfh[4], qfl[4], khf[4][4], klf[4][4];
            uint32_t aoff = ((wid * 16 + rA) * LKV + ks + cA8) * 2;
            ldmx4(qfh, sb + AQH + aoff);
            ldmx4(qfl, sb + AQL + aoff);
#pragma unroll
            for (int kb = 0; kb < 4; kb++) {
                uint32_t boff = ((16 * kb + rA) * LKV + ks + cA8) * 2;
                ldmx4(khf[kb], kb0 + boff);
                ldmx4(klf[kb], kb1 + boff);
            }
            // product 1: Qh x Kh (8 independent accumulators)
#pragma unroll
            for (int jn = 0; jn < 8; jn++) {
                int kb = jn >> 1, sub = jn & 1;
                mma16816(sac[jn], qfh, khf[kb][sub], khf[kb][sub + 2]);
            }
            // product 2: Qh x Kl
#pragma unroll
            for (int jn = 0; jn < 8; jn++) {
                int kb = jn >> 1, sub = jn & 1;
                mma16816(sac[jn], qfh, klf[kb][sub], klf[kb][sub + 2]);
            }
            // product 3: Ql x Kh
#pragma unroll
            for (int jn = 0; jn < 8; jn++) {
                int kb = jn >> 1, sub = jn & 1;
                mma16816(sac[jn], qfl, khf[kb][sub], khf[kb][sub + 2]);
            }
        }

        float vx0 = -1e30f, vx1 = -1e30f;
#pragma unroll
        for (int jn = 0; jn < 8; jn++) {
            int c = jn * 8 + qr;
            sac[jn][0] += bias_s[c - r0 + 127];
            sac[jn][1] += bias_s[c + 1 - r0 + 127];
            sac[jn][2] += bias_s[c - r1 + 127];
            sac[jn][3] += bias_s[c + 1 - r1 + 127];
            vx0 = fmaxf(vx0, fmaxf(sac[jn][0], sac[jn][1]));
            vx1 = fmaxf(vx1, fmaxf(sac[jn][2], sac[jn][3]));
        }
#pragma unroll
        for (int off = 1; off < 4; off <<= 1) {
            vx0 = fmaxf(vx0, __shfl_xor_sync(0xffffffffu, vx0, off));
            vx1 = fmaxf(vx1, __shfl_xor_sync(0xffffffffu, vx1, off));
        }
        float mn0 = fmaxf(m0, vx0), mn1 = fmaxf(m1, vx1);
        float al0 = ex2f(m0 - mn0), al1 = ex2f(m1 - mn1);
        m0 = mn0; m1 = mn1;
        l0 *= al0; l1 *= al1;
#pragma unroll
        for (int jn = 0; jn < 8; jn++) {
            oac[jn][0] *= al0; oac[jn][1] *= al0;
            oac[jn][2] *= al1; oac[jn][3] *= al1;
        }

#pragma unroll
        for (int t = 0; t < 4; t++) {
            uint32_t vhf[4][4];
#pragma unroll
            for (int db = 0; db < 4; db++) {
                uint32_t voff = ((16 * t + rA) * LKV + 16 * db + cA8) * 2;
                ldmx4t(vhf[db], vb + voff);
            }
            uint32_t pfh[4];
#pragma unroll
            for (int half = 0; half < 2; half++) {
                int j = 2 * t + half;
                float e0 = ex2f(sac[j][0] - mn0);
                float e1 = ex2f(sac[j][1] - mn0);
                float e2 = ex2f(sac[j][2] - mn1);
                float e3 = ex2f(sac[j][3] - mn1);
                l0 += e0 + e1;
                l1 += e2 + e3;
                pfh[half * 2 + 0] = pack_hf2(e0, e1);
                pfh[half * 2 + 1] = pack_hf2(e2, e3);
            }
#pragma unroll
            for (int db = 0; db < 4; db++) {
                mma16816(oac[2 * db],     pfh, vhf[db][0], vhf[db][1]);
                mma16816(oac[2 * db + 1], pfh, vhf[db][2], vhf[db][3]);
            }
        }
    }

#pragma unroll
    for (int off = 1; off < 4; off <<= 1) {
        l0 += __shfl_xor_sync(0xffffffffu, l0, off);
        l1 += __shfl_xor_sync(0xffffffffu, l1, off);
    }

    float inv0 = 1.0f / l0, inv1 = 1.0f / l1;
#pragma unroll
    for (int jn = 0; jn < 8; jn++) {
        int c = jn * 8 + qr;
        store_split2(Ch, Cl, obase + (size_t)(q0 + r0) * INNER + c,
                     oac[jn][0] * inv0, oac[jn][1] * inv0);
        store_split2(Ch, Cl, obase + (size_t)(q0 + r1) * INNER + c,
                     oac[jn][2] * inv1, oac[jn][3] * inv1);
    }
}

// ---------------------------------------------------------------------------
extern "C" void kernel_launch(void* const* d_in, const int* in_sizes, int n_in,
                              void* d_out, int out_size) {
    const float* hidden = (const float*)d_in[0];
    const float* Wq     = (const float*)d_in[1];
    const float* Wk     = (const float*)d_in[2];
    const float* Wv     = (const float*)d_in[3];
    const float* Wo     = (const float*)d_in[4];
    const float* rel    = (const float*)d_in[5];
    float* out = (float*)d_out;

    float* pB;
    __half *pHh, *pHl, *pXh, *pXl, *pCh, *pCl;
    __half *pWTh, *pWTl, *pWoTh, *pWoTl;
    cudaGetSymbolAddress((void**)&pB, g_biasTab);
    cudaGetSymbolAddress((void**)&pHh, g_Hh);
    cudaGetSymbolAddress((void**)&pHl, g_Hl);
    cudaGetSymbolAddress((void**)&pXh, g_QKVh);
    cudaGetSymbolAddress((void**)&pXl, g_QKVl);
    cudaGetSymbolAddress((void**)&pCh, g_Ch);
    cudaGetSymbolAddress((void**)&pCl, g_Cl);
    cudaGetSymbolAddress((void**)&pWTh, g_WTh);
    cudaGetSymbolAddress((void**)&pWTl, g_WTl);
    cudaGetSymbolAddress((void**)&pWoTh, g_WoTh);
    cudaGetSymbolAddress((void**)&pWoTl, g_WoTl);

    cudaFuncSetAttribute(mma_gemm,
                         cudaFuncAttributeMaxDynamicSharedMemorySize, 2 * STG_SZ);
    cudaFuncSetAttribute(attn_fa2,
                         cudaFuncAttributeMaxDynamicSharedMemorySize, ATTN_SMEM);

    // launch 1: split hidden to fp16 hi/lo
    int n4h = BS_TOT * DMODEL / 4;
    split_plain<<<n4h / 256, 256>>>(hidden, pHh, pHl, n4h);
    // launch 2: transpose+split Wq(*log2e)/Wk/Wv + bias table (*log2e)
    dim3 tblk(32, 8);
    split_transpose3b<<<dim3(32, 32, 4), tblk>>>(Wq, Wk, Wv, rel, pWTh, pWTl, pB);
    // launch 3: transpose+split Wo
    split_transpose1<<<dim3(32, 32), tblk>>>(Wo, pWoTh, pWoTl);
    // launch 4 (ncu capture slot): fused QKV projection
    mma_gemm<<<dim3(QSTR / 64, BS_TOT / 128), 256, 2 * STG_SZ>>>(
        pHh, pHl, pWTh, pWTl, nullptr, pXh, pXl, BS_TOT, QSTR, DMODEL, 1, 32);
    // launch 5: attention
    attn_fa2<<<dim3(SS / 128, BB * NH), 256, ATTN_SMEM>>>(
        pXh, pXl, pB, pCh, pCl);
    // launch 6: output projection, 2 products -> f32 out
    mma_gemm<<<dim3(DMODEL / 64, BS_TOT / 128), 256, 2 * STG_SZ>>>(
        pCh, pCl, pWoTh, pWoTl, out, nullptr, nullptr, BS_TOT, DMODEL, INNER, 0, 0);
}

// round 15
// speedup vs baseline: 1.4408x; 1.0602x over previous
#include <cuda_runtime.h>
#include <cuda_fp16.h>
#include <math.h>
#include <stdint.h>

#define BB 4
#define SS 2048
#define DMODEL 1024
#define NH 16
#define DKV 64
#define INNER 1024
#define QSTR 3072              // fused QKV row stride
#define BS_TOT (BB * SS)
#define NREL 4095
#define LOG2E 1.4426950408889634f

// ---------------- scratch (device globals: allocation-free) ----------------
__device__ __align__(256) float g_biasTab[NH * NREL];
__device__ __align__(256) __half g_Hh[BS_TOT * DMODEL];
__device__ __align__(256) __half g_Hl[BS_TOT * DMODEL];
__device__ __align__(256) __half g_QKVh[BS_TOT * QSTR];
__device__ __align__(256) __half g_QKVl[BS_TOT * QSTR];
__device__ __align__(256) __half g_Ch[BS_TOT * INNER];
__device__ __align__(256) __half g_WTh[QSTR * DMODEL];   // [Wq*log2e;Wk;Wv]^T
__device__ __align__(256) __half g_WTl[QSTR * DMODEL];
__device__ __align__(256) __half g_WoTh[DMODEL * INNER];
__device__ __align__(256) __half g_WoTl[DMODEL * INNER];

// ---------------------------- PTX helpers ----------------------------------
__device__ __forceinline__ uint32_t smem_u32(const void* p) {
    uint32_t a;
    asm("{ .reg .u64 t; cvta.to.shared.u64 t, %1; cvt.u32.u64 %0, t; }"
        : "=r"(a) : "l"(p));
    return a;
}
__device__ __forceinline__ void cp16(uint32_t dst, const void* src) {
    asm volatile("cp.async.cg.shared.global [%0], [%1], 16;"
                 :: "r"(dst), "l"(src) : "memory");
}
__device__ __forceinline__ void cp4(uint32_t dst, const void* src) {
    asm volatile("cp.async.ca.shared.global [%0], [%1], 4;"
                 :: "r"(dst), "l"(src) : "memory");
}
__device__ __forceinline__ void cp_commit() {
    asm volatile("cp.async.commit_group;" ::: "memory");
}
__device__ __forceinline__ void cp_wait0() {
    asm volatile("cp.async.wait_group 0;" ::: "memory");
}
__device__ __forceinline__ void ldmx4(uint32_t* r, uint32_t addr) {
    asm volatile("ldmatrix.sync.aligned.m8n8.x4.shared.b16 {%0,%1,%2,%3}, [%4];"
                 : "=r"(r[0]), "=r"(r[1]), "=r"(r[2]), "=r"(r[3]) : "r"(addr));
}
__device__ __forceinline__ void ldmx4t(uint32_t* r, uint32_t addr) {
    asm volatile("ldmatrix.sync.aligned.m8n8.x4.trans.shared.b16 {%0,%1,%2,%3}, [%4];"
                 : "=r"(r[0]), "=r"(r[1]), "=r"(r[2]), "=r"(r[3]) : "r"(addr));
}
__device__ __forceinline__ void mma16816(float* c, const uint32_t* a,
                                         uint32_t b0, uint32_t b1) {
    asm volatile("mma.sync.aligned.m16n8k16.row.col.f32.f16.f16.f32 "
                 "{%0,%1,%2,%3}, {%4,%5,%6,%7}, {%8,%9}, {%0,%1,%2,%3};"
                 : "+f"(c[0]), "+f"(c[1]), "+f"(c[2]), "+f"(c[3])
                 : "r"(a[0]), "r"(a[1]), "r"(a[2]), "r"(a[3]), "r"(b0), "r"(b1));
}
__device__ __forceinline__ float ex2f(float x) {
    float y;
    asm("ex2.approx.ftz.f32 %0, %1;" : "=f"(y) : "f"(x));
    return y;
}
__device__ __forceinline__ uint32_t pack_hf2(float x, float y) {
    __half2 p = __floats2half2_rn(x, y);
    return *(uint32_t*)&p;
}
__device__ __forceinline__ void store_split2(__half* Ch, __half* Cl,
                                             size_t off, float x, float y) {
    __half hx = __float2half_rn(x), hy = __float2half_rn(y);
    __half lx = __float2half_rn(x - __half2float(hx));
    __half ly = __float2half_rn(y - __half2float(hy));
    *(__half2*)(Ch + off) = __halves2half2(hx, hy);
    *(__half2*)(Cl + off) = __halves2half2(lx, ly);
}

// ---------------------------------------------------------------------------
// fp32 -> fp16 hi/lo split (row-major)
// ---------------------------------------------------------------------------
__global__ __launch_bounds__(256) void split_plain(const float* __restrict__ X,
                                                   __half* __restrict__ Xh,
                                                   __half* __restrict__ Xl,
                                                   int n4) {
    int i = blockIdx.x * 256 + threadIdx.x;
    if (i >= n4) return;
    float4 v = ((const float4*)X)[i];
    __half h0 = __float2half_rn(v.x), h1 = __float2half_rn(v.y);
    __half h2 = __float2half_rn(v.z), h3 = __float2half_rn(v.w);
    __half l0 = __float2half_rn(v.x - __half2float(h0));
    __half l1 = __float2half_rn(v.y - __half2float(h1));
    __half l2 = __float2half_rn(v.z - __half2float(h2));
    __half l3 = __float2half_rn(v.w - __half2float(h3));
    ((__half2*)Xh)[2 * i]     = __halves2half2(h0, h1);
    ((__half2*)Xh)[2 * i + 1] = __halves2half2(h2, h3);
    ((__half2*)Xl)[2 * i]     = __halves2half2(l0, l1);
    ((__half2*)Xl)[2 * i + 1] = __halves2half2(l2, l3);
}

// ---------------------------------------------------------------------------
// Weight transpose + split, with T5 bias table fused in (z==3 blocks).
// Wq (z==0) and the bias table are pre-scaled by log2(e).
// ---------------------------------------------------------------------------
__device__ __forceinline__ void transp_tile(const float* __restrict__ W,
                                            __half* __restrict__ Th,
                                            __half* __restrict__ Tl,
                                            float scale) {
    __shared__ float t[32][33];
    int bx = blockIdx.x * 32, by = blockIdx.y * 32;
    int tx = threadIdx.x, ty = threadIdx.y;
#pragma unroll
    for (int i = 0; i < 32; i += 8)
        t[ty + i][tx] = W[(size_t)(by + ty + i) * DMODEL + bx + tx];
    __syncthreads();
#pragma unroll
    for (int i = 0; i < 32; i += 8) {
        float v = t[tx][ty + i] * scale;
        __half h = __float2half_rn(v);
        __half l = __float2half_rn(v - __half2float(h));
        size_t o = (size_t)(bx + ty + i) * DMODEL + by + tx;
        Th[o] = h;
        Tl[o] = l;
    }
}
__global__ __launch_bounds__(256)
void split_transpose3b(const float* __restrict__ Wq, const float* __restrict__ Wk,
                       const float* __restrict__ Wv, const float* __restrict__ rel_emb,
                       __half* __restrict__ Th, __half* __restrict__ Tl,
                       float* __restrict__ biasTab) {
    if (blockIdx.z < 3) {
        const float* W = (blockIdx.z == 0) ? Wq : (blockIdx.z == 1) ? Wk : Wv;
        float sc = (blockIdx.z == 0) ? LOG2E : 1.0f;
        size_t off = (size_t)blockIdx.z * DMODEL * DMODEL;
        transp_tile(W, Th + off, Tl + off, sc);
        return;
    }
    int tid = threadIdx.y * 32 + threadIdx.x;
    int idx = (blockIdx.y * 32 + blockIdx.x) * 256 + tid;
    if (idx >= NH * NREL) return;
    int h = idx / NREL;
    int pos = idx - h * NREL;
    int rel = pos - (SS - 1);
    int n = -rel;
    int ret = 0;
    if (n < 0) { ret = 16; n = -n; }
    int bucket;
    if (n < 8) {
        bucket = ret + n;
    } else {
        float v = logf((float)n / 8.0f) / logf(16.0f) * 8.0f;
        int vi = 8 + (int)v;
        if (vi > 15) vi = 15;
        bucket = ret + vi;
    }
    biasTab[h * NREL + pos] = rel_emb[bucket * NH + h] * LOG2E;
}
__global__ __launch_bounds__(256)
void split_transpose1(const float* __restrict__ W,
                      __half* __restrict__ Th, __half* __restrict__ Tl) {
    transp_tile(W, Th, Tl, 1.0f);
}

// ---------------------------------------------------------------------------
// Split-fp16 mma.sync GEMM: C[M,N] = A[M,K] @ BT[N,K]^T
// CTA tile 128(M) x 64(N), BK=32, 256 threads = 8 warps (4x2), warp 32x32.
// Column-blocks < p3_end: 3 products (split in, split out).
// Column-blocks >= p3_end: 1 product (A-hi x B-hi; skips Al/Bl loads; hi-only
// or f32 store).
// ---------------------------------------------------------------------------
#define LDS 40
#define STG_A_L 10240
#define STG_B_H 20480
#define STG_B_L 25600
#define STG_SZ  30720

__global__ __launch_bounds__(256, 3)
void mma_gemm(const __half* __restrict__ Ah, const __half* __restrict__ Al,
              const __half* __restrict__ Bh, const __half* __restrict__ Bl,
              float* __restrict__ Cf,
              __half* __restrict__ Ch, __half* __restrict__ Cl,
              int M, int N, int K, int split_out, int p3_end) {
    extern __shared__ __align__(128) char smem[];
    const int tid = threadIdx.x, lane = tid & 31, wid = tid >> 5;
    const int wm = wid >> 1, wn = wid & 1;           // 4 x 2 warp grid
    const int rowA0 = blockIdx.y * 128, rowB0 = blockIdx.x * 64;
    const uint32_t sb = smem_u32(smem);
    const int nk = K >> 5;
    const bool np3 = ((int)blockIdx.x < p3_end);

    float acc[8][4];
#pragma unroll
    for (int i = 0; i < 8; i++)
#pragma unroll
        for (int j = 0; j < 4; j++) acc[i][j] = 0.0f;

    // ---- per-thread load geometry (constant): row=tid>>2, ch=(tid&3)*16 ----
    const int lr = tid >> 2;              // 0..63
    const int lc = (tid & 3) << 4;        // byte col 0..48
    const char* pAh0 = (const char*)Ah + ((size_t)(rowA0 + lr) * K) * 2 + lc;
    const char* pAh1 = pAh0 + (size_t)64 * K * 2;
    const char* pAl0 = (const char*)Al + ((size_t)(rowA0 + lr) * K) * 2 + lc;
    const char* pAl1 = pAl0 + (size_t)64 * K * 2;
    const char* pBh  = (const char*)Bh + ((size_t)(rowB0 + lr) * K) * 2 + lc;
    const char* pBl  = (const char*)Bl + ((size_t)(rowB0 + lr) * K) * 2 + lc;
    const uint32_t dA0 = (uint32_t)lr * 80 + lc;
    const uint32_t dA1 = dA0 + 64 * 80;
    const uint32_t dB  = STG_B_H + (uint32_t)lr * 80 + lc;

    auto load_stage = [&](int stage) {
        const uint32_t d0 = sb + (uint32_t)stage * STG_SZ;
        cp16(d0 + dA0, pAh0);
        cp16(d0 + dA1, pAh1);
        cp16(d0 + dB, pBh);
        if (np3) {
            cp16(d0 + STG_A_L + dA0, pAl0);
            cp16(d0 + STG_A_L + dA1, pAl1);
            cp16(d0 + dB + 5120, pBl);
        }
        pAh0 += 64; pAh1 += 64; pAl0 += 64; pAl1 += 64; pBh += 64; pBl += 64;
        cp_commit();
    };

    load_stage(0);

    const int rA = lane & 15;
    const int cA8 = (lane >> 4) << 3;

    for (int kc = 0; kc < nk; kc++) {
        const int s = kc & 1;
        cp_wait0();
        __syncthreads();
        if (kc + 1 < nk) load_stage(s ^ 1);

        const uint32_t base = sb + (uint32_t)s * STG_SZ;
#pragma unroll
        for (int ks = 0; ks < 32; ks += 16) {
            uint32_t a_h[2][4], a_l[2][4], b_h[2][4], b_l[2][4];
#pragma unroll
            for (int jb = 0; jb < 2; jb++) {
                uint32_t boff = ((32 * wn + jb * 16 + rA) * LDS + ks + cA8) * 2;
                ldmx4(b_h[jb], base + STG_B_H + boff);
                if (np3) ldmx4(b_l[jb], base + STG_B_L + boff);
            }
#pragma unroll
            for (int im = 0; im < 2; im++) {
                uint32_t aoff = ((32 * wm + im * 16 + rA) * LDS + ks + cA8) * 2;
                ldmx4(a_h[im], base + aoff);
                if (np3) ldmx4(a_l[im], base + STG_A_L + aoff);
            }
            // product 1: Ah x Bh (8 independent accumulators)
#pragma unroll
            for (int im = 0; im < 2; im++)
#pragma unroll
                for (int jn = 0; jn < 4; jn++) {
                    int jb = jn >> 1, sub = jn & 1;
                    mma16816(acc[im * 4 + jn], a_h[im], b_h[jb][sub], b_h[jb][sub + 2]);
                }
            if (np3) {
                // product 2: Ah x Bl
#pragma unroll
                for (int im = 0; im < 2; im++)
#pragma unroll
                    for (int jn = 0; jn < 4; jn++) {
                        int jb = jn >> 1, sub = jn & 1;
                        mma16816(acc[im * 4 + jn], a_h[im], b_l[jb][sub], b_l[jb][sub + 2]);
                    }
                // product 3: Al x Bh
#pragma unroll
                for (int im = 0; im < 2; im++)
#pragma unroll
                    for (int jn = 0; jn < 4; jn++) {
                        int jb = jn >> 1, sub = jn & 1;
                        mma16816(acc[im * 4 + jn], a_l[im], b_h[jb][sub], b_h[jb][sub + 2]);
                    }
            }
        }
    }

    const int er = lane >> 2, ec = (lane & 3) << 1;
#pragma unroll
    for (int im = 0; im < 2; im++) {
        int r0 = rowA0 + 32 * wm + im * 16 + er;
#pragma unroll
        for (int jn = 0; jn < 4; jn++) {
            int c = rowB0 + 32 * wn + jn * 8 + ec;
            float* a = acc[im * 4 + jn];
            if (split_out) {
                if (np3) {
                    store_split2(Ch, Cl, (size_t)r0 * N + c, a[0], a[1]);
                    store_split2(Ch, Cl, (size_t)(r0 + 8) * N + c, a[2], a[3]);
                } else {
                    *(__half2*)(Ch + (size_t)r0 * N + c) =
                        __floats2half2_rn(a[0], a[1]);
                    *(__half2*)(Ch + (size_t)(r0 + 8) * N + c) =
                        __floats2half2_rn(a[2], a[3]);
                }
            } else {
                *(float2*)(Cf + (size_t)r0 * N + c) = make_float2(a[0], a[1]);
                *(float2*)(Cf + (size_t)(r0 + 8) * N + c) = make_float2(a[2], a[3]);
            }
        }
    }
}

// ---------------------------------------------------------------------------
// Register-resident FA2 flash attention.
// Product-outer QK mma ordering; log2-domain scores; ex2 interleaved with PV;
// deferred l-reduction; 1 barrier/tile. Output: single fp16 (no split).
// ---------------------------------------------------------------------------
#define LKV 72
#define KBUF 18432
#define VBUF 9216
#define AQH 0
#define AQL 18432
#define AKB 36864
#define AVB 73728
#define ABI 92160
#define ATTN_SMEM 93696
#define NKT (SS / 64)

__global__ __launch_bounds__(256, 2)
void attn_fa2(const __half* __restrict__ Xh, const __half* __restrict__ Xl,
              const float* __restrict__ biasTab,
              __half* __restrict__ Ch) {
    extern __shared__ __align__(128) char sm[];
    const int tid = threadIdx.x, lane = tid & 31, wid = tid >> 5;
    const int qt = blockIdx.x, bhi = blockIdx.y;
    const int b = bhi >> 4, h = bhi & 15;
    const int q0 = qt * 128;
    const size_t ibase = (size_t)b * SS * QSTR + (size_t)h * DKV;
    const size_t obase = (size_t)b * SS * INNER + (size_t)h * DKV;
    const uint32_t sb = smem_u32(sm);

    const int rA = lane & 15, cA8 = (lane >> 4) << 3;
    const int er = lane >> 2, qr = (lane & 3) << 1;
    const int r0 = wid * 16 + er, r1 = r0 + 8;

    const int lrow = tid >> 3;
    const int lch  = (tid & 7) << 4;
    const uint32_t goffA = (uint32_t)lrow * (QSTR * 2) + lch;
    const uint32_t goffB = goffA + 32 * QSTR * 2;
    const uint32_t sA = (uint32_t)lrow * 144 + lch;
    const uint32_t sB = sA + 32 * 144;
    const char* srcKh = (const char*)Xh + (ibase + 1024) * 2;
    const char* srcKl = (const char*)Xl + (ibase + 1024) * 2;
    const char* srcV  = (const char*)Xh + (ibase + 2048) * 2;
    const float* srcB = biasTab + h * NREL + (SS - 1) - q0 - 127;

    auto loadKV = [&](int buf) {
        uint32_t kd = sb + AKB + (uint32_t)buf * KBUF;
        uint32_t vd = sb + AVB + (uint32_t)buf * VBUF;
        cp16(kd + sA, srcKh + goffA);
        cp16(kd + sB, srcKh + goffB);
        cp16(kd + 9216 + sA, srcKl + goffA);
        cp16(kd + 9216 + sB, srcKl + goffB);
        cp16(vd + sA, srcV + goffA);
        cp16(vd + sB, srcV + goffB);
        if (tid < 191)
            cp4(sb + ABI + (uint32_t)buf * 768 + tid * 4, srcB + tid);
        srcKh += (size_t)64 * QSTR * 2;
        srcKl += (size_t)64 * QSTR * 2;
        srcV  += (size_t)64 * QSTR * 2;
        srcB  += 64;
        cp_commit();
    };

#pragma unroll
    for (int i = 0; i < 8; i++) {
        int id = tid + i * 256;
        int arr = id >> 10, rem = id & 1023;
        int row = rem >> 3, ch = (rem & 7) << 4;
        const __half* src = arr ? Xl : Xh;
        cp16(sb + (arr ? AQL : AQH) + row * 144 + ch,
             (const char*)src + (ibase + (size_t)(q0 + row) * QSTR) * 2 + ch);
    }
    loadKV(0);

    float m0 = -1e30f, m1 = -1e30f, l0 = 0.0f, l1 = 0.0f;
    float oac[8][4];
#pragma unroll
    for (int i = 0; i < 8; i++)
#pragma unroll
        for (int j = 0; j < 4; j++) oac[i][j] = 0.0f;

    for (int kt = 0; kt < NKT; kt++) {
        const int buf = kt & 1;
        cp_wait0();
        __syncthreads();                       // ONE barrier per tile
        if (kt + 1 < NKT) loadKV(buf ^ 1);

        const uint32_t kb0 = sb + AKB + (uint32_t)buf * KBUF;
        const uint32_t kb1 = kb0 + 9216;
        const uint32_t vb  = sb + AVB + (uint32_t)buf * VBUF;
        const float* bias_s = (const float*)(sm + ABI + buf * 768);

        float sac[8][4];
#pragma unroll
        for (int i = 0; i < 8; i++)
#pragma unroll
            for (int j = 0; j < 4; j++) sac[i][j] = 0.0f;
#pragma unroll
        for (int ks = 0; ks < 64; ks += 16) {
            uint32_t qfh[4], qfl[4], khf[4][4], klf[4][4];
            uint32_t aoff = ((wid * 16 + rA) * LKV + ks + cA8) * 2;
            ldmx4(qfh, sb + AQH + aoff);
            ldmx4(qfl, sb + AQL + aoff);
#pragma unroll
            for (int kb = 0; kb < 4; kb++) {
                uint32_t boff = ((16 * kb + rA) * LKV + ks + cA8) * 2;
                ldmx4(khf[kb], kb0 + boff);
                ldmx4(klf[kb], kb1 + boff);
            }
#pragma unroll
            for (int jn = 0; jn < 8; jn++) {
                int kb = jn >> 1, sub = jn & 1;
                mma16816(sac[jn], qfh, khf[kb][sub], khf[kb][sub + 2]);
            }
#pragma unroll
            for (int jn = 0; jn < 8; jn++) {
                int kb = jn >> 1, sub = jn & 1;
                mma16816(sac[jn], qfh, klf[kb][sub], klf[kb][sub + 2]);
            }
#pragma unroll
            for (int jn = 0; jn < 8; jn++) {
                int kb = jn >> 1, sub = jn & 1;
                mma16816(sac[jn], qfl, khf[kb][sub], khf[kb][sub + 2]);
            }
        }

        float vx0 = -1e30f, vx1 = -1e30f;
#pragma unroll
        for (int jn = 0; jn < 8; jn++) {
            int c = jn * 8 + qr;
            sac[jn][0] += bias_s[c - r0 + 127];
            sac[jn][1] += bias_s[c + 1 - r0 + 127];
            sac[jn][2] += bias_s[c - r1 + 127];
            sac[jn][3] += bias_s[c + 1 - r1 + 127];
            vx0 = fmaxf(vx0, fmaxf(sac[jn][0], sac[jn][1]));
            vx1 = fmaxf(vx1, fmaxf(sac[jn][2], sac[jn][3]));
        }
#pragma unroll
        for (int off = 1; off < 4; off <<= 1) {
            vx0 = fmaxf(vx0, __shfl_xor_sync(0xffffffffu, vx0, off));
            vx1 = fmaxf(vx1, __shfl_xor_sync(0xffffffffu, vx1, off));
        }
        float mn0 = fmaxf(m0, vx0), mn1 = fmaxf(m1, vx1);
        float al0 = ex2f(m0 - mn0), al1 = ex2f(m1 - mn1);
        m0 = mn0; m1 = mn1;
        l0 *= al0; l1 *= al1;
#pragma unroll
        for (int jn = 0; jn < 8; jn++) {
            oac[jn][0] *= al0; oac[jn][1] *= al0;
            oac[jn][2] *= al1; oac[jn][3] *= al1;
        }

#pragma unroll
        for (int t = 0; t < 4; t++) {
            uint32_t vhf[4][4];
#pragma unroll
            for (int db = 0; db < 4; db++) {
                uint32_t voff = ((16 * t + rA) * LKV + 16 * db + cA8) * 2;
                ldmx4t(vhf[db], vb + voff);
            }
            uint32_t pfh[4];
#pragma unroll
            for (int half = 0; half < 2; half++) {
                int j = 2 * t + half;
                float e0 = ex2f(sac[j][0] - mn0);
                float e1 = ex2f(sac[j][1] - mn0);
                float e2 = ex2f(sac[j][2] - mn1);
                float e3 = ex2f(sac[j][3] - mn1);
                l0 += e0 + e1;
                l1 += e2 + e3;
                pfh[half * 2 + 0] = pack_hf2(e0, e1);
                pfh[half * 2 + 1] = pack_hf2(e2, e3);
            }
#pragma unroll
            for (int db = 0; db < 4; db++) {
                mma16816(oac[2 * db],     pfh, vhf[db][0], vhf[db][1]);
                mma16816(oac[2 * db + 1], pfh, vhf[db][2], vhf[db][3]);
            }
        }
    }

#pragma unroll
    for (int off = 1; off < 4; off <<= 1) {
        l0 += __shfl_xor_sync(0xffffffffu, l0, off);
        l1 += __shfl_xor_sync(0xffffffffu, l1, off);
    }

    // ---- epilogue: normalize + single-fp16 store ----
    float inv0 = 1.0f / l0, inv1 = 1.0f / l1;
#pragma unroll
    for (int jn = 0; jn < 8; jn++) {
        int c = jn * 8 + qr;
        *(__half2*)(Ch + obase + (size_t)(q0 + r0) * INNER + c) =
            __floats2half2_rn(oac[jn][0] * inv0, oac[jn][1] * inv0);
        *(__half2*)(Ch + obase + (size_t)(q0 + r1) * INNER + c) =
            __floats2half2_rn(oac[jn][2] * inv1, oac[jn][3] * inv1);
    }
}

// ---------------------------------------------------------------------------
extern "C" void kernel_launch(void* const* d_in, const int* in_sizes, int n_in,
                              void* d_out, int out_size) {
    const float* hidden = (const float*)d_in[0];
    const float* Wq     = (const float*)d_in[1];
    const float* Wk     = (const float*)d_in[2];
    const float* Wv     = (const float*)d_in[3];
    const float* Wo     = (const float*)d_in[4];
    const float* rel    = (const float*)d_in[5];
    float* out = (float*)d_out;

    float* pB;
    __half *pHh, *pHl, *pXh, *pXl, *pCh;
    __half *pWTh, *pWTl, *pWoTh, *pWoTl;
    cudaGetSymbolAddress((void**)&pB, g_biasTab);
    cudaGetSymbolAddress((void**)&pHh, g_Hh);
    cudaGetSymbolAddress((void**)&pHl, g_Hl);
    cudaGetSymbolAddress((void**)&pXh, g_QKVh);
    cudaGetSymbolAddress((void**)&pXl, g_QKVl);
    cudaGetSymbolAddress((void**)&pCh, g_Ch);
    cudaGetSymbolAddress((void**)&pWTh, g_WTh);
    cudaGetSymbolAddress((void**)&pWTl, g_WTl);
    cudaGetSymbolAddress((void**)&pWoTh, g_WoTh);
    cudaGetSymbolAddress((void**)&pWoTl, g_WoTl);

    cudaFuncSetAttribute(mma_gemm,
                         cudaFuncAttributeMaxDynamicSharedMemorySize, 2 * STG_SZ);
    cudaFuncSetAttribute(attn_fa2,
                         cudaFuncAttributeMaxDynamicSharedMemorySize, ATTN_SMEM);

    // launch 1: split hidden to fp16 hi/lo
    int n4h = BS_TOT * DMODEL / 4;
    split_plain<<<n4h / 256, 256>>>(hidden, pHh, pHl, n4h);
    // launch 2: transpose+split Wq(*log2e)/Wk/Wv + bias table (*log2e)
    dim3 tblk(32, 8);
    split_transpose3b<<<dim3(32, 32, 4), tblk>>>(Wq, Wk, Wv, rel, pWTh, pWTl, pB);
    // launch 3: transpose+split Wo
    split_transpose1<<<dim3(32, 32), tblk>>>(Wo, pWoTh, pWoTl);
    // launch 4 (ncu capture slot): fused QKV projection
    //   Q,K col-blocks (<32): 3 products; V col-blocks (>=32): 1 product
    mma_gemm<<<dim3(QSTR / 64, BS_TOT / 128), 256, 2 * STG_SZ>>>(
        pHh, pHl, pWTh, pWTl, nullptr, pXh, pXl, BS_TOT, QSTR, DMODEL, 1, 32);
    // launch 5: attention -> single-fp16 context
    attn_fa2<<<dim3(SS / 128, BB * NH), 256, ATTN_SMEM>>>(
        pXh, pXl, pB, pCh);
    // launch 6: output projection, 1 product (Ch x Wo-hi) -> f32 out
    mma_gemm<<<dim3(DMODEL / 64, BS_TOT / 128), 256, 2 * STG_SZ>>>(
        pCh, pCh, pWoTh, pWoTh, out, nullptr, nullptr, BS_TOT, DMODEL, INNER, 0, 0);
}